// round 1
// baseline (speedup 1.0000x reference)
#include <cuda_runtime.h>
#include <math.h>

#define D_MODEL   1024
#define NUM_HEADS 16
#define HEAD_DIM  64
#define BATCH     4
#define SEQ       2048
#define M_ROWS    (BATCH * SEQ)   // 8192

// ---------------------------------------------------------------------------
// Scratch (allocation-free rule: __device__ globals)
// ---------------------------------------------------------------------------
__device__ float g_Q [M_ROWS * D_MODEL];
__device__ float g_K [M_ROWS * D_MODEL];
__device__ float g_V [M_ROWS * D_MODEL];
__device__ float g_AO[M_ROWS * D_MODEL];

// ---------------------------------------------------------------------------
// GEMM: C[M,N] = A[M,K] * B[N,K]^T   (both row-major, K-contiguous -> NT form)
// 128x128 tile, BK=16, 256 threads, 8x8 per-thread microtile.
// Shared tiles stored [k][m] so compute frags are LDS.128.
// Assumes M%128==0, N%128==0, K%16==0 (true for all our shapes).
// ---------------------------------------------------------------------------
__global__ __launch_bounds__(256) void gemm_nt_kernel(
    const float* __restrict__ A, const float* __restrict__ B,
    float* __restrict__ C, int M, int N, int K)
{
    __shared__ float As[16][128];
    __shared__ float Bs[16][128];

    const int tid = threadIdx.x;
    const int tx  = tid & 15;
    const int ty  = tid >> 4;
    const int bm  = blockIdx.y * 128;
    const int bn  = blockIdx.x * 128;

    float acc[8][8];
#pragma unroll
    for (int i = 0; i < 8; i++)
#pragma unroll
        for (int j = 0; j < 8; j++) acc[i][j] = 0.0f;

    const int lr = tid >> 2;        // 0..63
    const int lc = (tid & 3) * 4;   // 0,4,8,12

    const float* Ab = A + (long)bm * K;
    const float* Bb = B + (long)bn * K;

    for (int k0 = 0; k0 < K; k0 += 16) {
#pragma unroll
        for (int h = 0; h < 2; h++) {
            int row = lr + h * 64;
            float4 av = *reinterpret_cast<const float4*>(Ab + (long)row * K + k0 + lc);
            As[lc + 0][row] = av.x; As[lc + 1][row] = av.y;
            As[lc + 2][row] = av.z; As[lc + 3][row] = av.w;
            float4 bv = *reinterpret_cast<const float4*>(Bb + (long)row * K + k0 + lc);
            Bs[lc + 0][row] = bv.x; Bs[lc + 1][row] = bv.y;
            Bs[lc + 2][row] = bv.z; Bs[lc + 3][row] = bv.w;
        }
        __syncthreads();

#pragma unroll
        for (int kk = 0; kk < 16; kk++) {
            float a[8], b[8];
            *reinterpret_cast<float4*>(&a[0]) = *reinterpret_cast<const float4*>(&As[kk][ty * 8]);
            *reinterpret_cast<float4*>(&a[4]) = *reinterpret_cast<const float4*>(&As[kk][ty * 8 + 4]);
            *reinterpret_cast<float4*>(&b[0]) = *reinterpret_cast<const float4*>(&Bs[kk][tx * 8]);
            *reinterpret_cast<float4*>(&b[4]) = *reinterpret_cast<const float4*>(&Bs[kk][tx * 8 + 4]);
#pragma unroll
            for (int i = 0; i < 8; i++)
#pragma unroll
                for (int j = 0; j < 8; j++)
                    acc[i][j] = fmaf(a[i], b[j], acc[i][j]);
        }
        __syncthreads();
    }

#pragma unroll
    for (int i = 0; i < 8; i++) {
        long row = bm + ty * 8 + i;
#pragma unroll
        for (int j = 0; j < 8; j += 4) {
            float4 v = make_float4(acc[i][j], acc[i][j + 1], acc[i][j + 2], acc[i][j + 3]);
            *reinterpret_cast<float4*>(C + row * N + bn + tx * 8 + j) = v;
        }
    }
}

// ---------------------------------------------------------------------------
// RoPE (interleaved-pair form, matches reference) applied in-place to Q and K.
// One thread per (row, pair).
// ---------------------------------------------------------------------------
__global__ void rope_kernel(const int* __restrict__ pos)
{
    int idx = blockIdx.x * blockDim.x + threadIdx.x;
    const int total = M_ROWS * (D_MODEL / 2);
    if (idx >= total) return;

    int row = idx >> 9;        // / 512 pairs per row
    int p2  = idx & 511;
    int h   = p2 >> 5;         // 32 pairs per head
    int j   = p2 & 31;
    int s   = row & (SEQ - 1); // row = b*SEQ + s

    float inv = powf(10000.0f, -(float)(2 * j) / 64.0f);
    float ang = (float)pos[s] * inv;
    float sn, cs;
    sincosf(ang, &sn, &cs);

    int base = row * D_MODEL + h * HEAD_DIM + 2 * j;

    float x1 = g_Q[base], x2 = g_Q[base + 1];
    g_Q[base]     = x1 * cs - x2 * sn;
    g_Q[base + 1] = x1 * sn + x2 * cs;

    x1 = g_K[base]; x2 = g_K[base + 1];
    g_K[base]     = x1 * cs - x2 * sn;
    g_K[base + 1] = x1 * sn + x2 * cs;
}

// ---------------------------------------------------------------------------
// Flash attention, causal, fp32. 64 q-rows x 64 kv per block, 256 threads.
// Qs/Ks stored [d][row] (pad 68), Vs [kv][d] (64), Ss [kv][q] (pad 68).
// Thread (tx,ty) owns a 4x4 microtile: q in [ty*4, ...), col in [tx*4, ...).
// ---------------------------------------------------------------------------
#define SW 68
#define ATTN_SMEM_FLOATS (64 * SW * 3 + 64 * 64 + 3 * 64)
#define ATTN_SMEM_BYTES  (ATTN_SMEM_FLOATS * 4)

__global__ __launch_bounds__(256) void attn_kernel()
{
    extern __shared__ float smem[];
    float* Qs  = smem;               // [64][SW] : [d][q]
    float* Ks  = Qs + 64 * SW;       // [64][SW] : [d][kv]
    float* Vs  = Ks + 64 * SW;       // [64][64] : [kv][d]
    float* Ss  = Vs + 64 * 64;       // [64][SW] : [kv][q]
    float* m_s = Ss + 64 * SW;       // [64]
    float* a_s = m_s + 64;           // [64]
    float* l_s = a_s + 64;           // [64]

    const int tid = threadIdx.x;
    const int tx  = tid & 15;
    const int ty  = tid >> 4;
    const int qt  = blockIdx.x;
    const int bh  = blockIdx.y;
    const int b   = bh >> 4;
    const int h   = bh & 15;

    const long base_bh = (long)b * SEQ * D_MODEL + h * HEAD_DIM;
    const int  q0      = qt * 64;
    const int  i0      = ty * 4;
    const int  j0      = tx * 4;

    // Load Q tile transposed: Qs[d][r]
    {
        int d4 = (tid & 15) * 4;
        int r0 = tid >> 4;
#pragma unroll
        for (int p = 0; p < 4; p++) {
            int r = r0 + p * 16;
            float4 v = *reinterpret_cast<const float4*>(
                &g_Q[base_bh + (long)(q0 + r) * D_MODEL + d4]);
            Qs[(d4 + 0) * SW + r] = v.x;
            Qs[(d4 + 1) * SW + r] = v.y;
            Qs[(d4 + 2) * SW + r] = v.z;
            Qs[(d4 + 3) * SW + r] = v.w;
        }
    }

    float o[4][4];
#pragma unroll
    for (int i = 0; i < 4; i++)
#pragma unroll
        for (int j = 0; j < 4; j++) o[i][j] = 0.0f;

    float m_old = -INFINITY;   // owner state (valid for tid < 64)
    float l_run = 0.0f;

    for (int t = 0; t <= qt; t++) {
        const int k0 = t * 64;

        // Load K (transposed) and V (natural)
        {
            int d4 = (tid & 15) * 4;
            int r0 = tid >> 4;
#pragma unroll
            for (int p = 0; p < 4; p++) {
                int r = r0 + p * 16;
                float4 kv = *reinterpret_cast<const float4*>(
                    &g_K[base_bh + (long)(k0 + r) * D_MODEL + d4]);
                Ks[(d4 + 0) * SW + r] = kv.x;
                Ks[(d4 + 1) * SW + r] = kv.y;
                Ks[(d4 + 2) * SW + r] = kv.z;
                Ks[(d4 + 3) * SW + r] = kv.w;
                float4 vv = *reinterpret_cast<const float4*>(
                    &g_V[base_bh + (long)(k0 + r) * D_MODEL + d4]);
                *reinterpret_cast<float4*>(&Vs[r * 64 + d4]) = vv;
            }
        }
        __syncthreads();

        // S = scale * Q K^T  (+ causal mask)
        float s[4][4];
#pragma unroll
        for (int i = 0; i < 4; i++)
#pragma unroll
            for (int j = 0; j < 4; j++) s[i][j] = 0.0f;

#pragma unroll 16
        for (int d = 0; d < 64; d++) {
            float a[4], bb[4];
            *reinterpret_cast<float4*>(a)  = *reinterpret_cast<const float4*>(&Qs[d * SW + i0]);
            *reinterpret_cast<float4*>(bb) = *reinterpret_cast<const float4*>(&Ks[d * SW + j0]);
#pragma unroll
            for (int i = 0; i < 4; i++)
#pragma unroll
                for (int j = 0; j < 4; j++)
                    s[i][j] = fmaf(a[i], bb[j], s[i][j]);
        }

#pragma unroll
        for (int i = 0; i < 4; i++)
#pragma unroll
            for (int j = 0; j < 4; j++) {
                float val = s[i][j] * 0.125f;
                if (k0 + j0 + j > q0 + i0 + i) val = -INFINITY;
                s[i][j] = val;
                Ss[(j0 + j) * SW + (i0 + i)] = val;
            }
        __syncthreads();

        // Row max + alpha (owner threads)
        if (tid < 64) {
            float mx = -INFINITY;
#pragma unroll 8
            for (int k = 0; k < 64; k++) mx = fmaxf(mx, Ss[k * SW + tid]);
            float m_new = fmaxf(m_old, mx);
            m_s[tid] = m_new;
            a_s[tid] = __expf(m_old - m_new);
            m_old = m_new;
        }
        __syncthreads();

        // P = exp(S - m) — each thread handles its own 16 entries
        {
            float mi[4];
#pragma unroll
            for (int i = 0; i < 4; i++) mi[i] = m_s[i0 + i];
#pragma unroll
            for (int i = 0; i < 4; i++)
#pragma unroll
                for (int j = 0; j < 4; j++) {
                    float p = __expf(s[i][j] - mi[i]);
                    Ss[(j0 + j) * SW + (i0 + i)] = p;
                }
        }
        __syncthreads();

        // Row sum -> l update (owners), then rescale O and accumulate PV (all)
        if (tid < 64) {
            float sum = 0.0f;
#pragma unroll 8
            for (int k = 0; k < 64; k++) sum += Ss[k * SW + tid];
            l_run = l_run * a_s[tid] + sum;
        }
        {
            float al[4];
#pragma unroll
            for (int i = 0; i < 4; i++) al[i] = a_s[i0 + i];
#pragma unroll
            for (int i = 0; i < 4; i++)
#pragma unroll
                for (int j = 0; j < 4; j++) o[i][j] *= al[i];
        }
#pragma unroll 8
        for (int p = 0; p < 64; p++) {
            float a[4], v[4];
            *reinterpret_cast<float4*>(a) = *reinterpret_cast<const float4*>(&Ss[p * SW + i0]);
            *reinterpret_cast<float4*>(v) = *reinterpret_cast<const float4*>(&Vs[p * 64 + j0]);
#pragma unroll
            for (int i = 0; i < 4; i++)
#pragma unroll
                for (int j = 0; j < 4; j++)
                    o[i][j] = fmaf(a[i], v[j], o[i][j]);
        }
        __syncthreads();
    }

    if (tid < 64) l_s[tid] = l_run;
    __syncthreads();

#pragma unroll
    for (int i = 0; i < 4; i++) {
        float inv_l = 1.0f / l_s[i0 + i];
        long  row   = q0 + i0 + i;
        float4 v = make_float4(o[i][0] * inv_l, o[i][1] * inv_l,
                               o[i][2] * inv_l, o[i][3] * inv_l);
        *reinterpret_cast<float4*>(&g_AO[base_bh + row * D_MODEL + j0]) = v;
    }
}

// ---------------------------------------------------------------------------
// Launch
// ---------------------------------------------------------------------------
extern "C" void kernel_launch(void* const* d_in, const int* in_sizes, int n_in,
                              void* d_out, int out_size)
{
    const float* x   = (const float*)d_in[0];
    const int*   pos = (const int*)  d_in[1];
    const float* Wq  = (const float*)d_in[2];
    const float* Wk  = (const float*)d_in[3];
    const float* Wv  = (const float*)d_in[4];
    const float* Wo  = (const float*)d_in[5];
    float*       out = (float*)d_out;

    float *Qp, *Kp, *Vp, *AOp;
    cudaGetSymbolAddress((void**)&Qp,  g_Q);
    cudaGetSymbolAddress((void**)&Kp,  g_K);
    cudaGetSymbolAddress((void**)&Vp,  g_V);
    cudaGetSymbolAddress((void**)&AOp, g_AO);

    cudaFuncSetAttribute(attn_kernel,
                         cudaFuncAttributeMaxDynamicSharedMemorySize,
                         ATTN_SMEM_BYTES);

    dim3 ggrid(D_MODEL / 128, M_ROWS / 128);

    gemm_nt_kernel<<<ggrid, 256>>>(x, Wq, Qp, M_ROWS, D_MODEL, D_MODEL);
    gemm_nt_kernel<<<ggrid, 256>>>(x, Wk, Kp, M_ROWS, D_MODEL, D_MODEL);
    gemm_nt_kernel<<<ggrid, 256>>>(x, Wv, Vp, M_ROWS, D_MODEL, D_MODEL);

    int rope_total = M_ROWS * (D_MODEL / 2);
    rope_kernel<<<(rope_total + 255) / 256, 256>>>(pos);

    attn_kernel<<<dim3(SEQ / 64, BATCH * NUM_HEADS), 256, ATTN_SMEM_BYTES>>>();

    gemm_nt_kernel<<<ggrid, 256>>>(AOp, Wo, out, M_ROWS, D_MODEL, D_MODEL);
}

// round 3
// speedup vs baseline: 1.4623x; 1.4623x over previous
#include <cuda_runtime.h>
#include <cuda_bf16.h>
#include <math.h>
#include <stdint.h>

#define D_MODEL   1024
#define NUM_HEADS 16
#define HEAD_DIM  64
#define BATCH     4
#define SEQ       2048
#define M_ROWS    (BATCH * SEQ)   // 8192

// ---------------------------------------------------------------------------
// Scratch (allocation-free rule: __device__ globals)
// ---------------------------------------------------------------------------
__device__ float g_Q [M_ROWS * D_MODEL];
__device__ float g_K [M_ROWS * D_MODEL];
__device__ float g_V [M_ROWS * D_MODEL];
__device__ float g_AO[M_ROWS * D_MODEL];

__device__ __nv_bfloat16 g_xhi [M_ROWS * D_MODEL];
__device__ __nv_bfloat16 g_xlo [M_ROWS * D_MODEL];
__device__ __nv_bfloat16 g_aohi[M_ROWS * D_MODEL];
__device__ __nv_bfloat16 g_aolo[M_ROWS * D_MODEL];
__device__ __nv_bfloat16 g_wqhi[D_MODEL * D_MODEL];
__device__ __nv_bfloat16 g_wqlo[D_MODEL * D_MODEL];
__device__ __nv_bfloat16 g_wkhi[D_MODEL * D_MODEL];
__device__ __nv_bfloat16 g_wklo[D_MODEL * D_MODEL];
__device__ __nv_bfloat16 g_wvhi[D_MODEL * D_MODEL];
__device__ __nv_bfloat16 g_wvlo[D_MODEL * D_MODEL];
__device__ __nv_bfloat16 g_wohi[D_MODEL * D_MODEL];
__device__ __nv_bfloat16 g_wolo[D_MODEL * D_MODEL];

// ---------------------------------------------------------------------------
// Helpers
// ---------------------------------------------------------------------------
__device__ __forceinline__ uint32_t smem_u32(const void* p) {
    uint32_t a;
    asm("{ .reg .u64 t; cvta.to.shared.u64 t, %1; cvt.u32.u64 %0, t; }"
        : "=r"(a) : "l"(p));
    return a;
}

#define CP_ASYNC16(dst, src) \
    asm volatile("cp.async.cg.shared.global [%0], [%1], 16;" \
                 :: "r"(dst), "l"(src) : "memory")
#define CP_COMMIT() asm volatile("cp.async.commit_group;" ::: "memory")
#define CP_WAIT(n)  asm volatile("cp.async.wait_group %0;" :: "n"(n) : "memory")

#define LDMATRIX_X4(r0, r1, r2, r3, addr) \
    asm volatile("ldmatrix.sync.aligned.m8n8.x4.shared.b16 {%0,%1,%2,%3}, [%4];" \
                 : "=r"(r0), "=r"(r1), "=r"(r2), "=r"(r3) : "r"(addr))

#define MMA_BF16(d, a, b) \
    asm volatile("mma.sync.aligned.m16n8k16.row.col.f32.bf16.bf16.f32 " \
                 "{%0,%1,%2,%3}, {%4,%5,%6,%7}, {%8,%9}, {%0,%1,%2,%3};" \
                 : "+f"((d)[0]), "+f"((d)[1]), "+f"((d)[2]), "+f"((d)[3]) \
                 : "r"((a)[0]), "r"((a)[1]), "r"((a)[2]), "r"((a)[3]), \
                   "r"((b)[0]), "r"((b)[1]))

// ---------------------------------------------------------------------------
// fp32 -> bf16 hi/lo split conversion
// ---------------------------------------------------------------------------
__global__ void split_bf16_kernel(const float* __restrict__ src,
                                  __nv_bfloat16* __restrict__ hi,
                                  __nv_bfloat16* __restrict__ lo, int n4)
{
    int i = blockIdx.x * blockDim.x + threadIdx.x;
    if (i >= n4) return;
    float4 v = reinterpret_cast<const float4*>(src)[i];
    float vv[4] = {v.x, v.y, v.z, v.w};
    __align__(8) __nv_bfloat16 h[4];
    __align__(8) __nv_bfloat16 l[4];
#pragma unroll
    for (int j = 0; j < 4; j++) {
        h[j] = __float2bfloat16(vv[j]);
        float r = vv[j] - __bfloat162float(h[j]);
        l[j] = __float2bfloat16(r);
    }
    reinterpret_cast<uint2*>(hi)[i] = *reinterpret_cast<uint2*>(h);
    reinterpret_cast<uint2*>(lo)[i] = *reinterpret_cast<uint2*>(l);
}

// ---------------------------------------------------------------------------
// bf16-split HMMA GEMM:  C[M,N] = A[M,K] * B[N,K]^T   (fp32 via hi/lo split)
// 128x128 tile, BK=32, cp.async double buffer, 8 warps (4x2), warp tile 32x64.
// 3 fused passes: A_hi*B_hi, A_lo*B_hi, A_hi*B_lo  -> fp32 accumulators.
// smem rows padded to 80B (32 bf16 + 16B) for conflict-free ldmatrix.
// ---------------------------------------------------------------------------
#define BK       32
#define ROWB     80          // bytes per smem row

__global__ __launch_bounds__(256, 2) void gemm_mma_kernel(
    const __nv_bfloat16* __restrict__ Ahi, const __nv_bfloat16* __restrict__ Alo,
    const __nv_bfloat16* __restrict__ Bhi, const __nv_bfloat16* __restrict__ Blo,
    float* __restrict__ C, int M, int N, int K)
{
    __shared__ __align__(128) char sA[2][128 * ROWB];
    __shared__ __align__(128) char sB[2][128 * ROWB];

    const int tid  = threadIdx.x;
    const int warp = tid >> 5;
    const int lane = tid & 31;
    const int wr   = warp & 3;   // 0..3 : 32-row block
    const int wc   = warp >> 2;  // 0..1 : 64-col block
    const int bm   = blockIdx.y * 128;
    const int bn   = blockIdx.x * 128;

    float acc[2][8][4];
#pragma unroll
    for (int i = 0; i < 2; i++)
#pragma unroll
        for (int j = 0; j < 8; j++)
#pragma unroll
            for (int k = 0; k < 4; k++) acc[i][j][k] = 0.0f;

    const int nkc = K / BK;      // 32
    const int nch = 3 * nkc;     // 96

    auto load_chunk = [&](int c, int buf) {
        const int kc  = (c % nkc) * BK;
        const int sel = c / nkc;
        const __nv_bfloat16* As = (sel == 1) ? Alo : Ahi;
        const __nv_bfloat16* Bs = (sel == 2) ? Blo : Bhi;
#pragma unroll
        for (int p = 0; p < 2; p++) {
            int v   = tid + p * 256;
            int r   = v >> 2;
            int seg = v & 3;
            uint32_t da = smem_u32(&sA[buf][r * ROWB + seg * 16]);
            CP_ASYNC16(da, As + (size_t)(bm + r) * K + kc + seg * 8);
            uint32_t db = smem_u32(&sB[buf][r * ROWB + seg * 16]);
            CP_ASYNC16(db, Bs + (size_t)(bn + r) * K + kc + seg * 8);
        }
    };

    load_chunk(0, 0);
    CP_COMMIT();

    const int sub  = lane >> 3;   // 0..3
    const int lrow = lane & 7;    // 0..7

    for (int c = 0; c < nch; ++c) {
        const int buf = c & 1;
        if (c + 1 < nch) {
            load_chunk(c + 1, buf ^ 1);
            CP_COMMIT();
            CP_WAIT(1);
        } else {
            CP_WAIT(0);
        }
        __syncthreads();

#pragma unroll
        for (int s = 0; s < 2; ++s) {          // two k16 steps per BK=32 chunk
            // A fragments: 2 m16 tiles
            uint32_t af[2][4];
#pragma unroll
            for (int mt = 0; mt < 2; ++mt) {
                int row  = wr * 32 + mt * 16 + (sub & 1) * 8 + lrow;
                int half = sub >> 1;
                uint32_t ad = smem_u32(&sA[buf][row * ROWB + s * 32 + half * 16]);
                LDMATRIX_X4(af[mt][0], af[mt][1], af[mt][2], af[mt][3], ad);
            }
            // B fragments: 4 n16 tiles -> 8 n8 frags
            uint32_t bf[4][4];
#pragma unroll
            for (int nt = 0; nt < 4; ++nt) {
                int row  = wc * 64 + nt * 16 + (sub >> 1) * 8 + lrow;
                int half = sub & 1;
                uint32_t bd = smem_u32(&sB[buf][row * ROWB + s * 32 + half * 16]);
                LDMATRIX_X4(bf[nt][0], bf[nt][1], bf[nt][2], bf[nt][3], bd);
            }
#pragma unroll
            for (int mt = 0; mt < 2; ++mt)
#pragma unroll
                for (int nt = 0; nt < 8; ++nt) {
                    uint32_t bb[2] = { bf[nt >> 1][(nt & 1) * 2],
                                       bf[nt >> 1][(nt & 1) * 2 + 1] };
                    MMA_BF16(acc[mt][nt], af[mt], bb);
                }
        }
        __syncthreads();
    }

    // Epilogue
#pragma unroll
    for (int mt = 0; mt < 2; ++mt) {
#pragma unroll
        for (int nt = 0; nt < 8; ++nt) {
            int r0 = bm + wr * 32 + mt * 16 + (lane >> 2);
            int cc = bn + wc * 64 + nt * 8 + (lane & 3) * 2;
            *reinterpret_cast<float2*>(&C[(size_t)r0 * N + cc]) =
                make_float2(acc[mt][nt][0], acc[mt][nt][1]);
            *reinterpret_cast<float2*>(&C[(size_t)(r0 + 8) * N + cc]) =
                make_float2(acc[mt][nt][2], acc[mt][nt][3]);
        }
    }
}

// ---------------------------------------------------------------------------
// RoPE (interleaved-pair form, matches reference) applied in-place to Q and K.
// ---------------------------------------------------------------------------
__global__ void rope_kernel(const int* __restrict__ pos)
{
    int idx = blockIdx.x * blockDim.x + threadIdx.x;
    const int total = M_ROWS * (D_MODEL / 2);
    if (idx >= total) return;

    int row = idx >> 9;
    int p2  = idx & 511;
    int h   = p2 >> 5;
    int j   = p2 & 31;
    int s   = row & (SEQ - 1);

    float inv = powf(10000.0f, -(float)(2 * j) / 64.0f);
    float ang = (float)pos[s] * inv;
    float sn, cs;
    sincosf(ang, &sn, &cs);

    int base = row * D_MODEL + h * HEAD_DIM + 2 * j;

    float x1 = g_Q[base], x2 = g_Q[base + 1];
    g_Q[base]     = x1 * cs - x2 * sn;
    g_Q[base + 1] = x1 * sn + x2 * cs;

    x1 = g_K[base]; x2 = g_K[base + 1];
    g_K[base]     = x1 * cs - x2 * sn;
    g_K[base + 1] = x1 * sn + x2 * cs;
}

// ---------------------------------------------------------------------------
// Flash attention, causal, fp32 (unchanged — passed in R1).
// ---------------------------------------------------------------------------
#define SW 68
#define ATTN_SMEM_FLOATS (64 * SW * 3 + 64 * 64 + 3 * 64)
#define ATTN_SMEM_BYTES  (ATTN_SMEM_FLOATS * 4)

__global__ __launch_bounds__(256) void attn_kernel()
{
    extern __shared__ float smem[];
    float* Qs  = smem;
    float* Ks  = Qs + 64 * SW;
    float* Vs  = Ks + 64 * SW;
    float* Ss  = Vs + 64 * 64;
    float* m_s = Ss + 64 * SW;
    float* a_s = m_s + 64;
    float* l_s = a_s + 64;

    const int tid = threadIdx.x;
    const int tx  = tid & 15;
    const int ty  = tid >> 4;
    const int qt  = blockIdx.x;
    const int bh  = blockIdx.y;
    const int b   = bh >> 4;
    const int h   = bh & 15;

    const long base_bh = (long)b * SEQ * D_MODEL + h * HEAD_DIM;
    const int  q0      = qt * 64;
    const int  i0      = ty * 4;
    const int  j0      = tx * 4;

    {
        int d4 = (tid & 15) * 4;
        int r0 = tid >> 4;
#pragma unroll
        for (int p = 0; p < 4; p++) {
            int r = r0 + p * 16;
            float4 v = *reinterpret_cast<const float4*>(
                &g_Q[base_bh + (long)(q0 + r) * D_MODEL + d4]);
            Qs[(d4 + 0) * SW + r] = v.x;
            Qs[(d4 + 1) * SW + r] = v.y;
            Qs[(d4 + 2) * SW + r] = v.z;
            Qs[(d4 + 3) * SW + r] = v.w;
        }
    }

    float o[4][4];
#pragma unroll
    for (int i = 0; i < 4; i++)
#pragma unroll
        for (int j = 0; j < 4; j++) o[i][j] = 0.0f;

    float m_old = -INFINITY;
    float l_run = 0.0f;

    for (int t = 0; t <= qt; t++) {
        const int k0 = t * 64;

        {
            int d4 = (tid & 15) * 4;
            int r0 = tid >> 4;
#pragma unroll
            for (int p = 0; p < 4; p++) {
                int r = r0 + p * 16;
                float4 kv = *reinterpret_cast<const float4*>(
                    &g_K[base_bh + (long)(k0 + r) * D_MODEL + d4]);
                Ks[(d4 + 0) * SW + r] = kv.x;
                Ks[(d4 + 1) * SW + r] = kv.y;
                Ks[(d4 + 2) * SW + r] = kv.z;
                Ks[(d4 + 3) * SW + r] = kv.w;
                float4 vv = *reinterpret_cast<const float4*>(
                    &g_V[base_bh + (long)(k0 + r) * D_MODEL + d4]);
                *reinterpret_cast<float4*>(&Vs[r * 64 + d4]) = vv;
            }
        }
        __syncthreads();

        float s[4][4];
#pragma unroll
        for (int i = 0; i < 4; i++)
#pragma unroll
            for (int j = 0; j < 4; j++) s[i][j] = 0.0f;

#pragma unroll 16
        for (int d = 0; d < 64; d++) {
            float a[4], bb[4];
            *reinterpret_cast<float4*>(a)  = *reinterpret_cast<const float4*>(&Qs[d * SW + i0]);
            *reinterpret_cast<float4*>(bb) = *reinterpret_cast<const float4*>(&Ks[d * SW + j0]);
#pragma unroll
            for (int i = 0; i < 4; i++)
#pragma unroll
                for (int j = 0; j < 4; j++)
                    s[i][j] = fmaf(a[i], bb[j], s[i][j]);
        }

#pragma unroll
        for (int i = 0; i < 4; i++)
#pragma unroll
            for (int j = 0; j < 4; j++) {
                float val = s[i][j] * 0.125f;
                if (k0 + j0 + j > q0 + i0 + i) val = -INFINITY;
                s[i][j] = val;
                Ss[(j0 + j) * SW + (i0 + i)] = val;
            }
        __syncthreads();

        if (tid < 64) {
            float mx = -INFINITY;
#pragma unroll 8
            for (int k = 0; k < 64; k++) mx = fmaxf(mx, Ss[k * SW + tid]);
            float m_new = fmaxf(m_old, mx);
            m_s[tid] = m_new;
            a_s[tid] = __expf(m_old - m_new);
            m_old = m_new;
        }
        __syncthreads();

        {
            float mi[4];
#pragma unroll
            for (int i = 0; i < 4; i++) mi[i] = m_s[i0 + i];
#pragma unroll
            for (int i = 0; i < 4; i++)
#pragma unroll
                for (int j = 0; j < 4; j++) {
                    float p = __expf(s[i][j] - mi[i]);
                    Ss[(j0 + j) * SW + (i0 + i)] = p;
                }
        }
        __syncthreads();

        if (tid < 64) {
            float sum = 0.0f;
#pragma unroll 8
            for (int k = 0; k < 64; k++) sum += Ss[k * SW + tid];
            l_run = l_run * a_s[tid] + sum;
        }
        {
            float al[4];
#pragma unroll
            for (int i = 0; i < 4; i++) al[i] = a_s[i0 + i];
#pragma unroll
            for (int i = 0; i < 4; i++)
#pragma unroll
                for (int j = 0; j < 4; j++) o[i][j] *= al[i];
        }
#pragma unroll 8
        for (int p = 0; p < 64; p++) {
            float a[4], v[4];
            *reinterpret_cast<float4*>(a) = *reinterpret_cast<const float4*>(&Ss[p * SW + i0]);
            *reinterpret_cast<float4*>(v) = *reinterpret_cast<const float4*>(&Vs[p * 64 + j0]);
#pragma unroll
            for (int i = 0; i < 4; i++)
#pragma unroll
                for (int j = 0; j < 4; j++)
                    o[i][j] = fmaf(a[i], v[j], o[i][j]);
        }
        __syncthreads();
    }

    if (tid < 64) l_s[tid] = l_run;
    __syncthreads();

#pragma unroll
    for (int i = 0; i < 4; i++) {
        float inv_l = 1.0f / l_s[i0 + i];
        long  row   = q0 + i0 + i;
        float4 v = make_float4(o[i][0] * inv_l, o[i][1] * inv_l,
                               o[i][2] * inv_l, o[i][3] * inv_l);
        *reinterpret_cast<float4*>(&g_AO[base_bh + row * D_MODEL + j0]) = v;
    }
}

// ---------------------------------------------------------------------------
// Launch
// ---------------------------------------------------------------------------
extern "C" void kernel_launch(void* const* d_in, const int* in_sizes, int n_in,
                              void* d_out, int out_size)
{
    const float* x   = (const float*)d_in[0];
    const int*   pos = (const int*)  d_in[1];
    const float* Wq  = (const float*)d_in[2];
    const float* Wk  = (const float*)d_in[3];
    const float* Wv  = (const float*)d_in[4];
    const float* Wo  = (const float*)d_in[5];
    float*       out = (float*)d_out;

    float *Qp, *Kp, *Vp, *AOp;
    cudaGetSymbolAddress((void**)&Qp,  g_Q);
    cudaGetSymbolAddress((void**)&Kp,  g_K);
    cudaGetSymbolAddress((void**)&Vp,  g_V);
    cudaGetSymbolAddress((void**)&AOp, g_AO);

    __nv_bfloat16 *xhi, *xlo, *aohi, *aolo;
    __nv_bfloat16 *wqhi, *wqlo, *wkhi, *wklo, *wvhi, *wvlo, *wohi, *wolo;
    cudaGetSymbolAddress((void**)&xhi,  g_xhi);
    cudaGetSymbolAddress((void**)&xlo,  g_xlo);
    cudaGetSymbolAddress((void**)&aohi, g_aohi);
    cudaGetSymbolAddress((void**)&aolo, g_aolo);
    cudaGetSymbolAddress((void**)&wqhi, g_wqhi);
    cudaGetSymbolAddress((void**)&wqlo, g_wqlo);
    cudaGetSymbolAddress((void**)&wkhi, g_wkhi);
    cudaGetSymbolAddress((void**)&wklo, g_wklo);
    cudaGetSymbolAddress((void**)&wvhi, g_wvhi);
    cudaGetSymbolAddress((void**)&wvlo, g_wvlo);
    cudaGetSymbolAddress((void**)&wohi, g_wohi);
    cudaGetSymbolAddress((void**)&wolo, g_wolo);

    cudaFuncSetAttribute(attn_kernel,
                         cudaFuncAttributeMaxDynamicSharedMemorySize,
                         ATTN_SMEM_BYTES);

    const int nx = M_ROWS * D_MODEL / 4;
    const int nw = D_MODEL * D_MODEL / 4;

    split_bf16_kernel<<<(nx + 255) / 256, 256>>>(x,  xhi,  xlo,  nx);
    split_bf16_kernel<<<(nw + 255) / 256, 256>>>(Wq, wqhi, wqlo, nw);
    split_bf16_kernel<<<(nw + 255) / 256, 256>>>(Wk, wkhi, wklo, nw);
    split_bf16_kernel<<<(nw + 255) / 256, 256>>>(Wv, wvhi, wvlo, nw);
    split_bf16_kernel<<<(nw + 255) / 256, 256>>>(Wo, wohi, wolo, nw);

    dim3 ggrid(D_MODEL / 128, M_ROWS / 128);

    gemm_mma_kernel<<<ggrid, 256>>>(xhi, xlo, wqhi, wqlo, Qp, M_ROWS, D_MODEL, D_MODEL);
    gemm_mma_kernel<<<ggrid, 256>>>(xhi, xlo, wkhi, wklo, Kp, M_ROWS, D_MODEL, D_MODEL);
    gemm_mma_kernel<<<ggrid, 256>>>(xhi, xlo, wvhi, wvlo, Vp, M_ROWS, D_MODEL, D_MODEL);

    int rope_total = M_ROWS * (D_MODEL / 2);
    rope_kernel<<<(rope_total + 255) / 256, 256>>>(pos);

    attn_kernel<<<dim3(SEQ / 64, BATCH * NUM_HEADS), 256, ATTN_SMEM_BYTES>>>();

    split_bf16_kernel<<<(nx + 255) / 256, 256>>>(AOp, aohi, aolo, nx);
    gemm_mma_kernel<<<ggrid, 256>>>(aohi, aolo, wohi, wolo, out, M_ROWS, D_MODEL, D_MODEL);
}

// round 4
// speedup vs baseline: 2.5173x; 1.7215x over previous
#include <cuda_runtime.h>
#include <cuda_bf16.h>
#include <math.h>
#include <stdint.h>

#define D_MODEL   1024
#define NUM_HEADS 16
#define HEAD_DIM  64
#define BATCH     4
#define SEQ       2048
#define M_ROWS    (BATCH * SEQ)   // 8192

// ---------------------------------------------------------------------------
// Scratch (allocation-free rule: __device__ globals)
// ---------------------------------------------------------------------------
__device__ float g_Q [M_ROWS * D_MODEL];
__device__ float g_K [M_ROWS * D_MODEL];
__device__ float g_V [M_ROWS * D_MODEL];
__device__ float g_AO[M_ROWS * D_MODEL];

__device__ __nv_bfloat16 g_xhi [M_ROWS * D_MODEL];
__device__ __nv_bfloat16 g_xlo [M_ROWS * D_MODEL];
__device__ __nv_bfloat16 g_aohi[M_ROWS * D_MODEL];
__device__ __nv_bfloat16 g_aolo[M_ROWS * D_MODEL];
__device__ __nv_bfloat16 g_qhi [M_ROWS * D_MODEL];
__device__ __nv_bfloat16 g_qlo [M_ROWS * D_MODEL];
__device__ __nv_bfloat16 g_khi [M_ROWS * D_MODEL];
__device__ __nv_bfloat16 g_klo [M_ROWS * D_MODEL];
__device__ __nv_bfloat16 g_vhi [M_ROWS * D_MODEL];
__device__ __nv_bfloat16 g_vlo [M_ROWS * D_MODEL];
__device__ __nv_bfloat16 g_wqhi[D_MODEL * D_MODEL];
__device__ __nv_bfloat16 g_wqlo[D_MODEL * D_MODEL];
__device__ __nv_bfloat16 g_wkhi[D_MODEL * D_MODEL];
__device__ __nv_bfloat16 g_wklo[D_MODEL * D_MODEL];
__device__ __nv_bfloat16 g_wvhi[D_MODEL * D_MODEL];
__device__ __nv_bfloat16 g_wvlo[D_MODEL * D_MODEL];
__device__ __nv_bfloat16 g_wohi[D_MODEL * D_MODEL];
__device__ __nv_bfloat16 g_wolo[D_MODEL * D_MODEL];

// ---------------------------------------------------------------------------
// Helpers
// ---------------------------------------------------------------------------
__device__ __forceinline__ uint32_t smem_u32(const void* p) {
    uint32_t a;
    asm("{ .reg .u64 t; cvta.to.shared.u64 t, %1; cvt.u32.u64 %0, t; }"
        : "=r"(a) : "l"(p));
    return a;
}

#define CP_ASYNC16(dst, src) \
    asm volatile("cp.async.cg.shared.global [%0], [%1], 16;" \
                 :: "r"(dst), "l"(src) : "memory")
#define CP_COMMIT() asm volatile("cp.async.commit_group;" ::: "memory")
#define CP_WAIT(n)  asm volatile("cp.async.wait_group %0;" :: "n"(n) : "memory")

#define LDMATRIX_X4(r0, r1, r2, r3, addr) \
    asm volatile("ldmatrix.sync.aligned.m8n8.x4.shared.b16 {%0,%1,%2,%3}, [%4];" \
                 : "=r"(r0), "=r"(r1), "=r"(r2), "=r"(r3) : "r"(addr))

#define LDMATRIX_X4_T(r0, r1, r2, r3, addr) \
    asm volatile("ldmatrix.sync.aligned.m8n8.x4.trans.shared.b16 {%0,%1,%2,%3}, [%4];" \
                 : "=r"(r0), "=r"(r1), "=r"(r2), "=r"(r3) : "r"(addr))

#define MMA_BF16(d, a, b0, b1) \
    asm volatile("mma.sync.aligned.m16n8k16.row.col.f32.bf16.bf16.f32 " \
                 "{%0,%1,%2,%3}, {%4,%5,%6,%7}, {%8,%9}, {%0,%1,%2,%3};" \
                 : "+f"((d)[0]), "+f"((d)[1]), "+f"((d)[2]), "+f"((d)[3]) \
                 : "r"((a)[0]), "r"((a)[1]), "r"((a)[2]), "r"((a)[3]), \
                   "r"(b0), "r"(b1))

__device__ __forceinline__ uint32_t packbf(float lo, float hi) {
    __nv_bfloat162 t = __floats2bfloat162_rn(lo, hi);
    return *reinterpret_cast<uint32_t*>(&t);
}

// ---------------------------------------------------------------------------
// fp32 -> bf16 hi/lo split conversion
// ---------------------------------------------------------------------------
__global__ void split_bf16_kernel(const float* __restrict__ src,
                                  __nv_bfloat16* __restrict__ hi,
                                  __nv_bfloat16* __restrict__ lo, int n4)
{
    int i = blockIdx.x * blockDim.x + threadIdx.x;
    if (i >= n4) return;
    float4 v = reinterpret_cast<const float4*>(src)[i];
    float vv[4] = {v.x, v.y, v.z, v.w};
    __align__(8) __nv_bfloat16 h[4];
    __align__(8) __nv_bfloat16 l[4];
#pragma unroll
    for (int j = 0; j < 4; j++) {
        h[j] = __float2bfloat16(vv[j]);
        float r = vv[j] - __bfloat162float(h[j]);
        l[j] = __float2bfloat16(r);
    }
    reinterpret_cast<uint2*>(hi)[i] = *reinterpret_cast<uint2*>(h);
    reinterpret_cast<uint2*>(lo)[i] = *reinterpret_cast<uint2*>(l);
}

// ---------------------------------------------------------------------------
// bf16-split HMMA GEMM, 4-stage cp.async pipeline.
// C[M,N] = A[M,K] * B[N,K]^T ; 3 fused passes hi*hi + lo*hi + hi*lo.
// 128x128 tile, BK=32, 8 warps (4x2), warp tile 32x64, smem rows 80B.
// ---------------------------------------------------------------------------
#define BK       32
#define ROWB     80
#define GSTAGE_B (128 * ROWB * 2)   // A+B per stage = 20480
#define GEMM_SMEM (4 * GSTAGE_B)    // 81920

__global__ __launch_bounds__(256, 2) void gemm_mma_kernel(
    const __nv_bfloat16* __restrict__ Ahi, const __nv_bfloat16* __restrict__ Alo,
    const __nv_bfloat16* __restrict__ Bhi, const __nv_bfloat16* __restrict__ Blo,
    float* __restrict__ C, int M, int N, int K)
{
    extern __shared__ char gsm[];

    const int tid  = threadIdx.x;
    const int warp = tid >> 5;
    const int lane = tid & 31;
    const int wr   = warp & 3;
    const int wc   = warp >> 2;
    const int bm   = blockIdx.y * 128;
    const int bn   = blockIdx.x * 128;

    float acc[2][8][4];
#pragma unroll
    for (int i = 0; i < 2; i++)
#pragma unroll
        for (int j = 0; j < 8; j++)
#pragma unroll
            for (int k = 0; k < 4; k++) acc[i][j][k] = 0.0f;

    const int nkc = K / BK;
    const int nch = 3 * nkc;

    auto load_chunk = [&](int c, int stage) {
        const int kc  = (c % nkc) * BK;
        const int sel = c / nkc;
        const __nv_bfloat16* As = (sel == 1) ? Alo : Ahi;
        const __nv_bfloat16* Bs = (sel == 2) ? Blo : Bhi;
        char* sA = gsm + stage * GSTAGE_B;
        char* sB = sA + 128 * ROWB;
#pragma unroll
        for (int p = 0; p < 2; p++) {
            int v   = tid + p * 256;
            int r   = v >> 2;
            int seg = v & 3;
            CP_ASYNC16(smem_u32(sA + r * ROWB + seg * 16),
                       As + (size_t)(bm + r) * K + kc + seg * 8);
            CP_ASYNC16(smem_u32(sB + r * ROWB + seg * 16),
                       Bs + (size_t)(bn + r) * K + kc + seg * 8);
        }
    };

    load_chunk(0, 0); CP_COMMIT();
    load_chunk(1, 1); CP_COMMIT();
    load_chunk(2, 2); CP_COMMIT();

    const int sub  = lane >> 3;
    const int lrow = lane & 7;

    for (int c = 0; c < nch; ++c) {
        const int stage = c & 3;
        {
            int rem = nch - 1 - c;
            if (rem >= 2)      { CP_WAIT(2); }
            else if (rem == 1) { CP_WAIT(1); }
            else               { CP_WAIT(0); }
        }
        __syncthreads();
        if (c + 3 < nch) { load_chunk(c + 3, (c + 3) & 3); CP_COMMIT(); }

        char* sA = gsm + stage * GSTAGE_B;
        char* sB = sA + 128 * ROWB;

#pragma unroll
        for (int s = 0; s < 2; ++s) {
            uint32_t af[2][4];
#pragma unroll
            for (int mt = 0; mt < 2; ++mt) {
                int row = wr * 32 + mt * 16 + (sub & 1) * 8 + lrow;
                uint32_t ad = smem_u32(sA + row * ROWB + s * 32 + (sub >> 1) * 16);
                LDMATRIX_X4(af[mt][0], af[mt][1], af[mt][2], af[mt][3], ad);
            }
            uint32_t bf[4][4];
#pragma unroll
            for (int nt = 0; nt < 4; ++nt) {
                int row = wc * 64 + nt * 16 + (sub >> 1) * 8 + lrow;
                uint32_t bd = smem_u32(sB + row * ROWB + s * 32 + (sub & 1) * 16);
                LDMATRIX_X4(bf[nt][0], bf[nt][1], bf[nt][2], bf[nt][3], bd);
            }
#pragma unroll
            for (int mt = 0; mt < 2; ++mt)
#pragma unroll
                for (int nt = 0; nt < 8; ++nt)
                    MMA_BF16(acc[mt][nt], af[mt],
                             bf[nt >> 1][(nt & 1) * 2], bf[nt >> 1][(nt & 1) * 2 + 1]);
        }
    }

#pragma unroll
    for (int mt = 0; mt < 2; ++mt) {
#pragma unroll
        for (int nt = 0; nt < 8; ++nt) {
            int r0 = bm + wr * 32 + mt * 16 + (lane >> 2);
            int cc = bn + wc * 64 + nt * 8 + (lane & 3) * 2;
            *reinterpret_cast<float2*>(&C[(size_t)r0 * N + cc]) =
                make_float2(acc[mt][nt][0], acc[mt][nt][1]);
            *reinterpret_cast<float2*>(&C[(size_t)(r0 + 8) * N + cc]) =
                make_float2(acc[mt][nt][2], acc[mt][nt][3]);
        }
    }
}

// ---------------------------------------------------------------------------
// RoPE (interleaved-pair, matches reference) in-place on Q and K.
// ---------------------------------------------------------------------------
__global__ void rope_kernel(const int* __restrict__ pos)
{
    int idx = blockIdx.x * blockDim.x + threadIdx.x;
    const int total = M_ROWS * (D_MODEL / 2);
    if (idx >= total) return;

    int row = idx >> 9;
    int p2  = idx & 511;
    int h   = p2 >> 5;
    int j   = p2 & 31;
    int s   = row & (SEQ - 1);

    float inv = powf(10000.0f, -(float)(2 * j) / 64.0f);
    float ang = (float)pos[s] * inv;
    float sn, cs;
    sincosf(ang, &sn, &cs);

    int base = row * D_MODEL + h * HEAD_DIM + 2 * j;

    float x1 = g_Q[base], x2 = g_Q[base + 1];
    g_Q[base]     = x1 * cs - x2 * sn;
    g_Q[base + 1] = x1 * sn + x2 * cs;

    x1 = g_K[base]; x2 = g_K[base + 1];
    g_K[base]     = x1 * cs - x2 * sn;
    g_K[base + 1] = x1 * sn + x2 * cs;
}

// ---------------------------------------------------------------------------
// HMMA flash attention, causal.
// CTA: 128 q-rows, 8 warps (warp w owns q rows 16w..16w+15), KV tiles of 64.
// QK^T: 3-pass bf16 split; P.V: 3-pass (Phi*Vhi + Plo*Vhi + Phi*Vlo).
// smem: double-buffered KV tiles {Khi,Klo,Vhi,Vlo}[64][72] bf16 (144B rows).
// ---------------------------------------------------------------------------
#define AT_ROWE 72
#define KV_ARRE (64 * AT_ROWE)          // 4608 elems per array
#define KV_BUFE (4 * KV_ARRE)           // 18432 elems per buffer
#define ATTN_SMEM (2 * KV_BUFE * 2)     // 73728 bytes

__global__ __launch_bounds__(256, 1) void attn_mma_kernel()
{
    extern __shared__ char at_sm[];
    __nv_bfloat16* smb = reinterpret_cast<__nv_bfloat16*>(at_sm);

    const int tid  = threadIdx.x;
    const int w    = tid >> 5;
    const int lane = tid & 31;
    const int sub  = lane >> 3;
    const int lrow = lane & 7;
    const int qt   = blockIdx.x;
    const int bh   = blockIdx.y;
    const int b    = bh >> 4;
    const int h    = bh & 15;

    const size_t rowbase = (size_t)b * SEQ;
    const int    q0      = qt * 128;

    // ---- Stage Q (hi/lo) through smem, capture fragments ----
    {
        const __nv_bfloat16* srcs[2];
        srcs[0] = g_qhi; srcs[1] = g_qlo;
#pragma unroll
        for (int arr = 0; arr < 2; ++arr) {
            const __nv_bfloat16* s = srcs[arr] + (rowbase + q0) * D_MODEL + h * 64;
            __nv_bfloat16* d = smb + arr * (128 * AT_ROWE);
#pragma unroll
            for (int p = 0; p < 4; ++p) {
                int v = tid + p * 256;
                int r = v >> 3, seg = v & 7;
                CP_ASYNC16(smem_u32(d + r * AT_ROWE + seg * 8),
                           s + (size_t)r * D_MODEL + seg * 8);
            }
        }
        CP_COMMIT(); CP_WAIT(0);
        __syncthreads();
    }

    uint32_t qh[4][4], ql[4][4];
#pragma unroll
    for (int kt = 0; kt < 4; ++kt) {
        int row = w * 16 + (sub & 1) * 8 + lrow;
        int col = kt * 16 + (sub >> 1) * 8;
        uint32_t a0 = smem_u32(smb + row * AT_ROWE + col);
        LDMATRIX_X4(qh[kt][0], qh[kt][1], qh[kt][2], qh[kt][3], a0);
        uint32_t a1 = smem_u32(smb + 128 * AT_ROWE + row * AT_ROWE + col);
        LDMATRIX_X4(ql[kt][0], ql[kt][1], ql[kt][2], ql[kt][3], a1);
    }
    __syncthreads();   // Q smem region now reusable as KV buffers

    float O[8][4];
#pragma unroll
    for (int i = 0; i < 8; i++)
#pragma unroll
        for (int j = 0; j < 4; j++) O[i][j] = 0.0f;
    float mrow[2] = { -INFINITY, -INFINITY };
    float lrow2[2] = { 0.0f, 0.0f };

    const int ntiles = 2 * qt + 2;

    auto load_kv = [&](int k0, __nv_bfloat16* buf) {
        const __nv_bfloat16* srcs[4];
        srcs[0] = g_khi; srcs[1] = g_klo; srcs[2] = g_vhi; srcs[3] = g_vlo;
#pragma unroll
        for (int arr = 0; arr < 4; ++arr) {
            const __nv_bfloat16* s = srcs[arr] + (rowbase + k0) * D_MODEL + h * 64;
            __nv_bfloat16* d = buf + arr * KV_ARRE;
#pragma unroll
            for (int p = 0; p < 2; ++p) {
                int v = tid + p * 256;
                int r = v >> 3, seg = v & 7;
                CP_ASYNC16(smem_u32(d + r * AT_ROWE + seg * 8),
                           s + (size_t)r * D_MODEL + seg * 8);
            }
        }
    };

    load_kv(0, smb); CP_COMMIT();

    for (int t = 0; t < ntiles; ++t) {
        __nv_bfloat16* cbuf = smb + (t & 1) * KV_BUFE;
        if (t + 1 < ntiles) {
            load_kv((t + 1) * 64, smb + ((t + 1) & 1) * KV_BUFE);
            CP_COMMIT();
            CP_WAIT(1);
        } else {
            CP_WAIT(0);
        }
        __syncthreads();

        const int k0 = t * 64;
        const bool active = (k0 <= q0 + w * 16 + 15);

        if (active) {
            __nv_bfloat16* sKhi = cbuf;
            __nv_bfloat16* sKlo = cbuf + KV_ARRE;
            __nv_bfloat16* sVhi = cbuf + 2 * KV_ARRE;
            __nv_bfloat16* sVlo = cbuf + 3 * KV_ARRE;

            // ---- S = Q K^T (3-pass split) ----
            float sacc[8][4];
#pragma unroll
            for (int i = 0; i < 8; i++)
#pragma unroll
                for (int j = 0; j < 4; j++) sacc[i][j] = 0.0f;

#pragma unroll
            for (int kt = 0; kt < 4; ++kt) {
#pragma unroll
                for (int g = 0; g < 4; ++g) {
                    int row = g * 16 + (sub >> 1) * 8 + lrow;
                    int col = kt * 16 + (sub & 1) * 8;
                    uint32_t kh[4], kl[4];
                    LDMATRIX_X4(kh[0], kh[1], kh[2], kh[3],
                                smem_u32(sKhi + row * AT_ROWE + col));
                    LDMATRIX_X4(kl[0], kl[1], kl[2], kl[3],
                                smem_u32(sKlo + row * AT_ROWE + col));
                    MMA_BF16(sacc[2 * g],     qh[kt], kh[0], kh[1]);
                    MMA_BF16(sacc[2 * g + 1], qh[kt], kh[2], kh[3]);
                    MMA_BF16(sacc[2 * g],     ql[kt], kh[0], kh[1]);
                    MMA_BF16(sacc[2 * g + 1], ql[kt], kh[2], kh[3]);
                    MMA_BF16(sacc[2 * g],     qh[kt], kl[0], kl[1]);
                    MMA_BF16(sacc[2 * g + 1], qh[kt], kl[2], kl[3]);
                }
            }

            // ---- scale + causal mask ----
            const int qrow0 = q0 + w * 16 + (lane >> 2);
            const bool need_mask = (k0 + 63 > q0 + w * 16);
#pragma unroll
            for (int nt = 0; nt < 8; ++nt) {
#pragma unroll
                for (int j = 0; j < 4; j++) sacc[nt][j] *= 0.125f;
                if (need_mask) {
                    int col = k0 + nt * 8 + (lane & 3) * 2;
                    if (col     > qrow0)     sacc[nt][0] = -INFINITY;
                    if (col + 1 > qrow0)     sacc[nt][1] = -INFINITY;
                    if (col     > qrow0 + 8) sacc[nt][2] = -INFINITY;
                    if (col + 1 > qrow0 + 8) sacc[nt][3] = -INFINITY;
                }
            }

            // ---- online softmax ----
            float mx0 = -INFINITY, mx1 = -INFINITY;
#pragma unroll
            for (int nt = 0; nt < 8; ++nt) {
                mx0 = fmaxf(mx0, fmaxf(sacc[nt][0], sacc[nt][1]));
                mx1 = fmaxf(mx1, fmaxf(sacc[nt][2], sacc[nt][3]));
            }
            mx0 = fmaxf(mx0, __shfl_xor_sync(0xffffffff, mx0, 1));
            mx0 = fmaxf(mx0, __shfl_xor_sync(0xffffffff, mx0, 2));
            mx1 = fmaxf(mx1, __shfl_xor_sync(0xffffffff, mx1, 1));
            mx1 = fmaxf(mx1, __shfl_xor_sync(0xffffffff, mx1, 2));

            float mn0 = fmaxf(mrow[0], mx0);
            float mn1 = fmaxf(mrow[1], mx1);
            float a0 = __expf(mrow[0] - mn0);
            float a1 = __expf(mrow[1] - mn1);
            mrow[0] = mn0; mrow[1] = mn1;

            float rs0 = 0.0f, rs1 = 0.0f;
#pragma unroll
            for (int nt = 0; nt < 8; ++nt) {
                sacc[nt][0] = __expf(sacc[nt][0] - mn0);
                sacc[nt][1] = __expf(sacc[nt][1] - mn0);
                sacc[nt][2] = __expf(sacc[nt][2] - mn1);
                sacc[nt][3] = __expf(sacc[nt][3] - mn1);
                rs0 += sacc[nt][0] + sacc[nt][1];
                rs1 += sacc[nt][2] + sacc[nt][3];
            }
            rs0 += __shfl_xor_sync(0xffffffff, rs0, 1);
            rs0 += __shfl_xor_sync(0xffffffff, rs0, 2);
            rs1 += __shfl_xor_sync(0xffffffff, rs1, 1);
            rs1 += __shfl_xor_sync(0xffffffff, rs1, 2);
            lrow2[0] = lrow2[0] * a0 + rs0;
            lrow2[1] = lrow2[1] * a1 + rs1;

#pragma unroll
            for (int dn = 0; dn < 8; ++dn) {
                O[dn][0] *= a0; O[dn][1] *= a0;
                O[dn][2] *= a1; O[dn][3] *= a1;
            }

            // ---- pack P hi/lo fragments (A-operand layout) ----
            uint32_t ph[4][4], pl[4][4];
#pragma unroll
            for (int kt = 0; kt < 4; ++kt) {
                float e[8] = { sacc[2 * kt][0],     sacc[2 * kt][1],
                               sacc[2 * kt][2],     sacc[2 * kt][3],
                               sacc[2 * kt + 1][0], sacc[2 * kt + 1][1],
                               sacc[2 * kt + 1][2], sacc[2 * kt + 1][3] };
                float r[8];
#pragma unroll
                for (int i = 0; i < 8; i++)
                    r[i] = e[i] - __bfloat162float(__float2bfloat16_rn(e[i]));
                ph[kt][0] = packbf(e[0], e[1]);
                ph[kt][1] = packbf(e[2], e[3]);
                ph[kt][2] = packbf(e[4], e[5]);
                ph[kt][3] = packbf(e[6], e[7]);
                pl[kt][0] = packbf(r[0], r[1]);
                pl[kt][1] = packbf(r[2], r[3]);
                pl[kt][2] = packbf(r[4], r[5]);
                pl[kt][3] = packbf(r[6], r[7]);
            }

            // ---- O += P V (3-pass split) ----
#pragma unroll
            for (int kt = 0; kt < 4; ++kt) {
#pragma unroll
                for (int dg = 0; dg < 4; ++dg) {
                    int row = kt * 16 + (sub & 1) * 8 + lrow;
                    int col = dg * 16 + (sub >> 1) * 8;
                    uint32_t vh[4], vl[4];
                    LDMATRIX_X4_T(vh[0], vh[1], vh[2], vh[3],
                                  smem_u32(sVhi + row * AT_ROWE + col));
                    LDMATRIX_X4_T(vl[0], vl[1], vl[2], vl[3],
                                  smem_u32(sVlo + row * AT_ROWE + col));
                    MMA_BF16(O[2 * dg],     ph[kt], vh[0], vh[1]);
                    MMA_BF16(O[2 * dg + 1], ph[kt], vh[2], vh[3]);
                    MMA_BF16(O[2 * dg],     pl[kt], vh[0], vh[1]);
                    MMA_BF16(O[2 * dg + 1], pl[kt], vh[2], vh[3]);
                    MMA_BF16(O[2 * dg],     ph[kt], vl[0], vl[1]);
                    MMA_BF16(O[2 * dg + 1], ph[kt], vl[2], vl[3]);
                }
            }
        }
        __syncthreads();
    }

    // ---- normalize + write ----
    const float inv0 = 1.0f / lrow2[0];
    const float inv1 = 1.0f / lrow2[1];
    const size_t r0 = rowbase + q0 + w * 16 + (lane >> 2);
#pragma unroll
    for (int dn = 0; dn < 8; ++dn) {
        int col = h * 64 + dn * 8 + (lane & 3) * 2;
        *reinterpret_cast<float2*>(&g_AO[r0 * D_MODEL + col]) =
            make_float2(O[dn][0] * inv0, O[dn][1] * inv0);
        *reinterpret_cast<float2*>(&g_AO[(r0 + 8) * D_MODEL + col]) =
            make_float2(O[dn][2] * inv1, O[dn][3] * inv1);
    }
}

// ---------------------------------------------------------------------------
// Launch
// ---------------------------------------------------------------------------
extern "C" void kernel_launch(void* const* d_in, const int* in_sizes, int n_in,
                              void* d_out, int out_size)
{
    const float* x   = (const float*)d_in[0];
    const int*   pos = (const int*)  d_in[1];
    const float* Wq  = (const float*)d_in[2];
    const float* Wk  = (const float*)d_in[3];
    const float* Wv  = (const float*)d_in[4];
    const float* Wo  = (const float*)d_in[5];
    float*       out = (float*)d_out;

    float *Qp, *Kp, *Vp, *AOp;
    cudaGetSymbolAddress((void**)&Qp,  g_Q);
    cudaGetSymbolAddress((void**)&Kp,  g_K);
    cudaGetSymbolAddress((void**)&Vp,  g_V);
    cudaGetSymbolAddress((void**)&AOp, g_AO);

    __nv_bfloat16 *xhi, *xlo, *aohi, *aolo;
    __nv_bfloat16 *qhi, *qlo, *khi, *klo, *vhi, *vlo;
    __nv_bfloat16 *wqhi, *wqlo, *wkhi, *wklo, *wvhi, *wvlo, *wohi, *wolo;
    cudaGetSymbolAddress((void**)&xhi,  g_xhi);
    cudaGetSymbolAddress((void**)&xlo,  g_xlo);
    cudaGetSymbolAddress((void**)&aohi, g_aohi);
    cudaGetSymbolAddress((void**)&aolo, g_aolo);
    cudaGetSymbolAddress((void**)&qhi,  g_qhi);
    cudaGetSymbolAddress((void**)&qlo,  g_qlo);
    cudaGetSymbolAddress((void**)&khi,  g_khi);
    cudaGetSymbolAddress((void**)&klo,  g_klo);
    cudaGetSymbolAddress((void**)&vhi,  g_vhi);
    cudaGetSymbolAddress((void**)&vlo,  g_vlo);
    cudaGetSymbolAddress((void**)&wqhi, g_wqhi);
    cudaGetSymbolAddress((void**)&wqlo, g_wqlo);
    cudaGetSymbolAddress((void**)&wkhi, g_wkhi);
    cudaGetSymbolAddress((void**)&wklo, g_wklo);
    cudaGetSymbolAddress((void**)&wvhi, g_wvhi);
    cudaGetSymbolAddress((void**)&wvlo, g_wvlo);
    cudaGetSymbolAddress((void**)&wohi, g_wohi);
    cudaGetSymbolAddress((void**)&wolo, g_wolo);

    cudaFuncSetAttribute(gemm_mma_kernel,
                         cudaFuncAttributeMaxDynamicSharedMemorySize, GEMM_SMEM);
    cudaFuncSetAttribute(attn_mma_kernel,
                         cudaFuncAttributeMaxDynamicSharedMemorySize, ATTN_SMEM);

    const int nx = M_ROWS * D_MODEL / 4;
    const int nw = D_MODEL * D_MODEL / 4;

    split_bf16_kernel<<<(nx + 255) / 256, 256>>>(x,  xhi,  xlo,  nx);
    split_bf16_kernel<<<(nw + 255) / 256, 256>>>(Wq, wqhi, wqlo, nw);
    split_bf16_kernel<<<(nw + 255) / 256, 256>>>(Wk, wkhi, wklo, nw);
    split_bf16_kernel<<<(nw + 255) / 256, 256>>>(Wv, wvhi, wvlo, nw);
    split_bf16_kernel<<<(nw + 255) / 256, 256>>>(Wo, wohi, wolo, nw);

    dim3 ggrid(D_MODEL / 128, M_ROWS / 128);

    gemm_mma_kernel<<<ggrid, 256, GEMM_SMEM>>>(xhi, xlo, wqhi, wqlo, Qp,
                                               M_ROWS, D_MODEL, D_MODEL);
    gemm_mma_kernel<<<ggrid, 256, GEMM_SMEM>>>(xhi, xlo, wkhi, wklo, Kp,
                                               M_ROWS, D_MODEL, D_MODEL);
    gemm_mma_kernel<<<ggrid, 256, GEMM_SMEM>>>(xhi, xlo, wvhi, wvlo, Vp,
                                               M_ROWS, D_MODEL, D_MODEL);

    int rope_total = M_ROWS * (D_MODEL / 2);
    rope_kernel<<<(rope_total + 255) / 256, 256>>>(pos);

    split_bf16_kernel<<<(nx + 255) / 256, 256>>>(Qp, qhi, qlo, nx);
    split_bf16_kernel<<<(nx + 255) / 256, 256>>>(Kp, khi, klo, nx);
    split_bf16_kernel<<<(nx + 255) / 256, 256>>>(Vp, vhi, vlo, nx);

    attn_mma_kernel<<<dim3(SEQ / 128, BATCH * NUM_HEADS), 256, ATTN_SMEM>>>();

    split_bf16_kernel<<<(nx + 255) / 256, 256>>>(AOp, aohi, aolo, nx);
    gemm_mma_kernel<<<ggrid, 256, GEMM_SMEM>>>(aohi, aolo, wohi, wolo, out,
                                               M_ROWS, D_MODEL, D_MODEL);
}

// round 6
// speedup vs baseline: 2.5932x; 1.0301x over previous
#include <cuda_runtime.h>
#include <cuda_bf16.h>
#include <math.h>
#include <stdint.h>

#define D_MODEL   1024
#define NUM_HEADS 16
#define HEAD_DIM  64
#define BATCH     4
#define SEQ       2048
#define M_ROWS    (BATCH * SEQ)   // 8192

// ---------------------------------------------------------------------------
// Scratch (allocation-free rule: __device__ globals)
// ---------------------------------------------------------------------------
__device__ float g_Q [M_ROWS * D_MODEL];
__device__ float g_K [M_ROWS * D_MODEL];
__device__ float g_V [M_ROWS * D_MODEL];
__device__ float g_AO[M_ROWS * D_MODEL];

__device__ __nv_bfloat16 g_xhi [M_ROWS * D_MODEL];
__device__ __nv_bfloat16 g_xlo [M_ROWS * D_MODEL];
__device__ __nv_bfloat16 g_aohi[M_ROWS * D_MODEL];
__device__ __nv_bfloat16 g_aolo[M_ROWS * D_MODEL];
__device__ __nv_bfloat16 g_qhi [M_ROWS * D_MODEL];
__device__ __nv_bfloat16 g_qlo [M_ROWS * D_MODEL];
__device__ __nv_bfloat16 g_khi [M_ROWS * D_MODEL];
__device__ __nv_bfloat16 g_klo [M_ROWS * D_MODEL];
__device__ __nv_bfloat16 g_vhi [M_ROWS * D_MODEL];
__device__ __nv_bfloat16 g_vlo [M_ROWS * D_MODEL];
__device__ __nv_bfloat16 g_wqhi[D_MODEL * D_MODEL];
__device__ __nv_bfloat16 g_wqlo[D_MODEL * D_MODEL];
__device__ __nv_bfloat16 g_wkhi[D_MODEL * D_MODEL];
__device__ __nv_bfloat16 g_wklo[D_MODEL * D_MODEL];
__device__ __nv_bfloat16 g_wvhi[D_MODEL * D_MODEL];
__device__ __nv_bfloat16 g_wvlo[D_MODEL * D_MODEL];
__device__ __nv_bfloat16 g_wohi[D_MODEL * D_MODEL];
__device__ __nv_bfloat16 g_wolo[D_MODEL * D_MODEL];

// ---------------------------------------------------------------------------
// Helpers
// ---------------------------------------------------------------------------
__device__ __forceinline__ uint32_t smem_u32(const void* p) {
    uint32_t a;
    asm("{ .reg .u64 t; cvta.to.shared.u64 t, %1; cvt.u32.u64 %0, t; }"
        : "=r"(a) : "l"(p));
    return a;
}

#define CP_ASYNC16(dst, src) \
    asm volatile("cp.async.cg.shared.global [%0], [%1], 16;" \
                 :: "r"(dst), "l"(src) : "memory")
#define CP_COMMIT() asm volatile("cp.async.commit_group;" ::: "memory")
#define CP_WAIT(n)  asm volatile("cp.async.wait_group %0;" :: "n"(n) : "memory")

#define LDMATRIX_X4(r0, r1, r2, r3, addr) \
    asm volatile("ldmatrix.sync.aligned.m8n8.x4.shared.b16 {%0,%1,%2,%3}, [%4];" \
                 : "=r"(r0), "=r"(r1), "=r"(r2), "=r"(r3) : "r"(addr))

#define LDMATRIX_X4_T(r0, r1, r2, r3, addr) \
    asm volatile("ldmatrix.sync.aligned.m8n8.x4.trans.shared.b16 {%0,%1,%2,%3}, [%4];" \
                 : "=r"(r0), "=r"(r1), "=r"(r2), "=r"(r3) : "r"(addr))

#define MMA_BF16(d, a, b0, b1) \
    asm volatile("mma.sync.aligned.m16n8k16.row.col.f32.bf16.bf16.f32 " \
                 "{%0,%1,%2,%3}, {%4,%5,%6,%7}, {%8,%9}, {%0,%1,%2,%3};" \
                 : "+f"((d)[0]), "+f"((d)[1]), "+f"((d)[2]), "+f"((d)[3]) \
                 : "r"((a)[0]), "r"((a)[1]), "r"((a)[2]), "r"((a)[3]), \
                   "r"(b0), "r"(b1))

__device__ __forceinline__ uint32_t packbf(float lo, float hi) {
    __nv_bfloat162 t = __floats2bfloat162_rn(lo, hi);
    return *reinterpret_cast<uint32_t*>(&t);
}

// ---------------------------------------------------------------------------
// fp32 -> bf16 hi/lo split
// ---------------------------------------------------------------------------
__global__ void split_bf16_kernel(const float* __restrict__ src,
                                  __nv_bfloat16* __restrict__ hi,
                                  __nv_bfloat16* __restrict__ lo, int n4)
{
    int i = blockIdx.x * blockDim.x + threadIdx.x;
    if (i >= n4) return;
    float4 v = reinterpret_cast<const float4*>(src)[i];
    float vv[4] = {v.x, v.y, v.z, v.w};
    __align__(8) __nv_bfloat16 h[4];
    __align__(8) __nv_bfloat16 l[4];
#pragma unroll
    for (int j = 0; j < 4; j++) {
        h[j] = __float2bfloat16(vv[j]);
        float r = vv[j] - __bfloat162float(h[j]);
        l[j] = __float2bfloat16(r);
    }
    reinterpret_cast<uint2*>(hi)[i] = *reinterpret_cast<uint2*>(h);
    reinterpret_cast<uint2*>(lo)[i] = *reinterpret_cast<uint2*>(l);
}

// ---------------------------------------------------------------------------
// Fused RoPE + bf16 hi/lo split (reads fp32 src, writes hi/lo bf16)
// ---------------------------------------------------------------------------
__global__ void rope_split_kernel(const int* __restrict__ pos,
                                  const float* __restrict__ src,
                                  __nv_bfloat16* __restrict__ hi,
                                  __nv_bfloat16* __restrict__ lo)
{
    int idx = blockIdx.x * blockDim.x + threadIdx.x;
    const int total = M_ROWS * (D_MODEL / 2);
    if (idx >= total) return;

    int row = idx >> 9;
    int p2  = idx & 511;
    int h   = p2 >> 5;
    int j   = p2 & 31;
    int s   = row & (SEQ - 1);

    float inv = powf(10000.0f, -(float)(2 * j) / 64.0f);
    float ang = (float)pos[s] * inv;
    float sn, cs;
    sincosf(ang, &sn, &cs);

    int base = row * D_MODEL + h * HEAD_DIM + 2 * j;
    float2 v = *reinterpret_cast<const float2*>(src + base);
    float y0 = v.x * cs - v.y * sn;
    float y1 = v.x * sn + v.y * cs;

    __nv_bfloat16 h0 = __float2bfloat16(y0);
    __nv_bfloat16 h1 = __float2bfloat16(y1);
    float r0 = y0 - __bfloat162float(h0);
    float r1 = y1 - __bfloat162float(h1);

    __nv_bfloat162 hp = make_bfloat162(h0, h1);
    __nv_bfloat162 lp = make_bfloat162(__float2bfloat16(r0), __float2bfloat16(r1));
    *reinterpret_cast<uint32_t*>(hi + base) = *reinterpret_cast<uint32_t*>(&hp);
    *reinterpret_cast<uint32_t*>(lo + base) = *reinterpret_cast<uint32_t*>(&lp);
}

// ---------------------------------------------------------------------------
// bf16-split HMMA GEMM, combined hi/lo chunk loads.
// C[M,N] = A[M,K] * B[N,K]^T ; per chunk: Ahi,Alo,Bhi,Blo resident -> 3 passes.
// 128x128 tile, BK=32, 4-stage cp.async, 8 warps (4x2), warp tile 32x64.
// Stage = 512 rows x 80B = 40960B; 4 stages = 163840B, 1 CTA/SM.
// ---------------------------------------------------------------------------
#define BK        32
#define ROWB      80
#define GSTAGE_B  (512 * ROWB)      // 40960
#define GEMM_SMEM (4 * GSTAGE_B)    // 163840

__global__ __launch_bounds__(256, 1) void gemm_mma_kernel(
    const __nv_bfloat16* __restrict__ Ahi, const __nv_bfloat16* __restrict__ Alo,
    const __nv_bfloat16* __restrict__ Bhi, const __nv_bfloat16* __restrict__ Blo,
    float* __restrict__ C, int M, int N, int K)
{
    extern __shared__ char gsm[];

    const int tid  = threadIdx.x;
    const int warp = tid >> 5;
    const int lane = tid & 31;
    const int wr   = warp & 3;
    const int wc   = warp >> 2;
    const int bm   = blockIdx.y * 128;
    const int bn   = blockIdx.x * 128;

    float acc[2][8][4];
#pragma unroll
    for (int i = 0; i < 2; i++)
#pragma unroll
        for (int j = 0; j < 8; j++)
#pragma unroll
            for (int k = 0; k < 4; k++) acc[i][j][k] = 0.0f;

    const int nkc = K / BK;   // 32

    // rows 0..127: Ahi, 128..255: Alo, 256..383: Bhi, 384..511: Blo
    auto load_chunk = [&](int c, int stage) {
        const int kc = c * BK;
        char* st = gsm + stage * GSTAGE_B;
#pragma unroll
        for (int p = 0; p < 8; p++) {
            int v   = tid + p * 256;
            int r   = v >> 2;
            int seg = v & 3;
            int rr  = r & 127;
            const __nv_bfloat16* base;
            size_t grow;
            if (r < 128)      { base = Ahi; grow = (size_t)(bm + rr); }
            else if (r < 256) { base = Alo; grow = (size_t)(bm + rr); }
            else if (r < 384) { base = Bhi; grow = (size_t)(bn + rr); }
            else              { base = Blo; grow = (size_t)(bn + rr); }
            CP_ASYNC16(smem_u32(st + r * ROWB + seg * 16),
                       base + grow * K + kc + seg * 8);
        }
    };

    load_chunk(0, 0); CP_COMMIT();
    load_chunk(1, 1); CP_COMMIT();
    load_chunk(2, 2); CP_COMMIT();

    const int sub  = lane >> 3;
    const int lrow = lane & 7;

    for (int c = 0; c < nkc; ++c) {
        {
            int rem = nkc - 1 - c;
            if (rem >= 2)      { CP_WAIT(2); }
            else if (rem == 1) { CP_WAIT(1); }
            else               { CP_WAIT(0); }
        }
        __syncthreads();
        if (c + 3 < nkc) { load_chunk(c + 3, (c + 3) & 3); CP_COMMIT(); }

        char* st = gsm + (c & 3) * GSTAGE_B;

#pragma unroll
        for (int s = 0; s < 2; ++s) {
            uint32_t afh[2][4], afl[2][4];
#pragma unroll
            for (int mt = 0; mt < 2; ++mt) {
                int row = wr * 32 + mt * 16 + (sub & 1) * 8 + lrow;
                uint32_t ad = smem_u32(st + row * ROWB + s * 32 + (sub >> 1) * 16);
                LDMATRIX_X4(afh[mt][0], afh[mt][1], afh[mt][2], afh[mt][3], ad);
                LDMATRIX_X4(afl[mt][0], afl[mt][1], afl[mt][2], afl[mt][3],
                            ad + 128 * ROWB);
            }
            uint32_t bfh[4][4], bfl[4][4];
#pragma unroll
            for (int nt = 0; nt < 4; ++nt) {
                int row = wc * 64 + nt * 16 + (sub >> 1) * 8 + lrow;
                uint32_t bd = smem_u32(st + (256 + row) * ROWB + s * 32 + (sub & 1) * 16);
                LDMATRIX_X4(bfh[nt][0], bfh[nt][1], bfh[nt][2], bfh[nt][3], bd);
                LDMATRIX_X4(bfl[nt][0], bfl[nt][1], bfl[nt][2], bfl[nt][3],
                            bd + 128 * ROWB);
            }
#pragma unroll
            for (int mt = 0; mt < 2; ++mt)
#pragma unroll
                for (int nt = 0; nt < 8; ++nt) {
                    uint32_t bh0 = bfh[nt >> 1][(nt & 1) * 2];
                    uint32_t bh1 = bfh[nt >> 1][(nt & 1) * 2 + 1];
                    uint32_t bl0 = bfl[nt >> 1][(nt & 1) * 2];
                    uint32_t bl1 = bfl[nt >> 1][(nt & 1) * 2 + 1];
                    MMA_BF16(acc[mt][nt], afh[mt], bh0, bh1);
                    MMA_BF16(acc[mt][nt], afl[mt], bh0, bh1);
                    MMA_BF16(acc[mt][nt], afh[mt], bl0, bl1);
                }
        }
    }

#pragma unroll
    for (int mt = 0; mt < 2; ++mt) {
#pragma unroll
        for (int nt = 0; nt < 8; ++nt) {
            int r0 = bm + wr * 32 + mt * 16 + (lane >> 2);
            int cc = bn + wc * 64 + nt * 8 + (lane & 3) * 2;
            *reinterpret_cast<float2*>(&C[(size_t)r0 * N + cc]) =
                make_float2(acc[mt][nt][0], acc[mt][nt][1]);
            *reinterpret_cast<float2*>(&C[(size_t)(r0 + 8) * N + cc]) =
                make_float2(acc[mt][nt][2], acc[mt][nt][3]);
        }
    }
}

// ---------------------------------------------------------------------------
// HMMA flash attention, causal (unchanged from R4 — passed).
// ---------------------------------------------------------------------------
#define AT_ROWE 72
#define KV_ARRE (64 * AT_ROWE)
#define KV_BUFE (4 * KV_ARRE)
#define ATTN_SMEM (2 * KV_BUFE * 2)

__global__ __launch_bounds__(256, 1) void attn_mma_kernel()
{
    extern __shared__ char at_sm[];
    __nv_bfloat16* smb = reinterpret_cast<__nv_bfloat16*>(at_sm);

    const int tid  = threadIdx.x;
    const int w    = tid >> 5;
    const int lane = tid & 31;
    const int sub  = lane >> 3;
    const int lrow = lane & 7;
    const int qt   = blockIdx.x;
    const int bh   = blockIdx.y;
    const int b    = bh >> 4;
    const int h    = bh & 15;

    const size_t rowbase = (size_t)b * SEQ;
    const int    q0      = qt * 128;

    {
        const __nv_bfloat16* srcs[2];
        srcs[0] = g_qhi; srcs[1] = g_qlo;
#pragma unroll
        for (int arr = 0; arr < 2; ++arr) {
            const __nv_bfloat16* s = srcs[arr] + (rowbase + q0) * D_MODEL + h * 64;
            __nv_bfloat16* d = smb + arr * (128 * AT_ROWE);
#pragma unroll
            for (int p = 0; p < 4; ++p) {
                int v = tid + p * 256;
                int r = v >> 3, seg = v & 7;
                CP_ASYNC16(smem_u32(d + r * AT_ROWE + seg * 8),
                           s + (size_t)r * D_MODEL + seg * 8);
            }
        }
        CP_COMMIT(); CP_WAIT(0);
        __syncthreads();
    }

    uint32_t qh[4][4], ql[4][4];
#pragma unroll
    for (int kt = 0; kt < 4; ++kt) {
        int row = w * 16 + (sub & 1) * 8 + lrow;
        int col = kt * 16 + (sub >> 1) * 8;
        uint32_t a0 = smem_u32(smb + row * AT_ROWE + col);
        LDMATRIX_X4(qh[kt][0], qh[kt][1], qh[kt][2], qh[kt][3], a0);
        uint32_t a1 = smem_u32(smb + 128 * AT_ROWE + row * AT_ROWE + col);
        LDMATRIX_X4(ql[kt][0], ql[kt][1], ql[kt][2], ql[kt][3], a1);
    }
    __syncthreads();

    float O[8][4];
#pragma unroll
    for (int i = 0; i < 8; i++)
#pragma unroll
        for (int j = 0; j < 4; j++) O[i][j] = 0.0f;
    float mrow[2] = { -INFINITY, -INFINITY };
    float lrow2[2] = { 0.0f, 0.0f };

    const int ntiles = 2 * qt + 2;

    auto load_kv = [&](int k0, __nv_bfloat16* buf) {
        const __nv_bfloat16* srcs[4];
        srcs[0] = g_khi; srcs[1] = g_klo; srcs[2] = g_vhi; srcs[3] = g_vlo;
#pragma unroll
        for (int arr = 0; arr < 4; ++arr) {
            const __nv_bfloat16* s = srcs[arr] + (rowbase + k0) * D_MODEL + h * 64;
            __nv_bfloat16* d = buf + arr * KV_ARRE;
#pragma unroll
            for (int p = 0; p < 2; ++p) {
                int v = tid + p * 256;
                int r = v >> 3, seg = v & 7;
                CP_ASYNC16(smem_u32(d + r * AT_ROWE + seg * 8),
                           s + (size_t)r * D_MODEL + seg * 8);
            }
        }
    };

    load_kv(0, smb); CP_COMMIT();

    for (int t = 0; t < ntiles; ++t) {
        __nv_bfloat16* cbuf = smb + (t & 1) * KV_BUFE;
        if (t + 1 < ntiles) {
            load_kv((t + 1) * 64, smb + ((t + 1) & 1) * KV_BUFE);
            CP_COMMIT();
            CP_WAIT(1);
        } else {
            CP_WAIT(0);
        }
        __syncthreads();

        const int k0 = t * 64;
        const bool active = (k0 <= q0 + w * 16 + 15);

        if (active) {
            __nv_bfloat16* sKhi = cbuf;
            __nv_bfloat16* sKlo = cbuf + KV_ARRE;
            __nv_bfloat16* sVhi = cbuf + 2 * KV_ARRE;
            __nv_bfloat16* sVlo = cbuf + 3 * KV_ARRE;

            float sacc[8][4];
#pragma unroll
            for (int i = 0; i < 8; i++)
#pragma unroll
                for (int j = 0; j < 4; j++) sacc[i][j] = 0.0f;

#pragma unroll
            for (int kt = 0; kt < 4; ++kt) {
#pragma unroll
                for (int g = 0; g < 4; ++g) {
                    int row = g * 16 + (sub >> 1) * 8 + lrow;
                    int col = kt * 16 + (sub & 1) * 8;
                    uint32_t kh[4], kl[4];
                    LDMATRIX_X4(kh[0], kh[1], kh[2], kh[3],
                                smem_u32(sKhi + row * AT_ROWE + col));
                    LDMATRIX_X4(kl[0], kl[1], kl[2], kl[3],
                                smem_u32(sKlo + row * AT_ROWE + col));
                    MMA_BF16(sacc[2 * g],     qh[kt], kh[0], kh[1]);
                    MMA_BF16(sacc[2 * g + 1], qh[kt], kh[2], kh[3]);
                    MMA_BF16(sacc[2 * g],     ql[kt], kh[0], kh[1]);
                    MMA_BF16(sacc[2 * g + 1], ql[kt], kh[2], kh[3]);
                    MMA_BF16(sacc[2 * g],     qh[kt], kl[0], kl[1]);
                    MMA_BF16(sacc[2 * g + 1], qh[kt], kl[2], kl[3]);
                }
            }

            const int qrow0 = q0 + w * 16 + (lane >> 2);
            const bool need_mask = (k0 + 63 > q0 + w * 16);
#pragma unroll
            for (int nt = 0; nt < 8; ++nt) {
#pragma unroll
                for (int j = 0; j < 4; j++) sacc[nt][j] *= 0.125f;
                if (need_mask) {
                    int col = k0 + nt * 8 + (lane & 3) * 2;
                    if (col     > qrow0)     sacc[nt][0] = -INFINITY;
                    if (col + 1 > qrow0)     sacc[nt][1] = -INFINITY;
                    if (col     > qrow0 + 8) sacc[nt][2] = -INFINITY;
                    if (col + 1 > qrow0 + 8) sacc[nt][3] = -INFINITY;
                }
            }

            float mx0 = -INFINITY, mx1 = -INFINITY;
#pragma unroll
            for (int nt = 0; nt < 8; ++nt) {
                mx0 = fmaxf(mx0, fmaxf(sacc[nt][0], sacc[nt][1]));
                mx1 = fmaxf(mx1, fmaxf(sacc[nt][2], sacc[nt][3]));
            }
            mx0 = fmaxf(mx0, __shfl_xor_sync(0xffffffff, mx0, 1));
            mx0 = fmaxf(mx0, __shfl_xor_sync(0xffffffff, mx0, 2));
            mx1 = fmaxf(mx1, __shfl_xor_sync(0xffffffff, mx1, 1));
            mx1 = fmaxf(mx1, __shfl_xor_sync(0xffffffff, mx1, 2));

            float mn0 = fmaxf(mrow[0], mx0);
            float mn1 = fmaxf(mrow[1], mx1);
            float a0 = __expf(mrow[0] - mn0);
            float a1 = __expf(mrow[1] - mn1);
            mrow[0] = mn0; mrow[1] = mn1;

            float rs0 = 0.0f, rs1 = 0.0f;
#pragma unroll
            for (int nt = 0; nt < 8; ++nt) {
                sacc[nt][0] = __expf(sacc[nt][0] - mn0);
                sacc[nt][1] = __expf(sacc[nt][1] - mn0);
                sacc[nt][2] = __expf(sacc[nt][2] - mn1);
                sacc[nt][3] = __expf(sacc[nt][3] - mn1);
                rs0 += sacc[nt][0] + sacc[nt][1];
                rs1 += sacc[nt][2] + sacc[nt][3];
            }
            rs0 += __shfl_xor_sync(0xffffffff, rs0, 1);
            rs0 += __shfl_xor_sync(0xffffffff, rs0, 2);
            rs1 += __shfl_xor_sync(0xffffffff, rs1, 1);
            rs1 += __shfl_xor_sync(0xffffffff, rs1, 2);
            lrow2[0] = lrow2[0] * a0 + rs0;
            lrow2[1] = lrow2[1] * a1 + rs1;

#pragma unroll
            for (int dn = 0; dn < 8; ++dn) {
                O[dn][0] *= a0; O[dn][1] *= a0;
                O[dn][2] *= a1; O[dn][3] *= a1;
            }

            uint32_t ph[4][4], pl[4][4];
#pragma unroll
            for (int kt = 0; kt < 4; ++kt) {
                float e[8] = { sacc[2 * kt][0],     sacc[2 * kt][1],
                               sacc[2 * kt][2],     sacc[2 * kt][3],
                               sacc[2 * kt + 1][0], sacc[2 * kt + 1][1],
                               sacc[2 * kt + 1][2], sacc[2 * kt + 1][3] };
                float r[8];
#pragma unroll
                for (int i = 0; i < 8; i++)
                    r[i] = e[i] - __bfloat162float(__float2bfloat16_rn(e[i]));
                ph[kt][0] = packbf(e[0], e[1]);
                ph[kt][1] = packbf(e[2], e[3]);
                ph[kt][2] = packbf(e[4], e[5]);
                ph[kt][3] = packbf(e[6], e[7]);
                pl[kt][0] = packbf(r[0], r[1]);
                pl[kt][1] = packbf(r[2], r[3]);
                pl[kt][2] = packbf(r[4], r[5]);
                pl[kt][3] = packbf(r[6], r[7]);
            }

#pragma unroll
            for (int kt = 0; kt < 4; ++kt) {
#pragma unroll
                for (int dg = 0; dg < 4; ++dg) {
                    int row = kt * 16 + (sub & 1) * 8 + lrow;
                    int col = dg * 16 + (sub >> 1) * 8;
                    uint32_t vh[4], vl[4];
                    LDMATRIX_X4_T(vh[0], vh[1], vh[2], vh[3],
                                  smem_u32(sVhi + row * AT_ROWE + col));
                    LDMATRIX_X4_T(vl[0], vl[1], vl[2], vl[3],
                                  smem_u32(sVlo + row * AT_ROWE + col));
                    MMA_BF16(O[2 * dg],     ph[kt], vh[0], vh[1]);
                    MMA_BF16(O[2 * dg + 1], ph[kt], vh[2], vh[3]);
                    MMA_BF16(O[2 * dg],     pl[kt], vh[0], vh[1]);
                    MMA_BF16(O[2 * dg + 1], pl[kt], vh[2], vh[3]);
                    MMA_BF16(O[2 * dg],     ph[kt], vl[0], vl[1]);
                    MMA_BF16(O[2 * dg + 1], ph[kt], vl[2], vl[3]);
                }
            }
        }
        __syncthreads();
    }

    const float inv0 = 1.0f / lrow2[0];
    const float inv1 = 1.0f / lrow2[1];
    const size_t r0 = rowbase + q0 + w * 16 + (lane >> 2);
#pragma unroll
    for (int dn = 0; dn < 8; ++dn) {
        int col = h * 64 + dn * 8 + (lane & 3) * 2;
        *reinterpret_cast<float2*>(&g_AO[r0 * D_MODEL + col]) =
            make_float2(O[dn][0] * inv0, O[dn][1] * inv0);
        *reinterpret_cast<float2*>(&g_AO[(r0 + 8) * D_MODEL + col]) =
            make_float2(O[dn][2] * inv1, O[dn][3] * inv1);
    }
}

// ---------------------------------------------------------------------------
// Launch
// ---------------------------------------------------------------------------
extern "C" void kernel_launch(void* const* d_in, const int* in_sizes, int n_in,
                              void* d_out, int out_size)
{
    const float* x   = (const float*)d_in[0];
    const int*   pos = (const int*)  d_in[1];
    const float* Wq  = (const float*)d_in[2];
    const float* Wk  = (const float*)d_in[3];
    const float* Wv  = (const float*)d_in[4];
    const float* Wo  = (const float*)d_in[5];
    float*       out = (float*)d_out;

    float *Qp, *Kp, *Vp, *AOp;
    cudaGetSymbolAddress((void**)&Qp,  g_Q);
    cudaGetSymbolAddress((void**)&Kp,  g_K);
    cudaGetSymbolAddress((void**)&Vp,  g_V);
    cudaGetSymbolAddress((void**)&AOp, g_AO);

    __nv_bfloat16 *xhi, *xlo, *aohi, *aolo;
    __nv_bfloat16 *qhi, *qlo, *khi, *klo, *vhi, *vlo;
    __nv_bfloat16 *wqhi, *wqlo, *wkhi, *wklo, *wvhi, *wvlo, *wohi, *wolo;
    cudaGetSymbolAddress((void**)&xhi,  g_xhi);
    cudaGetSymbolAddress((void**)&xlo,  g_xlo);
    cudaGetSymbolAddress((void**)&aohi, g_aohi);
    cudaGetSymbolAddress((void**)&aolo, g_aolo);
    cudaGetSymbolAddress((void**)&qhi,  g_qhi);
    cudaGetSymbolAddress((void**)&qlo,  g_qlo);
    cudaGetSymbolAddress((void**)&khi,  g_khi);
    cudaGetSymbolAddress((void**)&klo,  g_klo);
    cudaGetSymbolAddress((void**)&vhi,  g_vhi);
    cudaGetSymbolAddress((void**)&vlo,  g_vlo);
    cudaGetSymbolAddress((void**)&wqhi, g_wqhi);
    cudaGetSymbolAddress((void**)&wqlo, g_wqlo);
    cudaGetSymbolAddress((void**)&wkhi, g_wkhi);
    cudaGetSymbolAddress((void**)&wklo, g_wklo);
    cudaGetSymbolAddress((void**)&wvhi, g_wvhi);
    cudaGetSymbolAddress((void**)&wvlo, g_wvlo);
    cudaGetSymbolAddress((void**)&wohi, g_wohi);
    cudaGetSymbolAddress((void**)&wolo, g_wolo);

    cudaFuncSetAttribute(gemm_mma_kernel,
                         cudaFuncAttributeMaxDynamicSharedMemorySize, GEMM_SMEM);
    cudaFuncSetAttribute(attn_mma_kernel,
                         cudaFuncAttributeMaxDynamicSharedMemorySize, ATTN_SMEM);

    const int nx = M_ROWS * D_MODEL / 4;
    const int nw = D_MODEL * D_MODEL / 4;

    split_bf16_kernel<<<(nx + 255) / 256, 256>>>(x,  xhi,  xlo,  nx);
    split_bf16_kernel<<<(nw + 255) / 256, 256>>>(Wq, wqhi, wqlo, nw);
    split_bf16_kernel<<<(nw + 255) / 256, 256>>>(Wk, wkhi, wklo, nw);
    split_bf16_kernel<<<(nw + 255) / 256, 256>>>(Wv, wvhi, wvlo, nw);
    split_bf16_kernel<<<(nw + 255) / 256, 256>>>(Wo, wohi, wolo, nw);

    dim3 ggrid(D_MODEL / 128, M_ROWS / 128);

    gemm_mma_kernel<<<ggrid, 256, GEMM_SMEM>>>(xhi, xlo, wqhi, wqlo, Qp,
                                               M_ROWS, D_MODEL, D_MODEL);
    gemm_mma_kernel<<<ggrid, 256, GEMM_SMEM>>>(xhi, xlo, wkhi, wklo, Kp,
                                               M_ROWS, D_MODEL, D_MODEL);
    gemm_mma_kernel<<<ggrid, 256, GEMM_SMEM>>>(xhi, xlo, wvhi, wvlo, Vp,
                                               M_ROWS, D_MODEL, D_MODEL);

    const int rp_total = M_ROWS * (D_MODEL / 2);
    rope_split_kernel<<<(rp_total + 255) / 256, 256>>>(pos, Qp, qhi, qlo);
    rope_split_kernel<<<(rp_total + 255) / 256, 256>>>(pos, Kp, khi, klo);
    split_bf16_kernel<<<(nx + 255) / 256, 256>>>(Vp, vhi, vlo, nx);

    attn_mma_kernel<<<dim3(SEQ / 128, BATCH * NUM_HEADS), 256, ATTN_SMEM>>>();

    split_bf16_kernel<<<(nx + 255) / 256, 256>>>(AOp, aohi, aolo, nx);
    gemm_mma_kernel<<<ggrid, 256, GEMM_SMEM>>>(aohi, aolo, wohi, wolo, out,
                                               M_ROWS, D_MODEL, D_MODEL);
}

// round 8
// speedup vs baseline: 2.9131x; 1.1234x over previous
#include <cuda_runtime.h>
#include <cuda_bf16.h>
#include <math.h>
#include <stdint.h>

#define D_MODEL   1024
#define NUM_HEADS 16
#define HEAD_DIM  64
#define BATCH     4
#define SEQ       2048
#define M_ROWS    (BATCH * SEQ)   // 8192

// ---------------------------------------------------------------------------
// Scratch (allocation-free rule: __device__ globals)
// ---------------------------------------------------------------------------
__device__ float g_Q [M_ROWS * D_MODEL];   // fp32 Q before rope
__device__ float g_K [M_ROWS * D_MODEL];   // fp32 K before rope

__device__ __nv_bfloat16 g_xhi [M_ROWS * D_MODEL];
__device__ __nv_bfloat16 g_xlo [M_ROWS * D_MODEL];
__device__ __nv_bfloat16 g_aohi[M_ROWS * D_MODEL];
__device__ __nv_bfloat16 g_aolo[M_ROWS * D_MODEL];
__device__ __nv_bfloat16 g_qhi [M_ROWS * D_MODEL];
__device__ __nv_bfloat16 g_qlo [M_ROWS * D_MODEL];
__device__ __nv_bfloat16 g_khi [M_ROWS * D_MODEL];
__device__ __nv_bfloat16 g_klo [M_ROWS * D_MODEL];
__device__ __nv_bfloat16 g_vhi [M_ROWS * D_MODEL];
__device__ __nv_bfloat16 g_vlo [M_ROWS * D_MODEL];
__device__ __nv_bfloat16 g_whi [3 * D_MODEL * D_MODEL];  // packed Wq|Wk|Wv
__device__ __nv_bfloat16 g_wlo [3 * D_MODEL * D_MODEL];
__device__ __nv_bfloat16 g_wohi[D_MODEL * D_MODEL];
__device__ __nv_bfloat16 g_wolo[D_MODEL * D_MODEL];

// ---------------------------------------------------------------------------
// Helpers
// ---------------------------------------------------------------------------
__device__ __forceinline__ uint32_t smem_u32(const void* p) {
    uint32_t a;
    asm("{ .reg .u64 t; cvta.to.shared.u64 t, %1; cvt.u32.u64 %0, t; }"
        : "=r"(a) : "l"(p));
    return a;
}

#define CP_ASYNC16(dst, src) \
    asm volatile("cp.async.cg.shared.global [%0], [%1], 16;" \
                 :: "r"(dst), "l"(src) : "memory")
#define CP_COMMIT() asm volatile("cp.async.commit_group;" ::: "memory")
#define CP_WAIT(n)  asm volatile("cp.async.wait_group %0;" :: "n"(n) : "memory")

#define LDMATRIX_X4(r0, r1, r2, r3, addr) \
    asm volatile("ldmatrix.sync.aligned.m8n8.x4.shared.b16 {%0,%1,%2,%3}, [%4];" \
                 : "=r"(r0), "=r"(r1), "=r"(r2), "=r"(r3) : "r"(addr))

#define LDMATRIX_X4_T(r0, r1, r2, r3, addr) \
    asm volatile("ldmatrix.sync.aligned.m8n8.x4.trans.shared.b16 {%0,%1,%2,%3}, [%4];" \
                 : "=r"(r0), "=r"(r1), "=r"(r2), "=r"(r3) : "r"(addr))

#define MMA_BF16(d, a, b0, b1) \
    asm volatile("mma.sync.aligned.m16n8k16.row.col.f32.bf16.bf16.f32 " \
                 "{%0,%1,%2,%3}, {%4,%5,%6,%7}, {%8,%9}, {%0,%1,%2,%3};" \
                 : "+f"((d)[0]), "+f"((d)[1]), "+f"((d)[2]), "+f"((d)[3]) \
                 : "r"((a)[0]), "r"((a)[1]), "r"((a)[2]), "r"((a)[3]), \
                   "r"(b0), "r"(b1))

__device__ __forceinline__ uint32_t packbf(float lo, float hi) {
    __nv_bfloat162 t = __floats2bfloat162_rn(lo, hi);
    return *reinterpret_cast<uint32_t*>(&t);
}

__device__ __forceinline__ uint32_t split_pair(float y0, float y1, uint32_t& lo_out) {
    __nv_bfloat16 h0 = __float2bfloat16(y0);
    __nv_bfloat16 h1 = __float2bfloat16(y1);
    float r0 = y0 - __bfloat162float(h0);
    float r1 = y1 - __bfloat162float(h1);
    __nv_bfloat162 lp = make_bfloat162(__float2bfloat16(r0), __float2bfloat16(r1));
    lo_out = *reinterpret_cast<uint32_t*>(&lp);
    __nv_bfloat162 hp = make_bfloat162(h0, h1);
    return *reinterpret_cast<uint32_t*>(&hp);
}

// ---------------------------------------------------------------------------
// fp32 -> bf16 hi/lo split
// ---------------------------------------------------------------------------
__global__ void split_bf16_kernel(const float* __restrict__ src,
                                  __nv_bfloat16* __restrict__ hi,
                                  __nv_bfloat16* __restrict__ lo, int n4)
{
    int i = blockIdx.x * blockDim.x + threadIdx.x;
    if (i >= n4) return;
    float4 v = reinterpret_cast<const float4*>(src)[i];
    float vv[4] = {v.x, v.y, v.z, v.w};
    __align__(8) __nv_bfloat16 h[4];
    __align__(8) __nv_bfloat16 l[4];
#pragma unroll
    for (int j = 0; j < 4; j++) {
        h[j] = __float2bfloat16(vv[j]);
        float r = vv[j] - __bfloat162float(h[j]);
        l[j] = __float2bfloat16(r);
    }
    reinterpret_cast<uint2*>(hi)[i] = *reinterpret_cast<uint2*>(h);
    reinterpret_cast<uint2*>(lo)[i] = *reinterpret_cast<uint2*>(l);
}

// ---------------------------------------------------------------------------
// Fused RoPE (Q and K together) + bf16 hi/lo split
// ---------------------------------------------------------------------------
__global__ void rope2_split_kernel(const int* __restrict__ pos)
{
    int idx = blockIdx.x * blockDim.x + threadIdx.x;
    const int total = M_ROWS * (D_MODEL / 2);
    if (idx >= total) return;

    int row = idx >> 9;
    int p2  = idx & 511;
    int h   = p2 >> 5;
    int j   = p2 & 31;
    int s   = row & (SEQ - 1);

    float inv = powf(10000.0f, -(float)(2 * j) / 64.0f);
    float ang = (float)pos[s] * inv;
    float sn, cs;
    sincosf(ang, &sn, &cs);

    int base = row * D_MODEL + h * HEAD_DIM + 2 * j;

    {
        float2 v = *reinterpret_cast<const float2*>(g_Q + base);
        float y0 = v.x * cs - v.y * sn;
        float y1 = v.x * sn + v.y * cs;
        uint32_t lo, hi = split_pair(y0, y1, lo);
        *reinterpret_cast<uint32_t*>(g_qhi + base) = hi;
        *reinterpret_cast<uint32_t*>(g_qlo + base) = lo;
    }
    {
        float2 v = *reinterpret_cast<const float2*>(g_K + base);
        float y0 = v.x * cs - v.y * sn;
        float y1 = v.x * sn + v.y * cs;
        uint32_t lo, hi = split_pair(y0, y1, lo);
        *reinterpret_cast<uint32_t*>(g_khi + base) = hi;
        *reinterpret_cast<uint32_t*>(g_klo + base) = lo;
    }
}

// ---------------------------------------------------------------------------
// bf16-split HMMA GEMM, combined hi/lo chunk loads, 2-stage, 2 CTAs/SM.
// C[M,N] = A[M,K] * B[N,K]^T via Ahi*Bhi + Alo*Bhi + Ahi*Blo.
// Epilogue routing (per 128-col tile, uniform per CTA):
//   gc <  1024 : fp32 -> Cq   (Q, or final output)
//   gc <  2048 : fp32 -> Ck   (K)
//   gc >= 2048 : bf16 hi/lo -> Vhi/Vlo  (V, split fused)
// ---------------------------------------------------------------------------
#define BK        32
#define ROWB      80
#define GSTAGE_B  (512 * ROWB)      // 40960
#define GEMM_SMEM (2 * GSTAGE_B)    // 81920

__global__ __launch_bounds__(256, 2) void gemm_mma_kernel(
    const __nv_bfloat16* __restrict__ Ahi, const __nv_bfloat16* __restrict__ Alo,
    const __nv_bfloat16* __restrict__ Bhi, const __nv_bfloat16* __restrict__ Blo,
    float* __restrict__ Cq, float* __restrict__ Ck,
    __nv_bfloat16* __restrict__ Vhi, __nv_bfloat16* __restrict__ Vlo,
    int K)
{
    extern __shared__ char gsm[];

    const int tid  = threadIdx.x;
    const int warp = tid >> 5;
    const int lane = tid & 31;
    const int wr   = warp & 3;
    const int wc   = warp >> 2;
    const int bm   = blockIdx.y * 128;
    const int bn   = blockIdx.x * 128;

    float acc[2][8][4];
#pragma unroll
    for (int i = 0; i < 2; i++)
#pragma unroll
        for (int j = 0; j < 8; j++)
#pragma unroll
            for (int k = 0; k < 4; k++) acc[i][j][k] = 0.0f;

    const int nkc = K / BK;   // 32

    // stage rows: 0..127 Ahi, 128..255 Alo, 256..383 Bhi, 384..511 Blo
    auto load_chunk = [&](int c, int stage) {
        const int kc = c * BK;
        char* st = gsm + stage * GSTAGE_B;
#pragma unroll
        for (int p = 0; p < 8; p++) {
            int v   = tid + p * 256;
            int r   = v >> 2;
            int seg = v & 3;
            int rr  = r & 127;
            const __nv_bfloat16* base;
            size_t grow;
            if (r < 128)      { base = Ahi; grow = (size_t)(bm + rr); }
            else if (r < 256) { base = Alo; grow = (size_t)(bm + rr); }
            else if (r < 384) { base = Bhi; grow = (size_t)(bn + rr); }
            else              { base = Blo; grow = (size_t)(bn + rr); }
            CP_ASYNC16(smem_u32(st + r * ROWB + seg * 16),
                       base + grow * K + kc + seg * 8);
        }
    };

    load_chunk(0, 0); CP_COMMIT();

    const int sub  = lane >> 3;
    const int lrow = lane & 7;

    for (int c = 0; c < nkc; ++c) {
        if (c + 1 < nkc) {
            load_chunk(c + 1, (c + 1) & 1);
            CP_COMMIT();
            CP_WAIT(1);
        } else {
            CP_WAIT(0);
        }
        __syncthreads();

        char* st = gsm + (c & 1) * GSTAGE_B;

#pragma unroll
        for (int s = 0; s < 2; ++s) {
            uint32_t afh[2][4], afl[2][4];
#pragma unroll
            for (int mt = 0; mt < 2; ++mt) {
                int row = wr * 32 + mt * 16 + (sub & 1) * 8 + lrow;
                uint32_t ad = smem_u32(st + row * ROWB + s * 32 + (sub >> 1) * 16);
                LDMATRIX_X4(afh[mt][0], afh[mt][1], afh[mt][2], afh[mt][3], ad);
                LDMATRIX_X4(afl[mt][0], afl[mt][1], afl[mt][2], afl[mt][3],
                            ad + 128 * ROWB);
            }
#pragma unroll
            for (int nt = 0; nt < 4; ++nt) {
                int row = wc * 64 + nt * 16 + (sub >> 1) * 8 + lrow;
                uint32_t bd = smem_u32(st + (256 + row) * ROWB + s * 32 + (sub & 1) * 16);
                uint32_t bh[4], bl[4];
                LDMATRIX_X4(bh[0], bh[1], bh[2], bh[3], bd);
                LDMATRIX_X4(bl[0], bl[1], bl[2], bl[3], bd + 128 * ROWB);
#pragma unroll
                for (int mt = 0; mt < 2; ++mt) {
                    MMA_BF16(acc[mt][2 * nt],     afh[mt], bh[0], bh[1]);
                    MMA_BF16(acc[mt][2 * nt + 1], afh[mt], bh[2], bh[3]);
                    MMA_BF16(acc[mt][2 * nt],     afl[mt], bh[0], bh[1]);
                    MMA_BF16(acc[mt][2 * nt + 1], afl[mt], bh[2], bh[3]);
                    MMA_BF16(acc[mt][2 * nt],     afh[mt], bl[0], bl[1]);
                    MMA_BF16(acc[mt][2 * nt + 1], afh[mt], bl[2], bl[3]);
                }
            }
        }
        __syncthreads();
    }

    // ---- routed epilogue (branch uniform per CTA) ----
    if (bn < 1024) {
#pragma unroll
        for (int mt = 0; mt < 2; ++mt)
#pragma unroll
            for (int nt = 0; nt < 8; ++nt) {
                int r0 = bm + wr * 32 + mt * 16 + (lane >> 2);
                int cc = bn + wc * 64 + nt * 8 + (lane & 3) * 2;
                *reinterpret_cast<float2*>(&Cq[(size_t)r0 * 1024 + cc]) =
                    make_float2(acc[mt][nt][0], acc[mt][nt][1]);
                *reinterpret_cast<float2*>(&Cq[(size_t)(r0 + 8) * 1024 + cc]) =
                    make_float2(acc[mt][nt][2], acc[mt][nt][3]);
            }
    } else if (bn < 2048) {
#pragma unroll
        for (int mt = 0; mt < 2; ++mt)
#pragma unroll
            for (int nt = 0; nt < 8; ++nt) {
                int r0 = bm + wr * 32 + mt * 16 + (lane >> 2);
                int cc = bn - 1024 + wc * 64 + nt * 8 + (lane & 3) * 2;
                *reinterpret_cast<float2*>(&Ck[(size_t)r0 * 1024 + cc]) =
                    make_float2(acc[mt][nt][0], acc[mt][nt][1]);
                *reinterpret_cast<float2*>(&Ck[(size_t)(r0 + 8) * 1024 + cc]) =
                    make_float2(acc[mt][nt][2], acc[mt][nt][3]);
            }
    } else {
#pragma unroll
        for (int mt = 0; mt < 2; ++mt)
#pragma unroll
            for (int nt = 0; nt < 8; ++nt) {
                int r0 = bm + wr * 32 + mt * 16 + (lane >> 2);
                int cc = bn - 2048 + wc * 64 + nt * 8 + (lane & 3) * 2;
                uint32_t lo0, hi0 = split_pair(acc[mt][nt][0], acc[mt][nt][1], lo0);
                uint32_t lo1, hi1 = split_pair(acc[mt][nt][2], acc[mt][nt][3], lo1);
                *reinterpret_cast<uint32_t*>(&Vhi[(size_t)r0 * 1024 + cc]) = hi0;
                *reinterpret_cast<uint32_t*>(&Vlo[(size_t)r0 * 1024 + cc]) = lo0;
                *reinterpret_cast<uint32_t*>(&Vhi[(size_t)(r0 + 8) * 1024 + cc]) = hi1;
                *reinterpret_cast<uint32_t*>(&Vlo[(size_t)(r0 + 8) * 1024 + cc]) = lo1;
            }
    }
}

// ---------------------------------------------------------------------------
// HMMA flash attention, causal. Epilogue writes AO directly as bf16 hi/lo.
// ---------------------------------------------------------------------------
#define AT_ROWE 72
#define KV_ARRE (64 * AT_ROWE)
#define KV_BUFE (4 * KV_ARRE)
#define ATTN_SMEM (2 * KV_BUFE * 2)

__global__ __launch_bounds__(256, 1) void attn_mma_kernel()
{
    extern __shared__ char at_sm[];
    __nv_bfloat16* smb = reinterpret_cast<__nv_bfloat16*>(at_sm);

    const int tid  = threadIdx.x;
    const int w    = tid >> 5;
    const int lane = tid & 31;
    const int sub  = lane >> 3;
    const int lrow = lane & 7;
    const int qt   = blockIdx.x;
    const int bh   = blockIdx.y;
    const int b    = bh >> 4;
    const int h    = bh & 15;

    const size_t rowbase = (size_t)b * SEQ;
    const int    q0      = qt * 128;

    {
        const __nv_bfloat16* srcs[2];
        srcs[0] = g_qhi; srcs[1] = g_qlo;
#pragma unroll
        for (int arr = 0; arr < 2; ++arr) {
            const __nv_bfloat16* s = srcs[arr] + (rowbase + q0) * D_MODEL + h * 64;
            __nv_bfloat16* d = smb + arr * (128 * AT_ROWE);
#pragma unroll
            for (int p = 0; p < 4; ++p) {
                int v = tid + p * 256;
                int r = v >> 3, seg = v & 7;
                CP_ASYNC16(smem_u32(d + r * AT_ROWE + seg * 8),
                           s + (size_t)r * D_MODEL + seg * 8);
            }
        }
        CP_COMMIT(); CP_WAIT(0);
        __syncthreads();
    }

    uint32_t qh[4][4], ql[4][4];
#pragma unroll
    for (int kt = 0; kt < 4; ++kt) {
        int row = w * 16 + (sub & 1) * 8 + lrow;
        int col = kt * 16 + (sub >> 1) * 8;
        uint32_t a0 = smem_u32(smb + row * AT_ROWE + col);
        LDMATRIX_X4(qh[kt][0], qh[kt][1], qh[kt][2], qh[kt][3], a0);
        uint32_t a1 = smem_u32(smb + 128 * AT_ROWE + row * AT_ROWE + col);
        LDMATRIX_X4(ql[kt][0], ql[kt][1], ql[kt][2], ql[kt][3], a1);
    }
    __syncthreads();

    float O[8][4];
#pragma unroll
    for (int i = 0; i < 8; i++)
#pragma unroll
        for (int j = 0; j < 4; j++) O[i][j] = 0.0f;
    float mrow[2] = { -INFINITY, -INFINITY };
    float lrow2[2] = { 0.0f, 0.0f };

    const int ntiles = 2 * qt + 2;

    auto load_kv = [&](int k0, __nv_bfloat16* buf) {
        const __nv_bfloat16* srcs[4];
        srcs[0] = g_khi; srcs[1] = g_klo; srcs[2] = g_vhi; srcs[3] = g_vlo;
#pragma unroll
        for (int arr = 0; arr < 4; ++arr) {
            const __nv_bfloat16* s = srcs[arr] + (rowbase + k0) * D_MODEL + h * 64;
            __nv_bfloat16* d = buf + arr * KV_ARRE;
#pragma unroll
            for (int p = 0; p < 2; ++p) {
                int v = tid + p * 256;
                int r = v >> 3, seg = v & 7;
                CP_ASYNC16(smem_u32(d + r * AT_ROWE + seg * 8),
                           s + (size_t)r * D_MODEL + seg * 8);
            }
        }
    };

    load_kv(0, smb); CP_COMMIT();

    for (int t = 0; t < ntiles; ++t) {
        __nv_bfloat16* cbuf = smb + (t & 1) * KV_BUFE;
        if (t + 1 < ntiles) {
            load_kv((t + 1) * 64, smb + ((t + 1) & 1) * KV_BUFE);
            CP_COMMIT();
            CP_WAIT(1);
        } else {
            CP_WAIT(0);
        }
        __syncthreads();

        const int k0 = t * 64;
        const bool active = (k0 <= q0 + w * 16 + 15);

        if (active) {
            __nv_bfloat16* sKhi = cbuf;
            __nv_bfloat16* sKlo = cbuf + KV_ARRE;
            __nv_bfloat16* sVhi = cbuf + 2 * KV_ARRE;
            __nv_bfloat16* sVlo = cbuf + 3 * KV_ARRE;

            float sacc[8][4];
#pragma unroll
            for (int i = 0; i < 8; i++)
#pragma unroll
                for (int j = 0; j < 4; j++) sacc[i][j] = 0.0f;

#pragma unroll
            for (int kt = 0; kt < 4; ++kt) {
#pragma unroll
                for (int g = 0; g < 4; ++g) {
                    int row = g * 16 + (sub >> 1) * 8 + lrow;
                    int col = kt * 16 + (sub & 1) * 8;
                    uint32_t kh[4], kl[4];
                    LDMATRIX_X4(kh[0], kh[1], kh[2], kh[3],
                                smem_u32(sKhi + row * AT_ROWE + col));
                    LDMATRIX_X4(kl[0], kl[1], kl[2], kl[3],
                                smem_u32(sKlo + row * AT_ROWE + col));
                    MMA_BF16(sacc[2 * g],     qh[kt], kh[0], kh[1]);
                    MMA_BF16(sacc[2 * g + 1], qh[kt], kh[2], kh[3]);
                    MMA_BF16(sacc[2 * g],     ql[kt], kh[0], kh[1]);
                    MMA_BF16(sacc[2 * g + 1], ql[kt], kh[2], kh[3]);
                    MMA_BF16(sacc[2 * g],     qh[kt], kl[0], kl[1]);
                    MMA_BF16(sacc[2 * g + 1], qh[kt], kl[2], kl[3]);
                }
            }

            const int qrow0 = q0 + w * 16 + (lane >> 2);
            const bool need_mask = (k0 + 63 > q0 + w * 16);
#pragma unroll
            for (int nt = 0; nt < 8; ++nt) {
#pragma unroll
                for (int j = 0; j < 4; j++) sacc[nt][j] *= 0.125f;
                if (need_mask) {
                    int col = k0 + nt * 8 + (lane & 3) * 2;
                    if (col     > qrow0)     sacc[nt][0] = -INFINITY;
                    if (col + 1 > qrow0)     sacc[nt][1] = -INFINITY;
                    if (col     > qrow0 + 8) sacc[nt][2] = -INFINITY;
                    if (col + 1 > qrow0 + 8) sacc[nt][3] = -INFINITY;
                }
            }

            float mx0 = -INFINITY, mx1 = -INFINITY;
#pragma unroll
            for (int nt = 0; nt < 8; ++nt) {
                mx0 = fmaxf(mx0, fmaxf(sacc[nt][0], sacc[nt][1]));
                mx1 = fmaxf(mx1, fmaxf(sacc[nt][2], sacc[nt][3]));
            }
            mx0 = fmaxf(mx0, __shfl_xor_sync(0xffffffff, mx0, 1));
            mx0 = fmaxf(mx0, __shfl_xor_sync(0xffffffff, mx0, 2));
            mx1 = fmaxf(mx1, __shfl_xor_sync(0xffffffff, mx1, 1));
            mx1 = fmaxf(mx1, __shfl_xor_sync(0xffffffff, mx1, 2));

            float mn0 = fmaxf(mrow[0], mx0);
            float mn1 = fmaxf(mrow[1], mx1);
            float a0 = __expf(mrow[0] - mn0);
            float a1 = __expf(mrow[1] - mn1);
            mrow[0] = mn0; mrow[1] = mn1;

            float rs0 = 0.0f, rs1 = 0.0f;
#pragma unroll
            for (int nt = 0; nt < 8; ++nt) {
                sacc[nt][0] = __expf(sacc[nt][0] - mn0);
                sacc[nt][1] = __expf(sacc[nt][1] - mn0);
                sacc[nt][2] = __expf(sacc[nt][2] - mn1);
                sacc[nt][3] = __expf(sacc[nt][3] - mn1);
                rs0 += sacc[nt][0] + sacc[nt][1];
                rs1 += sacc[nt][2] + sacc[nt][3];
            }
            rs0 += __shfl_xor_sync(0xffffffff, rs0, 1);
            rs0 += __shfl_xor_sync(0xffffffff, rs0, 2);
            rs1 += __shfl_xor_sync(0xffffffff, rs1, 1);
            rs1 += __shfl_xor_sync(0xffffffff, rs1, 2);
            lrow2[0] = lrow2[0] * a0 + rs0;
            lrow2[1] = lrow2[1] * a1 + rs1;

#pragma unroll
            for (int dn = 0; dn < 8; ++dn) {
                O[dn][0] *= a0; O[dn][1] *= a0;
                O[dn][2] *= a1; O[dn][3] *= a1;
            }

            uint32_t ph[4][4], pl[4][4];
#pragma unroll
            for (int kt = 0; kt < 4; ++kt) {
                float e[8] = { sacc[2 * kt][0],     sacc[2 * kt][1],
                               sacc[2 * kt][2],     sacc[2 * kt][3],
                               sacc[2 * kt + 1][0], sacc[2 * kt + 1][1],
                               sacc[2 * kt + 1][2], sacc[2 * kt + 1][3] };
                float r[8];
#pragma unroll
                for (int i = 0; i < 8; i++)
                    r[i] = e[i] - __bfloat162float(__float2bfloat16_rn(e[i]));
                ph[kt][0] = packbf(e[0], e[1]);
                ph[kt][1] = packbf(e[2], e[3]);
                ph[kt][2] = packbf(e[4], e[5]);
                ph[kt][3] = packbf(e[6], e[7]);
                pl[kt][0] = packbf(r[0], r[1]);
                pl[kt][1] = packbf(r[2], r[3]);
                pl[kt][2] = packbf(r[4], r[5]);
                pl[kt][3] = packbf(r[6], r[7]);
            }

#pragma unroll
            for (int kt = 0; kt < 4; ++kt) {
#pragma unroll
                for (int dg = 0; dg < 4; ++dg) {
                    int row = kt * 16 + (sub & 1) * 8 + lrow;
                    int col = dg * 16 + (sub >> 1) * 8;
                    uint32_t vh[4], vl[4];
                    LDMATRIX_X4_T(vh[0], vh[1], vh[2], vh[3],
                                  smem_u32(sVhi + row * AT_ROWE + col));
                    LDMATRIX_X4_T(vl[0], vl[1], vl[2], vl[3],
                                  smem_u32(sVlo + row * AT_ROWE + col));
                    MMA_BF16(O[2 * dg],     ph[kt], vh[0], vh[1]);
                    MMA_BF16(O[2 * dg + 1], ph[kt], vh[2], vh[3]);
                    MMA_BF16(O[2 * dg],     pl[kt], vh[0], vh[1]);
                    MMA_BF16(O[2 * dg + 1], pl[kt], vh[2], vh[3]);
                    MMA_BF16(O[2 * dg],     ph[kt], vl[0], vl[1]);
                    MMA_BF16(O[2 * dg + 1], ph[kt], vl[2], vl[3]);
                }
            }
        }
        __syncthreads();
    }

    // ---- normalize + write AO directly as bf16 hi/lo ----
    const float inv0 = 1.0f / lrow2[0];
    const float inv1 = 1.0f / lrow2[1];
    const size_t r0 = rowbase + q0 + w * 16 + (lane >> 2);
#pragma unroll
    for (int dn = 0; dn < 8; ++dn) {
        int col = h * 64 + dn * 8 + (lane & 3) * 2;
        uint32_t lo0, hi0 = split_pair(O[dn][0] * inv0, O[dn][1] * inv0, lo0);
        uint32_t lo1, hi1 = split_pair(O[dn][2] * inv1, O[dn][3] * inv1, lo1);
        *reinterpret_cast<uint32_t*>(&g_aohi[r0 * D_MODEL + col]) = hi0;
        *reinterpret_cast<uint32_t*>(&g_aolo[r0 * D_MODEL + col]) = lo0;
        *reinterpret_cast<uint32_t*>(&g_aohi[(r0 + 8) * D_MODEL + col]) = hi1;
        *reinterpret_cast<uint32_t*>(&g_aolo[(r0 + 8) * D_MODEL + col]) = lo1;
    }
}

// ---------------------------------------------------------------------------
// Launch
// ---------------------------------------------------------------------------
extern "C" void kernel_launch(void* const* d_in, const int* in_sizes, int n_in,
                              void* d_out, int out_size)
{
    const float* x   = (const float*)d_in[0];
    const int*   pos = (const int*)  d_in[1];
    const float* Wq  = (const float*)d_in[2];
    const float* Wk  = (const float*)d_in[3];
    const float* Wv  = (const float*)d_in[4];
    const float* Wo  = (const float*)d_in[5];
    float*       out = (float*)d_out;

    float *Qp, *Kp;
    cudaGetSymbolAddress((void**)&Qp, g_Q);
    cudaGetSymbolAddress((void**)&Kp, g_K);

    __nv_bfloat16 *xhi, *xlo, *aohi, *aolo, *vhi, *vlo;
    __nv_bfloat16 *whi, *wlo, *wohi, *wolo;
    cudaGetSymbolAddress((void**)&xhi,  g_xhi);
    cudaGetSymbolAddress((void**)&xlo,  g_xlo);
    cudaGetSymbolAddress((void**)&aohi, g_aohi);
    cudaGetSymbolAddress((void**)&aolo, g_aolo);
    cudaGetSymbolAddress((void**)&vhi,  g_vhi);
    cudaGetSymbolAddress((void**)&vlo,  g_vlo);
    cudaGetSymbolAddress((void**)&whi,  g_whi);
    cudaGetSymbolAddress((void**)&wlo,  g_wlo);
    cudaGetSymbolAddress((void**)&wohi, g_wohi);
    cudaGetSymbolAddress((void**)&wolo, g_wolo);

    cudaFuncSetAttribute(gemm_mma_kernel,
                         cudaFuncAttributeMaxDynamicSharedMemorySize, GEMM_SMEM);
    cudaFuncSetAttribute(attn_mma_kernel,
                         cudaFuncAttributeMaxDynamicSharedMemorySize, ATTN_SMEM);

    const int nx = M_ROWS * D_MODEL / 4;
    const int nw = D_MODEL * D_MODEL / 4;
    const int WSZ = D_MODEL * D_MODEL;

    split_bf16_kernel<<<(nx + 255) / 256, 256>>>(x,  xhi, xlo, nx);
    split_bf16_kernel<<<(nw + 255) / 256, 256>>>(Wq, whi,           wlo,           nw);
    split_bf16_kernel<<<(nw + 255) / 256, 256>>>(Wk, whi + WSZ,     wlo + WSZ,     nw);
    split_bf16_kernel<<<(nw + 255) / 256, 256>>>(Wv, whi + 2 * WSZ, wlo + 2 * WSZ, nw);
    split_bf16_kernel<<<(nw + 255) / 256, 256>>>(Wo, wohi, wolo, nw);

    // Fused QKV projection: B has 3072 rows; V epilogue writes bf16 split.
    gemm_mma_kernel<<<dim3(24, 64), 256, GEMM_SMEM>>>(
        xhi, xlo, whi, wlo, Qp, Kp, vhi, vlo, D_MODEL);

    const int rp_total = M_ROWS * (D_MODEL / 2);
    rope2_split_kernel<<<(rp_total + 255) / 256, 256>>>(pos);

    attn_mma_kernel<<<dim3(SEQ / 128, BATCH * NUM_HEADS), 256, ATTN_SMEM>>>();

    // Output projection (bn < 1024 -> Cq path = out).
    gemm_mma_kernel<<<dim3(8, 64), 256, GEMM_SMEM>>>(
        aohi, aolo, wohi, wolo, out, out, vhi, vlo, D_MODEL);
}

// round 9
// speedup vs baseline: 4.0280x; 1.3827x over previous
#include <cuda_runtime.h>
#include <cuda_fp16.h>
#include <math.h>
#include <stdint.h>

#define D_MODEL   1024
#define NUM_HEADS 16
#define HEAD_DIM  64
#define BATCH     4
#define SEQ       2048
#define M_ROWS    (BATCH * SEQ)   // 8192

// ---------------------------------------------------------------------------
// Scratch (allocation-free rule: __device__ globals)
// ---------------------------------------------------------------------------
__device__ float g_Q [M_ROWS * D_MODEL];   // fp32 Q before rope
__device__ float g_K [M_ROWS * D_MODEL];   // fp32 K before rope

__device__ __half g_xhi [M_ROWS * D_MODEL];
__device__ __half g_xlo [M_ROWS * D_MODEL];
__device__ __half g_aohi[M_ROWS * D_MODEL];
__device__ __half g_aolo[M_ROWS * D_MODEL];
__device__ __half g_qhi [M_ROWS * D_MODEL];
__device__ __half g_qlo [M_ROWS * D_MODEL];
__device__ __half g_khi [M_ROWS * D_MODEL];   // K is B-operand: hi only
__device__ __half g_vhi [M_ROWS * D_MODEL];   // V is B-operand: hi only
__device__ __half g_whi [3 * D_MODEL * D_MODEL];  // packed Wq|Wk|Wv, hi only
__device__ __half g_wohi[D_MODEL * D_MODEL];      // Wo, hi only

// ---------------------------------------------------------------------------
// Helpers
// ---------------------------------------------------------------------------
__device__ __forceinline__ uint32_t smem_u32(const void* p) {
    uint32_t a;
    asm("{ .reg .u64 t; cvta.to.shared.u64 t, %1; cvt.u32.u64 %0, t; }"
        : "=r"(a) : "l"(p));
    return a;
}

#define CP_ASYNC16(dst, src) \
    asm volatile("cp.async.cg.shared.global [%0], [%1], 16;" \
                 :: "r"(dst), "l"(src) : "memory")
#define CP_COMMIT() asm volatile("cp.async.commit_group;" ::: "memory")
#define CP_WAIT(n)  asm volatile("cp.async.wait_group %0;" :: "n"(n) : "memory")

#define LDMATRIX_X4(r0, r1, r2, r3, addr) \
    asm volatile("ldmatrix.sync.aligned.m8n8.x4.shared.b16 {%0,%1,%2,%3}, [%4];" \
                 : "=r"(r0), "=r"(r1), "=r"(r2), "=r"(r3) : "r"(addr))

#define LDMATRIX_X4_T(r0, r1, r2, r3, addr) \
    asm volatile("ldmatrix.sync.aligned.m8n8.x4.trans.shared.b16 {%0,%1,%2,%3}, [%4];" \
                 : "=r"(r0), "=r"(r1), "=r"(r2), "=r"(r3) : "r"(addr))

#define MMA_F16(d, a, b0, b1) \
    asm volatile("mma.sync.aligned.m16n8k16.row.col.f32.f16.f16.f32 " \
                 "{%0,%1,%2,%3}, {%4,%5,%6,%7}, {%8,%9}, {%0,%1,%2,%3};" \
                 : "+f"((d)[0]), "+f"((d)[1]), "+f"((d)[2]), "+f"((d)[3]) \
                 : "r"((a)[0]), "r"((a)[1]), "r"((a)[2]), "r"((a)[3]), \
                   "r"(b0), "r"(b1))

__device__ __forceinline__ uint32_t packh(float lo, float hi) {
    __half2 t = __floats2half2_rn(lo, hi);
    return *reinterpret_cast<uint32_t*>(&t);
}

// hi/lo fp16 split of a pair; returns hi-packed, writes lo-packed
__device__ __forceinline__ uint32_t split_pair_h(float y0, float y1, uint32_t& lo_out) {
    __half h0 = __float2half_rn(y0);
    __half h1 = __float2half_rn(y1);
    float r0 = y0 - __half2float(h0);
    float r1 = y1 - __half2float(h1);
    lo_out = packh(r0, r1);
    __half2 hp = make_half2(h0, h1);
    return *reinterpret_cast<uint32_t*>(&hp);
}

// ---------------------------------------------------------------------------
// fp32 -> fp16 hi/lo split (A-side operands)
// ---------------------------------------------------------------------------
__global__ void split_h_kernel(const float* __restrict__ src,
                               __half* __restrict__ hi,
                               __half* __restrict__ lo, int n4)
{
    int i = blockIdx.x * blockDim.x + threadIdx.x;
    if (i >= n4) return;
    float4 v = reinterpret_cast<const float4*>(src)[i];
    uint32_t l0, h0 = split_pair_h(v.x, v.y, l0);
    uint32_t l1, h1 = split_pair_h(v.z, v.w, l1);
    reinterpret_cast<uint2*>(hi)[i] = make_uint2(h0, h1);
    reinterpret_cast<uint2*>(lo)[i] = make_uint2(l0, l1);
}

// fp32 -> fp16 convert (B-side operands: hi only)
__global__ void conv_h_kernel(const float* __restrict__ src,
                              __half* __restrict__ dst, int n4)
{
    int i = blockIdx.x * blockDim.x + threadIdx.x;
    if (i >= n4) return;
    float4 v = reinterpret_cast<const float4*>(src)[i];
    reinterpret_cast<uint2*>(dst)[i] =
        make_uint2(packh(v.x, v.y), packh(v.z, v.w));
}

// ---------------------------------------------------------------------------
// Fused RoPE (Q and K together): Q -> fp16 hi/lo (A-side), K -> fp16 hi only
// ---------------------------------------------------------------------------
__global__ void rope2_split_kernel(const int* __restrict__ pos)
{
    int idx = blockIdx.x * blockDim.x + threadIdx.x;
    const int total = M_ROWS * (D_MODEL / 2);
    if (idx >= total) return;

    int row = idx >> 9;
    int p2  = idx & 511;
    int h   = p2 >> 5;
    int j   = p2 & 31;
    int s   = row & (SEQ - 1);

    float inv = powf(10000.0f, -(float)(2 * j) / 64.0f);
    float ang = (float)pos[s] * inv;
    float sn, cs;
    sincosf(ang, &sn, &cs);

    int base = row * D_MODEL + h * HEAD_DIM + 2 * j;

    {
        float2 v = *reinterpret_cast<const float2*>(g_Q + base);
        float y0 = v.x * cs - v.y * sn;
        float y1 = v.x * sn + v.y * cs;
        uint32_t lo, hi = split_pair_h(y0, y1, lo);
        *reinterpret_cast<uint32_t*>(g_qhi + base) = hi;
        *reinterpret_cast<uint32_t*>(g_qlo + base) = lo;
    }
    {
        float2 v = *reinterpret_cast<const float2*>(g_K + base);
        float y0 = v.x * cs - v.y * sn;
        float y1 = v.x * sn + v.y * cs;
        *reinterpret_cast<uint32_t*>(g_khi + base) = packh(y0, y1);
    }
}

// ---------------------------------------------------------------------------
// fp16-split HMMA GEMM, 2-pass: C = (Ah+Al) * Bh^T.
// 128x128 tile, BK=32, 3-stage cp.async, 8 warps (4x2), warp tile 32x64.
// Stage rows: 0..127 Ahi, 128..255 Alo, 256..383 Bhi  (80B rows).
// Routed epilogue: bn<1024 fp32->Cq ; <2048 fp32->Ck ; else fp16->Vh.
// ---------------------------------------------------------------------------
#define BK        32
#define ROWB      80
#define GSTAGE_B  (384 * ROWB)      // 30720
#define GEMM_SMEM (3 * GSTAGE_B)    // 92160

__global__ __launch_bounds__(256, 2) void gemm_mma_kernel(
    const __half* __restrict__ Ahi, const __half* __restrict__ Alo,
    const __half* __restrict__ Bh,
    float* __restrict__ Cq, float* __restrict__ Ck,
    __half* __restrict__ Vh, int K)
{
    extern __shared__ char gsm[];

    const int tid  = threadIdx.x;
    const int warp = tid >> 5;
    const int lane = tid & 31;
    const int wr   = warp & 3;
    const int wc   = warp >> 2;
    const int bm   = blockIdx.y * 128;
    const int bn   = blockIdx.x * 128;

    float acc[2][8][4];
#pragma unroll
    for (int i = 0; i < 2; i++)
#pragma unroll
        for (int j = 0; j < 8; j++)
#pragma unroll
            for (int k = 0; k < 4; k++) acc[i][j][k] = 0.0f;

    const int nkc = K / BK;   // 32

    auto load_chunk = [&](int c, int stage) {
        const int kc = c * BK;
        char* st = gsm + stage * GSTAGE_B;
#pragma unroll
        for (int p = 0; p < 6; p++) {
            int v   = tid + p * 256;
            int r   = v >> 2;
            int seg = v & 3;
            int rr  = r & 127;
            const __half* base;
            size_t grow;
            if (r < 128)      { base = Ahi; grow = (size_t)(bm + rr); }
            else if (r < 256) { base = Alo; grow = (size_t)(bm + rr); }
            else              { base = Bh;  grow = (size_t)(bn + rr); }
            CP_ASYNC16(smem_u32(st + r * ROWB + seg * 16),
                       base + grow * K + kc + seg * 8);
        }
    };

    load_chunk(0, 0); CP_COMMIT();
    load_chunk(1, 1); CP_COMMIT();

    const int sub  = lane >> 3;
    const int lrow = lane & 7;

    for (int c = 0; c < nkc; ++c) {
        if (c + 1 < nkc) { CP_WAIT(1); } else { CP_WAIT(0); }
        __syncthreads();
        if (c + 2 < nkc) {
            int nst = (c + 2) % 3;
            load_chunk(c + 2, nst);
            CP_COMMIT();
        }

        char* st = gsm + (c % 3) * GSTAGE_B;

#pragma unroll
        for (int s = 0; s < 2; ++s) {
            uint32_t afh[2][4], afl[2][4];
#pragma unroll
            for (int mt = 0; mt < 2; ++mt) {
                int row = wr * 32 + mt * 16 + (sub & 1) * 8 + lrow;
                uint32_t ad = smem_u32(st + row * ROWB + s * 32 + (sub >> 1) * 16);
                LDMATRIX_X4(afh[mt][0], afh[mt][1], afh[mt][2], afh[mt][3], ad);
                LDMATRIX_X4(afl[mt][0], afl[mt][1], afl[mt][2], afl[mt][3],
                            ad + 128 * ROWB);
            }
#pragma unroll
            for (int nt = 0; nt < 4; ++nt) {
                int row = wc * 64 + nt * 16 + (sub >> 1) * 8 + lrow;
                uint32_t bd = smem_u32(st + (256 + row) * ROWB + s * 32 + (sub & 1) * 16);
                uint32_t bh[4];
                LDMATRIX_X4(bh[0], bh[1], bh[2], bh[3], bd);
#pragma unroll
                for (int mt = 0; mt < 2; ++mt) {
                    MMA_F16(acc[mt][2 * nt],     afh[mt], bh[0], bh[1]);
                    MMA_F16(acc[mt][2 * nt + 1], afh[mt], bh[2], bh[3]);
                    MMA_F16(acc[mt][2 * nt],     afl[mt], bh[0], bh[1]);
                    MMA_F16(acc[mt][2 * nt + 1], afl[mt], bh[2], bh[3]);
                }
            }
        }
        __syncthreads();
    }

    // ---- routed epilogue (branch uniform per CTA) ----
    if (bn < 1024) {
#pragma unroll
        for (int mt = 0; mt < 2; ++mt)
#pragma unroll
            for (int nt = 0; nt < 8; ++nt) {
                int r0 = bm + wr * 32 + mt * 16 + (lane >> 2);
                int cc = bn + wc * 64 + nt * 8 + (lane & 3) * 2;
                *reinterpret_cast<float2*>(&Cq[(size_t)r0 * 1024 + cc]) =
                    make_float2(acc[mt][nt][0], acc[mt][nt][1]);
                *reinterpret_cast<float2*>(&Cq[(size_t)(r0 + 8) * 1024 + cc]) =
                    make_float2(acc[mt][nt][2], acc[mt][nt][3]);
            }
    } else if (bn < 2048) {
#pragma unroll
        for (int mt = 0; mt < 2; ++mt)
#pragma unroll
            for (int nt = 0; nt < 8; ++nt) {
                int r0 = bm + wr * 32 + mt * 16 + (lane >> 2);
                int cc = bn - 1024 + wc * 64 + nt * 8 + (lane & 3) * 2;
                *reinterpret_cast<float2*>(&Ck[(size_t)r0 * 1024 + cc]) =
                    make_float2(acc[mt][nt][0], acc[mt][nt][1]);
                *reinterpret_cast<float2*>(&Ck[(size_t)(r0 + 8) * 1024 + cc]) =
                    make_float2(acc[mt][nt][2], acc[mt][nt][3]);
            }
    } else {
#pragma unroll
        for (int mt = 0; mt < 2; ++mt)
#pragma unroll
            for (int nt = 0; nt < 8; ++nt) {
                int r0 = bm + wr * 32 + mt * 16 + (lane >> 2);
                int cc = bn - 2048 + wc * 64 + nt * 8 + (lane & 3) * 2;
                *reinterpret_cast<uint32_t*>(&Vh[(size_t)r0 * 1024 + cc]) =
                    packh(acc[mt][nt][0], acc[mt][nt][1]);
                *reinterpret_cast<uint32_t*>(&Vh[(size_t)(r0 + 8) * 1024 + cc]) =
                    packh(acc[mt][nt][2], acc[mt][nt][3]);
            }
    }
}

// ---------------------------------------------------------------------------
// fp16 HMMA flash attention, causal, 2-pass splits.
// Q: hi/lo frags (A-side).  K,V: hi only (B-side).  P: hi/lo (A-side).
// qt is REVERSED across blockIdx.x so heavy (high-qt) CTAs launch first.
// ---------------------------------------------------------------------------
#define AT_ROWE 72
#define KV_ARRE (64 * AT_ROWE)          // one K or V tile (halves)
#define KV_BUFE (2 * KV_ARRE)           // K + V per buffer
#define ATTN_SMEM (2 * KV_BUFE * 2)     // 36864 bytes (also covers Q staging)

__global__ __launch_bounds__(256, 1) void attn_mma_kernel()
{
    extern __shared__ char at_sm[];
    __half* smb = reinterpret_cast<__half*>(at_sm);

    const int tid  = threadIdx.x;
    const int w    = tid >> 5;
    const int lane = tid & 31;
    const int sub  = lane >> 3;
    const int lrow = lane & 7;
    const int qt   = (int)(gridDim.x - 1 - blockIdx.x);   // reversed: big first
    const int bh   = blockIdx.y;
    const int b    = bh >> 4;
    const int h    = bh & 15;

    const size_t rowbase = (size_t)b * SEQ;
    const int    q0      = qt * 128;

    // ---- Stage Q hi/lo through smem (fits in the 36864B region) ----
    {
        const __half* srcs[2];
        srcs[0] = g_qhi; srcs[1] = g_qlo;
#pragma unroll
        for (int arr = 0; arr < 2; ++arr) {
            const __half* s = srcs[arr] + (rowbase + q0) * D_MODEL + h * 64;
            __half* d = smb + arr * (128 * AT_ROWE);
#pragma unroll
            for (int p = 0; p < 4; ++p) {
                int v = tid + p * 256;
                int r = v >> 3, seg = v & 7;
                CP_ASYNC16(smem_u32(d + r * AT_ROWE + seg * 8),
                           s + (size_t)r * D_MODEL + seg * 8);
            }
        }
        CP_COMMIT(); CP_WAIT(0);
        __syncthreads();
    }

    uint32_t qh[4][4], ql[4][4];
#pragma unroll
    for (int kt = 0; kt < 4; ++kt) {
        int row = w * 16 + (sub & 1) * 8 + lrow;
        int col = kt * 16 + (sub >> 1) * 8;
        uint32_t a0 = smem_u32(smb + row * AT_ROWE + col);
        LDMATRIX_X4(qh[kt][0], qh[kt][1], qh[kt][2], qh[kt][3], a0);
        uint32_t a1 = smem_u32(smb + 128 * AT_ROWE + row * AT_ROWE + col);
        LDMATRIX_X4(ql[kt][0], ql[kt][1], ql[kt][2], ql[kt][3], a1);
    }
    __syncthreads();   // Q region now reused as KV double-buffer

    float O[8][4];
#pragma unroll
    for (int i = 0; i < 8; i++)
#pragma unroll
        for (int j = 0; j < 4; j++) O[i][j] = 0.0f;
    float mrow[2] = { -INFINITY, -INFINITY };
    float lrow2[2] = { 0.0f, 0.0f };

    const int ntiles = 2 * qt + 2;

    auto load_kv = [&](int k0, __half* buf) {
        const __half* srcs[2];
        srcs[0] = g_khi; srcs[1] = g_vhi;
#pragma unroll
        for (int arr = 0; arr < 2; ++arr) {
            const __half* s = srcs[arr] + (rowbase + k0) * D_MODEL + h * 64;
            __half* d = buf + arr * KV_ARRE;
#pragma unroll
            for (int p = 0; p < 2; ++p) {
                int v = tid + p * 256;
                int r = v >> 3, seg = v & 7;
                CP_ASYNC16(smem_u32(d + r * AT_ROWE + seg * 8),
                           s + (size_t)r * D_MODEL + seg * 8);
            }
        }
    };

    load_kv(0, smb); CP_COMMIT();

    for (int t = 0; t < ntiles; ++t) {
        __half* cbuf = smb + (t & 1) * KV_BUFE;
        if (t + 1 < ntiles) {
            load_kv((t + 1) * 64, smb + ((t + 1) & 1) * KV_BUFE);
            CP_COMMIT();
            CP_WAIT(1);
        } else {
            CP_WAIT(0);
        }
        __syncthreads();

        const int k0 = t * 64;
        const bool active = (k0 <= q0 + w * 16 + 15);

        if (active) {
            __half* sKh = cbuf;
            __half* sVh = cbuf + KV_ARRE;

            // ---- S = Q K^T (2-pass fp16 split) ----
            float sacc[8][4];
#pragma unroll
            for (int i = 0; i < 8; i++)
#pragma unroll
                for (int j = 0; j < 4; j++) sacc[i][j] = 0.0f;

#pragma unroll
            for (int kt = 0; kt < 4; ++kt) {
#pragma unroll
                for (int g = 0; g < 4; ++g) {
                    int row = g * 16 + (sub >> 1) * 8 + lrow;
                    int col = kt * 16 + (sub & 1) * 8;
                    uint32_t kh[4];
                    LDMATRIX_X4(kh[0], kh[1], kh[2], kh[3],
                                smem_u32(sKh + row * AT_ROWE + col));
                    MMA_F16(sacc[2 * g],     qh[kt], kh[0], kh[1]);
                    MMA_F16(sacc[2 * g + 1], qh[kt], kh[2], kh[3]);
                    MMA_F16(sacc[2 * g],     ql[kt], kh[0], kh[1]);
                    MMA_F16(sacc[2 * g + 1], ql[kt], kh[2], kh[3]);
                }
            }

            // ---- scale + causal mask ----
            const int qrow0 = q0 + w * 16 + (lane >> 2);
            const bool need_mask = (k0 + 63 > q0 + w * 16);
#pragma unroll
            for (int nt = 0; nt < 8; ++nt) {
#pragma unroll
                for (int j = 0; j < 4; j++) sacc[nt][j] *= 0.125f;
                if (need_mask) {
                    int col = k0 + nt * 8 + (lane & 3) * 2;
                    if (col     > qrow0)     sacc[nt][0] = -INFINITY;
                    if (col + 1 > qrow0)     sacc[nt][1] = -INFINITY;
                    if (col     > qrow0 + 8) sacc[nt][2] = -INFINITY;
                    if (col + 1 > qrow0 + 8) sacc[nt][3] = -INFINITY;
                }
            }

            // ---- online softmax ----
            float mx0 = -INFINITY, mx1 = -INFINITY;
#pragma unroll
            for (int nt = 0; nt < 8; ++nt) {
                mx0 = fmaxf(mx0, fmaxf(sacc[nt][0], sacc[nt][1]));
                mx1 = fmaxf(mx1, fmaxf(sacc[nt][2], sacc[nt][3]));
            }
            mx0 = fmaxf(mx0, __shfl_xor_sync(0xffffffff, mx0, 1));
            mx0 = fmaxf(mx0, __shfl_xor_sync(0xffffffff, mx0, 2));
            mx1 = fmaxf(mx1, __shfl_xor_sync(0xffffffff, mx1, 1));
            mx1 = fmaxf(mx1, __shfl_xor_sync(0xffffffff, mx1, 2));

            float mn0 = fmaxf(mrow[0], mx0);
            float mn1 = fmaxf(mrow[1], mx1);
            float a0 = __expf(mrow[0] - mn0);
            float a1 = __expf(mrow[1] - mn1);
            mrow[0] = mn0; mrow[1] = mn1;

            float rs0 = 0.0f, rs1 = 0.0f;
#pragma unroll
            for (int nt = 0; nt < 8; ++nt) {
                sacc[nt][0] = __expf(sacc[nt][0] - mn0);
                sacc[nt][1] = __expf(sacc[nt][1] - mn0);
                sacc[nt][2] = __expf(sacc[nt][2] - mn1);
                sacc[nt][3] = __expf(sacc[nt][3] - mn1);
                rs0 += sacc[nt][0] + sacc[nt][1];
                rs1 += sacc[nt][2] + sacc[nt][3];
            }
            rs0 += __shfl_xor_sync(0xffffffff, rs0, 1);
            rs0 += __shfl_xor_sync(0xffffffff, rs0, 2);
            rs1 += __shfl_xor_sync(0xffffffff, rs1, 1);
            rs1 += __shfl_xor_sync(0xffffffff, rs1, 2);
            lrow2[0] = lrow2[0] * a0 + rs0;
            lrow2[1] = lrow2[1] * a1 + rs1;

#pragma unroll
            for (int dn = 0; dn < 8; ++dn) {
                O[dn][0] *= a0; O[dn][1] *= a0;
                O[dn][2] *= a1; O[dn][3] *= a1;
            }

            // ---- pack P hi/lo fragments (A-operand layout) ----
            uint32_t ph[4][4], pl[4][4];
#pragma unroll
            for (int kt = 0; kt < 4; ++kt) {
                float e[8] = { sacc[2 * kt][0],     sacc[2 * kt][1],
                               sacc[2 * kt][2],     sacc[2 * kt][3],
                               sacc[2 * kt + 1][0], sacc[2 * kt + 1][1],
                               sacc[2 * kt + 1][2], sacc[2 * kt + 1][3] };
#pragma unroll
                for (int i = 0; i < 4; i++) {
                    uint32_t lo;
                    ph[kt][i] = split_pair_h(e[2 * i], e[2 * i + 1], lo);
                    pl[kt][i] = lo;
                }
            }

            // ---- O += P V (2-pass fp16 split) ----
#pragma unroll
            for (int kt = 0; kt < 4; ++kt) {
#pragma unroll
                for (int dg = 0; dg < 4; ++dg) {
                    int row = kt * 16 + (sub & 1) * 8 + lrow;
                    int col = dg * 16 + (sub >> 1) * 8;
                    uint32_t vh[4];
                    LDMATRIX_X4_T(vh[0], vh[1], vh[2], vh[3],
                                  smem_u32(sVh + row * AT_ROWE + col));
                    MMA_F16(O[2 * dg],     ph[kt], vh[0], vh[1]);
                    MMA_F16(O[2 * dg + 1], ph[kt], vh[2], vh[3]);
                    MMA_F16(O[2 * dg],     pl[kt], vh[0], vh[1]);
                    MMA_F16(O[2 * dg + 1], pl[kt], vh[2], vh[3]);
                }
            }
        }
        __syncthreads();
    }

    // ---- normalize + write AO directly as fp16 hi/lo (A-side of Wo GEMM) ----
    const float inv0 = 1.0f / lrow2[0];
    const float inv1 = 1.0f / lrow2[1];
    const size_t r0 = rowbase + q0 + w * 16 + (lane >> 2);
#pragma unroll
    for (int dn = 0; dn < 8; ++dn) {
        int col = h * 64 + dn * 8 + (lane & 3) * 2;
        uint32_t lo0, hi0 = split_pair_h(O[dn][0] * inv0, O[dn][1] * inv0, lo0);
        uint32_t lo1, hi1 = split_pair_h(O[dn][2] * inv1, O[dn][3] * inv1, lo1);
        *reinterpret_cast<uint32_t*>(&g_aohi[r0 * D_MODEL + col]) = hi0;
        *reinterpret_cast<uint32_t*>(&g_aolo[r0 * D_MODEL + col]) = lo0;
        *reinterpret_cast<uint32_t*>(&g_aohi[(r0 + 8) * D_MODEL + col]) = hi1;
        *reinterpret_cast<uint32_t*>(&g_aolo[(r0 + 8) * D_MODEL + col]) = lo1;
    }
}

// ---------------------------------------------------------------------------
// Launch
// ---------------------------------------------------------------------------
extern "C" void kernel_launch(void* const* d_in, const int* in_sizes, int n_in,
                              void* d_out, int out_size)
{
    const float* x   = (const float*)d_in[0];
    const int*   pos = (const int*)  d_in[1];
    const float* Wq  = (const float*)d_in[2];
    const float* Wk  = (const float*)d_in[3];
    const float* Wv  = (const float*)d_in[4];
    const float* Wo  = (const float*)d_in[5];
    float*       out = (float*)d_out;

    float *Qp, *Kp;
    cudaGetSymbolAddress((void**)&Qp, g_Q);
    cudaGetSymbolAddress((void**)&Kp, g_K);

    __half *xhi, *xlo, *aohi, *aolo, *vhi, *whi, *wohi;
    cudaGetSymbolAddress((void**)&xhi,  g_xhi);
    cudaGetSymbolAddress((void**)&xlo,  g_xlo);
    cudaGetSymbolAddress((void**)&aohi, g_aohi);
    cudaGetSymbolAddress((void**)&aolo, g_aolo);
    cudaGetSymbolAddress((void**)&vhi,  g_vhi);
    cudaGetSymbolAddress((void**)&whi,  g_whi);
    cudaGetSymbolAddress((void**)&wohi, g_wohi);

    cudaFuncSetAttribute(gemm_mma_kernel,
                         cudaFuncAttributeMaxDynamicSharedMemorySize, GEMM_SMEM);
    cudaFuncSetAttribute(attn_mma_kernel,
                         cudaFuncAttributeMaxDynamicSharedMemorySize, ATTN_SMEM);

    const int nx = M_ROWS * D_MODEL / 4;
    const int nw = D_MODEL * D_MODEL / 4;
    const int WSZ = D_MODEL * D_MODEL;

    split_h_kernel<<<(nx + 255) / 256, 256>>>(x, xhi, xlo, nx);
    conv_h_kernel<<<(nw + 255) / 256, 256>>>(Wq, whi,           nw);
    conv_h_kernel<<<(nw + 255) / 256, 256>>>(Wk, whi + WSZ,     nw);
    conv_h_kernel<<<(nw + 255) / 256, 256>>>(Wv, whi + 2 * WSZ, nw);
    conv_h_kernel<<<(nw + 255) / 256, 256>>>(Wo, wohi, nw);

    // Fused QKV projection: B rows 0..3071 = Wq|Wk|Wv; V written as fp16.
    gemm_mma_kernel<<<dim3(24, 64), 256, GEMM_SMEM>>>(
        xhi, xlo, whi, Qp, Kp, vhi, D_MODEL);

    const int rp_total = M_ROWS * (D_MODEL / 2);
    rope2_split_kernel<<<(rp_total + 255) / 256, 256>>>(pos);

    attn_mma_kernel<<<dim3(SEQ / 128, BATCH * NUM_HEADS), 256, ATTN_SMEM>>>();

    // Output projection (bn < 1024 -> Cq path = out).
    gemm_mma_kernel<<<dim3(8, 64), 256, GEMM_SMEM>>>(
        aohi, aolo, wohi, out, out, vhi, D_MODEL);
}

// round 10
// speedup vs baseline: 4.5118x; 1.1201x over previous
#include <cuda_runtime.h>
#include <cuda_fp16.h>
#include <math.h>
#include <stdint.h>

#define D_MODEL   1024
#define NUM_HEADS 16
#define HEAD_DIM  64
#define BATCH     4
#define SEQ       2048
#define M_ROWS    (BATCH * SEQ)   // 8192

// ---------------------------------------------------------------------------
// Scratch (allocation-free rule: __device__ globals)
// ---------------------------------------------------------------------------
__device__ __half g_xhi [M_ROWS * D_MODEL];
__device__ __half g_xlo [M_ROWS * D_MODEL];
__device__ __half g_aohi[M_ROWS * D_MODEL];
__device__ __half g_aolo[M_ROWS * D_MODEL];
__device__ __half g_qhi [M_ROWS * D_MODEL];
__device__ __half g_qlo [M_ROWS * D_MODEL];
__device__ __half g_khi [M_ROWS * D_MODEL];   // B-operand: hi only
__device__ __half g_vhi [M_ROWS * D_MODEL];   // B-operand: hi only
__device__ __half g_whi [3 * D_MODEL * D_MODEL];  // packed Wq|Wk|Wv
__device__ __half g_wohi[D_MODEL * D_MODEL];

// ---------------------------------------------------------------------------
// Helpers
// ---------------------------------------------------------------------------
__device__ __forceinline__ uint32_t smem_u32(const void* p) {
    uint32_t a;
    asm("{ .reg .u64 t; cvta.to.shared.u64 t, %1; cvt.u32.u64 %0, t; }"
        : "=r"(a) : "l"(p));
    return a;
}

#define CP_ASYNC16(dst, src) \
    asm volatile("cp.async.cg.shared.global [%0], [%1], 16;" \
                 :: "r"(dst), "l"(src) : "memory")
#define CP_COMMIT() asm volatile("cp.async.commit_group;" ::: "memory")
#define CP_WAIT(n)  asm volatile("cp.async.wait_group %0;" :: "n"(n) : "memory")

#define LDMATRIX_X4(r0, r1, r2, r3, addr) \
    asm volatile("ldmatrix.sync.aligned.m8n8.x4.shared.b16 {%0,%1,%2,%3}, [%4];" \
                 : "=r"(r0), "=r"(r1), "=r"(r2), "=r"(r3) : "r"(addr))

#define LDMATRIX_X4_T(r0, r1, r2, r3, addr) \
    asm volatile("ldmatrix.sync.aligned.m8n8.x4.trans.shared.b16 {%0,%1,%2,%3}, [%4];" \
                 : "=r"(r0), "=r"(r1), "=r"(r2), "=r"(r3) : "r"(addr))

#define MMA_F16(d, a, b0, b1) \
    asm volatile("mma.sync.aligned.m16n8k16.row.col.f32.f16.f16.f32 " \
                 "{%0,%1,%2,%3}, {%4,%5,%6,%7}, {%8,%9}, {%0,%1,%2,%3};" \
                 : "+f"((d)[0]), "+f"((d)[1]), "+f"((d)[2]), "+f"((d)[3]) \
                 : "r"((a)[0]), "r"((a)[1]), "r"((a)[2]), "r"((a)[3]), \
                   "r"(b0), "r"(b1))

__device__ __forceinline__ uint32_t packh(float lo, float hi) {
    __half2 t = __floats2half2_rn(lo, hi);
    return *reinterpret_cast<uint32_t*>(&t);
}

__device__ __forceinline__ uint32_t split_pair_h(float y0, float y1, uint32_t& lo_out) {
    __half h0 = __float2half_rn(y0);
    __half h1 = __float2half_rn(y1);
    float r0 = y0 - __half2float(h0);
    float r1 = y1 - __half2float(h1);
    lo_out = packh(r0, r1);
    __half2 hp = make_half2(h0, h1);
    return *reinterpret_cast<uint32_t*>(&hp);
}

// ---------------------------------------------------------------------------
// fp32 -> fp16 hi/lo split (A-side: x)
// ---------------------------------------------------------------------------
__global__ void split_h_kernel(const float* __restrict__ src,
                               __half* __restrict__ hi,
                               __half* __restrict__ lo, int n4)
{
    int i = blockIdx.x * blockDim.x + threadIdx.x;
    if (i >= n4) return;
    float4 v = reinterpret_cast<const float4*>(src)[i];
    uint32_t l0, h0 = split_pair_h(v.x, v.y, l0);
    uint32_t l1, h1 = split_pair_h(v.z, v.w, l1);
    reinterpret_cast<uint2*>(hi)[i] = make_uint2(h0, h1);
    reinterpret_cast<uint2*>(lo)[i] = make_uint2(l0, l1);
}

// All four weights -> fp16 in one launch (B-side: hi only)
__global__ void conv_w_kernel(const float* __restrict__ Wq, const float* __restrict__ Wk,
                              const float* __restrict__ Wv, const float* __restrict__ Wo,
                              __half* __restrict__ whi, __half* __restrict__ wohi, int n4)
{
    int i = blockIdx.x * blockDim.x + threadIdx.x;
    if (i >= 4 * n4) return;
    int sel = i / n4;
    int rem = i - sel * n4;
    const float* src = (sel == 0) ? Wq : (sel == 1) ? Wk : (sel == 2) ? Wv : Wo;
    float4 v = reinterpret_cast<const float4*>(src)[rem];
    uint2 o = make_uint2(packh(v.x, v.y), packh(v.z, v.w));
    if (sel < 3) reinterpret_cast<uint2*>(whi)[(size_t)sel * n4 + rem] = o;
    else         reinterpret_cast<uint2*>(wohi)[rem] = o;
}

// ---------------------------------------------------------------------------
// fp16-split HMMA GEMM, 2-pass: C = (Ah+Al) * Bh^T.
// 128x128 tile, BK=64, 2-stage cp.async double buffer, 2 CTAs/SM.
// Stage rows (144B each): 0..127 Ahi, 128..255 Alo, 256..383 Bh.
// Routed epilogue (uniform per CTA):
//   bn<1024 : do_rope ? RoPE+split -> qhi/qlo : fp32 -> Cq
//   bn<2048 : RoPE -> khi (fp16)
//   else    : fp16 -> vhi
// ---------------------------------------------------------------------------
#define BK        64
#define ROWB      144
#define GSTAGE_B  (384 * ROWB)      // 55296
#define GEMM_SMEM (2 * GSTAGE_B)    // 110592

__global__ __launch_bounds__(256, 2) void gemm_mma_kernel(
    const __half* __restrict__ Ahi, const __half* __restrict__ Alo,
    const __half* __restrict__ Bh, const int* __restrict__ pos,
    float* __restrict__ Cq,
    __half* __restrict__ Qhi, __half* __restrict__ Qlo,
    __half* __restrict__ Kh, __half* __restrict__ Vh,
    int K, int do_rope)
{
    extern __shared__ char gsm[];

    const int tid  = threadIdx.x;
    const int warp = tid >> 5;
    const int lane = tid & 31;
    const int wr   = warp & 3;
    const int wc   = warp >> 2;
    const int bm   = blockIdx.y * 128;
    const int bn   = blockIdx.x * 128;

    float acc[2][8][4];
#pragma unroll
    for (int i = 0; i < 2; i++)
#pragma unroll
        for (int j = 0; j < 8; j++)
#pragma unroll
            for (int k = 0; k < 4; k++) acc[i][j][k] = 0.0f;

    const int nkc = K / BK;   // 16

    auto load_chunk = [&](int c, int stage) {
        const int kc = c * BK;
        char* st = gsm + stage * GSTAGE_B;
#pragma unroll
        for (int p = 0; p < 12; p++) {
            int v   = tid + p * 256;
            int r   = v >> 3;
            int seg = v & 7;
            int rr  = r & 127;
            const __half* base;
            size_t grow;
            if (r < 128)      { base = Ahi; grow = (size_t)(bm + rr); }
            else if (r < 256) { base = Alo; grow = (size_t)(bm + rr); }
            else              { base = Bh;  grow = (size_t)(bn + rr); }
            CP_ASYNC16(smem_u32(st + r * ROWB + seg * 16),
                       base + grow * K + kc + seg * 8);
        }
    };

    load_chunk(0, 0); CP_COMMIT();

    const int sub  = lane >> 3;
    const int lrow = lane & 7;

    for (int c = 0; c < nkc; ++c) {
        if (c + 1 < nkc) {
            load_chunk(c + 1, (c + 1) & 1);
            CP_COMMIT();
            CP_WAIT(1);
        } else {
            CP_WAIT(0);
        }
        __syncthreads();

        char* st = gsm + (c & 1) * GSTAGE_B;

#pragma unroll
        for (int s = 0; s < 4; ++s) {
            uint32_t afh[2][4], afl[2][4];
#pragma unroll
            for (int mt = 0; mt < 2; ++mt) {
                int row = wr * 32 + mt * 16 + (sub & 1) * 8 + lrow;
                uint32_t ad = smem_u32(st + row * ROWB + s * 32 + (sub >> 1) * 16);
                LDMATRIX_X4(afh[mt][0], afh[mt][1], afh[mt][2], afh[mt][3], ad);
                LDMATRIX_X4(afl[mt][0], afl[mt][1], afl[mt][2], afl[mt][3],
                            ad + 128 * ROWB);
            }
#pragma unroll
            for (int nt = 0; nt < 4; ++nt) {
                int row = wc * 64 + nt * 16 + (sub >> 1) * 8 + lrow;
                uint32_t bd = smem_u32(st + (256 + row) * ROWB + s * 32 + (sub & 1) * 16);
                uint32_t bh[4];
                LDMATRIX_X4(bh[0], bh[1], bh[2], bh[3], bd);
#pragma unroll
                for (int mt = 0; mt < 2; ++mt) {
                    MMA_F16(acc[mt][2 * nt],     afh[mt], bh[0], bh[1]);
                    MMA_F16(acc[mt][2 * nt + 1], afh[mt], bh[2], bh[3]);
                    MMA_F16(acc[mt][2 * nt],     afl[mt], bh[0], bh[1]);
                    MMA_F16(acc[mt][2 * nt + 1], afl[mt], bh[2], bh[3]);
                }
            }
        }
        __syncthreads();
    }

    // ---- routed epilogue (branch uniform per CTA) ----
    if (bn < 1024 && !do_rope) {
        // fp32 output (final projection)
#pragma unroll
        for (int mt = 0; mt < 2; ++mt)
#pragma unroll
            for (int nt = 0; nt < 8; ++nt) {
                int r0 = bm + wr * 32 + mt * 16 + (lane >> 2);
                int cc = bn + wc * 64 + nt * 8 + (lane & 3) * 2;
                *reinterpret_cast<float2*>(&Cq[(size_t)r0 * 1024 + cc]) =
                    make_float2(acc[mt][nt][0], acc[mt][nt][1]);
                *reinterpret_cast<float2*>(&Cq[(size_t)(r0 + 8) * 1024 + cc]) =
                    make_float2(acc[mt][nt][2], acc[mt][nt][3]);
            }
    } else if (bn < 2048) {
        // Q (bn<1024, rope+split) or K (rope, hi only)
        const bool isQ = (bn < 1024);
#pragma unroll
        for (int mt = 0; mt < 2; ++mt)
#pragma unroll
            for (int nt = 0; nt < 8; ++nt) {
                int r0 = bm + wr * 32 + mt * 16 + (lane >> 2);
                int cc = (isQ ? bn : bn - 1024) + wc * 64 + nt * 8 + (lane & 3) * 2;
                int j  = (cc & 63) >> 1;
                float invf = powf(10000.0f, -(float)(2 * j) / 64.0f);
                // row r0
                {
                    float ang = (float)pos[r0 & (SEQ - 1)] * invf;
                    float sn, cs; sincosf(ang, &sn, &cs);
                    float y0 = acc[mt][nt][0] * cs - acc[mt][nt][1] * sn;
                    float y1 = acc[mt][nt][0] * sn + acc[mt][nt][1] * cs;
                    if (isQ) {
                        uint32_t lo, hi = split_pair_h(y0, y1, lo);
                        *reinterpret_cast<uint32_t*>(&Qhi[(size_t)r0 * 1024 + cc]) = hi;
                        *reinterpret_cast<uint32_t*>(&Qlo[(size_t)r0 * 1024 + cc]) = lo;
                    } else {
                        *reinterpret_cast<uint32_t*>(&Kh[(size_t)r0 * 1024 + cc]) =
                            packh(y0, y1);
                    }
                }
                // row r0+8
                {
                    int r1 = r0 + 8;
                    float ang = (float)pos[r1 & (SEQ - 1)] * invf;
                    float sn, cs; sincosf(ang, &sn, &cs);
                    float y0 = acc[mt][nt][2] * cs - acc[mt][nt][3] * sn;
                    float y1 = acc[mt][nt][2] * sn + acc[mt][nt][3] * cs;
                    if (isQ) {
                        uint32_t lo, hi = split_pair_h(y0, y1, lo);
                        *reinterpret_cast<uint32_t*>(&Qhi[(size_t)r1 * 1024 + cc]) = hi;
                        *reinterpret_cast<uint32_t*>(&Qlo[(size_t)r1 * 1024 + cc]) = lo;
                    } else {
                        *reinterpret_cast<uint32_t*>(&Kh[(size_t)r1 * 1024 + cc]) =
                            packh(y0, y1);
                    }
                }
            }
    } else {
        // V: fp16 hi only
#pragma unroll
        for (int mt = 0; mt < 2; ++mt)
#pragma unroll
            for (int nt = 0; nt < 8; ++nt) {
                int r0 = bm + wr * 32 + mt * 16 + (lane >> 2);
                int cc = bn - 2048 + wc * 64 + nt * 8 + (lane & 3) * 2;
                *reinterpret_cast<uint32_t*>(&Vh[(size_t)r0 * 1024 + cc]) =
                    packh(acc[mt][nt][0], acc[mt][nt][1]);
                *reinterpret_cast<uint32_t*>(&Vh[(size_t)(r0 + 8) * 1024 + cc]) =
                    packh(acc[mt][nt][2], acc[mt][nt][3]);
            }
    }
}

// ---------------------------------------------------------------------------
// fp16 HMMA flash attention, causal, 2-pass splits (unchanged from R9).
// ---------------------------------------------------------------------------
#define AT_ROWE 72
#define KV_ARRE (64 * AT_ROWE)
#define KV_BUFE (2 * KV_ARRE)
#define ATTN_SMEM (2 * KV_BUFE * 2)

__global__ __launch_bounds__(256, 1) void attn_mma_kernel()
{
    extern __shared__ char at_sm[];
    __half* smb = reinterpret_cast<__half*>(at_sm);

    const int tid  = threadIdx.x;
    const int w    = tid >> 5;
    const int lane = tid & 31;
    const int sub  = lane >> 3;
    const int lrow = lane & 7;
    const int qt   = (int)(gridDim.x - 1 - blockIdx.x);
    const int bh   = blockIdx.y;
    const int b    = bh >> 4;
    const int h    = bh & 15;

    const size_t rowbase = (size_t)b * SEQ;
    const int    q0      = qt * 128;

    {
        const __half* srcs[2];
        srcs[0] = g_qhi; srcs[1] = g_qlo;
#pragma unroll
        for (int arr = 0; arr < 2; ++arr) {
            const __half* s = srcs[arr] + (rowbase + q0) * D_MODEL + h * 64;
            __half* d = smb + arr * (128 * AT_ROWE);
#pragma unroll
            for (int p = 0; p < 4; ++p) {
                int v = tid + p * 256;
                int r = v >> 3, seg = v & 7;
                CP_ASYNC16(smem_u32(d + r * AT_ROWE + seg * 8),
                           s + (size_t)r * D_MODEL + seg * 8);
            }
        }
        CP_COMMIT(); CP_WAIT(0);
        __syncthreads();
    }

    uint32_t qh[4][4], ql[4][4];
#pragma unroll
    for (int kt = 0; kt < 4; ++kt) {
        int row = w * 16 + (sub & 1) * 8 + lrow;
        int col = kt * 16 + (sub >> 1) * 8;
        uint32_t a0 = smem_u32(smb + row * AT_ROWE + col);
        LDMATRIX_X4(qh[kt][0], qh[kt][1], qh[kt][2], qh[kt][3], a0);
        uint32_t a1 = smem_u32(smb + 128 * AT_ROWE + row * AT_ROWE + col);
        LDMATRIX_X4(ql[kt][0], ql[kt][1], ql[kt][2], ql[kt][3], a1);
    }
    __syncthreads();

    float O[8][4];
#pragma unroll
    for (int i = 0; i < 8; i++)
#pragma unroll
        for (int j = 0; j < 4; j++) O[i][j] = 0.0f;
    float mrow[2] = { -INFINITY, -INFINITY };
    float lrow2[2] = { 0.0f, 0.0f };

    const int ntiles = 2 * qt + 2;

    auto load_kv = [&](int k0, __half* buf) {
        const __half* srcs[2];
        srcs[0] = g_khi; srcs[1] = g_vhi;
#pragma unroll
        for (int arr = 0; arr < 2; ++arr) {
            const __half* s = srcs[arr] + (rowbase + k0) * D_MODEL + h * 64;
            __half* d = buf + arr * KV_ARRE;
#pragma unroll
            for (int p = 0; p < 2; ++p) {
                int v = tid + p * 256;
                int r = v >> 3, seg = v & 7;
                CP_ASYNC16(smem_u32(d + r * AT_ROWE + seg * 8),
                           s + (size_t)r * D_MODEL + seg * 8);
            }
        }
    };

    load_kv(0, smb); CP_COMMIT();

    for (int t = 0; t < ntiles; ++t) {
        __half* cbuf = smb + (t & 1) * KV_BUFE;
        if (t + 1 < ntiles) {
            load_kv((t + 1) * 64, smb + ((t + 1) & 1) * KV_BUFE);
            CP_COMMIT();
            CP_WAIT(1);
        } else {
            CP_WAIT(0);
        }
        __syncthreads();

        const int k0 = t * 64;
        const bool active = (k0 <= q0 + w * 16 + 15);

        if (active) {
            __half* sKh = cbuf;
            __half* sVh = cbuf + KV_ARRE;

            float sacc[8][4];
#pragma unroll
            for (int i = 0; i < 8; i++)
#pragma unroll
                for (int j = 0; j < 4; j++) sacc[i][j] = 0.0f;

#pragma unroll
            for (int kt = 0; kt < 4; ++kt) {
#pragma unroll
                for (int g = 0; g < 4; ++g) {
                    int row = g * 16 + (sub >> 1) * 8 + lrow;
                    int col = kt * 16 + (sub & 1) * 8;
                    uint32_t kh[4];
                    LDMATRIX_X4(kh[0], kh[1], kh[2], kh[3],
                                smem_u32(sKh + row * AT_ROWE + col));
                    MMA_F16(sacc[2 * g],     qh[kt], kh[0], kh[1]);
                    MMA_F16(sacc[2 * g + 1], qh[kt], kh[2], kh[3]);
                    MMA_F16(sacc[2 * g],     ql[kt], kh[0], kh[1]);
                    MMA_F16(sacc[2 * g + 1], ql[kt], kh[2], kh[3]);
                }
            }

            const int qrow0 = q0 + w * 16 + (lane >> 2);
            const bool need_mask = (k0 + 63 > q0 + w * 16);
#pragma unroll
            for (int nt = 0; nt < 8; ++nt) {
#pragma unroll
                for (int j = 0; j < 4; j++) sacc[nt][j] *= 0.125f;
                if (need_mask) {
                    int col = k0 + nt * 8 + (lane & 3) * 2;
                    if (col     > qrow0)     sacc[nt][0] = -INFINITY;
                    if (col + 1 > qrow0)     sacc[nt][1] = -INFINITY;
                    if (col     > qrow0 + 8) sacc[nt][2] = -INFINITY;
                    if (col + 1 > qrow0 + 8) sacc[nt][3] = -INFINITY;
                }
            }

            float mx0 = -INFINITY, mx1 = -INFINITY;
#pragma unroll
            for (int nt = 0; nt < 8; ++nt) {
                mx0 = fmaxf(mx0, fmaxf(sacc[nt][0], sacc[nt][1]));
                mx1 = fmaxf(mx1, fmaxf(sacc[nt][2], sacc[nt][3]));
            }
            mx0 = fmaxf(mx0, __shfl_xor_sync(0xffffffff, mx0, 1));
            mx0 = fmaxf(mx0, __shfl_xor_sync(0xffffffff, mx0, 2));
            mx1 = fmaxf(mx1, __shfl_xor_sync(0xffffffff, mx1, 1));
            mx1 = fmaxf(mx1, __shfl_xor_sync(0xffffffff, mx1, 2));

            float mn0 = fmaxf(mrow[0], mx0);
            float mn1 = fmaxf(mrow[1], mx1);
            float a0 = __expf(mrow[0] - mn0);
            float a1 = __expf(mrow[1] - mn1);
            mrow[0] = mn0; mrow[1] = mn1;

            float rs0 = 0.0f, rs1 = 0.0f;
#pragma unroll
            for (int nt = 0; nt < 8; ++nt) {
                sacc[nt][0] = __expf(sacc[nt][0] - mn0);
                sacc[nt][1] = __expf(sacc[nt][1] - mn0);
                sacc[nt][2] = __expf(sacc[nt][2] - mn1);
                sacc[nt][3] = __expf(sacc[nt][3] - mn1);
                rs0 += sacc[nt][0] + sacc[nt][1];
                rs1 += sacc[nt][2] + sacc[nt][3];
            }
            rs0 += __shfl_xor_sync(0xffffffff, rs0, 1);
            rs0 += __shfl_xor_sync(0xffffffff, rs0, 2);
            rs1 += __shfl_xor_sync(0xffffffff, rs1, 1);
            rs1 += __shfl_xor_sync(0xffffffff, rs1, 2);
            lrow2[0] = lrow2[0] * a0 + rs0;
            lrow2[1] = lrow2[1] * a1 + rs1;

#pragma unroll
            for (int dn = 0; dn < 8; ++dn) {
                O[dn][0] *= a0; O[dn][1] *= a0;
                O[dn][2] *= a1; O[dn][3] *= a1;
            }

            uint32_t ph[4][4], pl[4][4];
#pragma unroll
            for (int kt = 0; kt < 4; ++kt) {
                float e[8] = { sacc[2 * kt][0],     sacc[2 * kt][1],
                               sacc[2 * kt][2],     sacc[2 * kt][3],
                               sacc[2 * kt + 1][0], sacc[2 * kt + 1][1],
                               sacc[2 * kt + 1][2], sacc[2 * kt + 1][3] };
#pragma unroll
                for (int i = 0; i < 4; i++) {
                    uint32_t lo;
                    ph[kt][i] = split_pair_h(e[2 * i], e[2 * i + 1], lo);
                    pl[kt][i] = lo;
                }
            }

#pragma unroll
            for (int kt = 0; kt < 4; ++kt) {
#pragma unroll
                for (int dg = 0; dg < 4; ++dg) {
                    int row = kt * 16 + (sub & 1) * 8 + lrow;
                    int col = dg * 16 + (sub >> 1) * 8;
                    uint32_t vh[4];
                    LDMATRIX_X4_T(vh[0], vh[1], vh[2], vh[3],
                                  smem_u32(sVh + row * AT_ROWE + col));
                    MMA_F16(O[2 * dg],     ph[kt], vh[0], vh[1]);
                    MMA_F16(O[2 * dg + 1], ph[kt], vh[2], vh[3]);
                    MMA_F16(O[2 * dg],     pl[kt], vh[0], vh[1]);
                    MMA_F16(O[2 * dg + 1], pl[kt], vh[2], vh[3]);
                }
            }
        }
        __syncthreads();
    }

    const float inv0 = 1.0f / lrow2[0];
    const float inv1 = 1.0f / lrow2[1];
    const size_t r0 = rowbase + q0 + w * 16 + (lane >> 2);
#pragma unroll
    for (int dn = 0; dn < 8; ++dn) {
        int col = h * 64 + dn * 8 + (lane & 3) * 2;
        uint32_t lo0, hi0 = split_pair_h(O[dn][0] * inv0, O[dn][1] * inv0, lo0);
        uint32_t lo1, hi1 = split_pair_h(O[dn][2] * inv1, O[dn][3] * inv1, lo1);
        *reinterpret_cast<uint32_t*>(&g_aohi[r0 * D_MODEL + col]) = hi0;
        *reinterpret_cast<uint32_t*>(&g_aolo[r0 * D_MODEL + col]) = lo0;
        *reinterpret_cast<uint32_t*>(&g_aohi[(r0 + 8) * D_MODEL + col]) = hi1;
        *reinterpret_cast<uint32_t*>(&g_aolo[(r0 + 8) * D_MODEL + col]) = lo1;
    }
}

// ---------------------------------------------------------------------------
// Launch
// ---------------------------------------------------------------------------
extern "C" void kernel_launch(void* const* d_in, const int* in_sizes, int n_in,
                              void* d_out, int out_size)
{
    const float* x   = (const float*)d_in[0];
    const int*   pos = (const int*)  d_in[1];
    const float* Wq  = (const float*)d_in[2];
    const float* Wk  = (const float*)d_in[3];
    const float* Wv  = (const float*)d_in[4];
    const float* Wo  = (const float*)d_in[5];
    float*       out = (float*)d_out;

    __half *xhi, *xlo, *aohi, *aolo, *qhi, *qlo, *khi, *vhi, *whi, *wohi;
    cudaGetSymbolAddress((void**)&xhi,  g_xhi);
    cudaGetSymbolAddress((void**)&xlo,  g_xlo);
    cudaGetSymbolAddress((void**)&aohi, g_aohi);
    cudaGetSymbolAddress((void**)&aolo, g_aolo);
    cudaGetSymbolAddress((void**)&qhi,  g_qhi);
    cudaGetSymbolAddress((void**)&qlo,  g_qlo);
    cudaGetSymbolAddress((void**)&khi,  g_khi);
    cudaGetSymbolAddress((void**)&vhi,  g_vhi);
    cudaGetSymbolAddress((void**)&whi,  g_whi);
    cudaGetSymbolAddress((void**)&wohi, g_wohi);

    cudaFuncSetAttribute(gemm_mma_kernel,
                         cudaFuncAttributeMaxDynamicSharedMemorySize, GEMM_SMEM);
    cudaFuncSetAttribute(attn_mma_kernel,
                         cudaFuncAttributeMaxDynamicSharedMemorySize, ATTN_SMEM);

    const int nx = M_ROWS * D_MODEL / 4;
    const int nw = D_MODEL * D_MODEL / 4;

    split_h_kernel<<<(nx + 255) / 256, 256>>>(x, xhi, xlo, nx);
    conv_w_kernel<<<(4 * nw + 255) / 256, 256>>>(Wq, Wk, Wv, Wo, whi, wohi, nw);

    // Fused QKV projection + RoPE epilogue (Q->hi/lo, K->hi, V->hi).
    gemm_mma_kernel<<<dim3(24, 64), 256, GEMM_SMEM>>>(
        xhi, xlo, whi, pos, nullptr, qhi, qlo, khi, vhi, D_MODEL, 1);

    attn_mma_kernel<<<dim3(SEQ / 128, BATCH * NUM_HEADS), 256, ATTN_SMEM>>>();

    // Output projection: fp32 -> out.
    gemm_mma_kernel<<<dim3(8, 64), 256, GEMM_SMEM>>>(
        aohi, aolo, wohi, pos, out, qhi, qlo, khi, vhi, D_MODEL, 0);
}

// round 11
// speedup vs baseline: 4.5534x; 1.0092x over previous
#include <cuda_runtime.h>
#include <cuda_fp16.h>
#include <math.h>
#include <stdint.h>

#define D_MODEL   1024
#define NUM_HEADS 16
#define HEAD_DIM  64
#define BATCH     4
#define SEQ       2048
#define M_ROWS    (BATCH * SEQ)   // 8192

// ---------------------------------------------------------------------------
// Scratch (allocation-free rule: __device__ globals)
// ---------------------------------------------------------------------------
__device__ __half g_xhi [M_ROWS * D_MODEL];
__device__ __half g_xlo [M_ROWS * D_MODEL];
__device__ __half g_aohi[M_ROWS * D_MODEL];
__device__ __half g_aolo[M_ROWS * D_MODEL];
__device__ __half g_qhi [M_ROWS * D_MODEL];
__device__ __half g_qlo [M_ROWS * D_MODEL];
__device__ __half g_khi [M_ROWS * D_MODEL];   // B-operand: hi only
__device__ __half g_vhi [M_ROWS * D_MODEL];   // B-operand: hi only
__device__ __half g_whi [3 * D_MODEL * D_MODEL];  // packed Wq|Wk|Wv
__device__ __half g_wohi[D_MODEL * D_MODEL];

// ---------------------------------------------------------------------------
// Helpers
// ---------------------------------------------------------------------------
__device__ __forceinline__ uint32_t smem_u32(const void* p) {
    uint32_t a;
    asm("{ .reg .u64 t; cvta.to.shared.u64 t, %1; cvt.u32.u64 %0, t; }"
        : "=r"(a) : "l"(p));
    return a;
}

#define CP_ASYNC16(dst, src) \
    asm volatile("cp.async.cg.shared.global [%0], [%1], 16;" \
                 :: "r"(dst), "l"(src) : "memory")
#define CP_COMMIT() asm volatile("cp.async.commit_group;" ::: "memory")
#define CP_WAIT(n)  asm volatile("cp.async.wait_group %0;" :: "n"(n) : "memory")

#define LDMATRIX_X4(r0, r1, r2, r3, addr) \
    asm volatile("ldmatrix.sync.aligned.m8n8.x4.shared.b16 {%0,%1,%2,%3}, [%4];" \
                 : "=r"(r0), "=r"(r1), "=r"(r2), "=r"(r3) : "r"(addr))

#define LDMATRIX_X4_T(r0, r1, r2, r3, addr) \
    asm volatile("ldmatrix.sync.aligned.m8n8.x4.trans.shared.b16 {%0,%1,%2,%3}, [%4];" \
                 : "=r"(r0), "=r"(r1), "=r"(r2), "=r"(r3) : "r"(addr))

#define MMA_F16(d, a, b0, b1) \
    asm volatile("mma.sync.aligned.m16n8k16.row.col.f32.f16.f16.f32 " \
                 "{%0,%1,%2,%3}, {%4,%5,%6,%7}, {%8,%9}, {%0,%1,%2,%3};" \
                 : "+f"((d)[0]), "+f"((d)[1]), "+f"((d)[2]), "+f"((d)[3]) \
                 : "r"((a)[0]), "r"((a)[1]), "r"((a)[2]), "r"((a)[3]), \
                   "r"(b0), "r"(b1))

__device__ __forceinline__ uint32_t packh(float lo, float hi) {
    __half2 t = __floats2half2_rn(lo, hi);
    return *reinterpret_cast<uint32_t*>(&t);
}

__device__ __forceinline__ uint32_t split_pair_h(float y0, float y1, uint32_t& lo_out) {
    __half h0 = __float2half_rn(y0);
    __half h1 = __float2half_rn(y1);
    float r0 = y0 - __half2float(h0);
    float r1 = y1 - __half2float(h1);
    lo_out = packh(r0, r1);
    __half2 hp = make_half2(h0, h1);
    return *reinterpret_cast<uint32_t*>(&hp);
}

// ---------------------------------------------------------------------------
// fp32 -> fp16 hi/lo split (A-side: x)
// ---------------------------------------------------------------------------
__global__ void split_h_kernel(const float* __restrict__ src,
                               __half* __restrict__ hi,
                               __half* __restrict__ lo, int n4)
{
    int i = blockIdx.x * blockDim.x + threadIdx.x;
    if (i >= n4) return;
    float4 v = reinterpret_cast<const float4*>(src)[i];
    uint32_t l0, h0 = split_pair_h(v.x, v.y, l0);
    uint32_t l1, h1 = split_pair_h(v.z, v.w, l1);
    reinterpret_cast<uint2*>(hi)[i] = make_uint2(h0, h1);
    reinterpret_cast<uint2*>(lo)[i] = make_uint2(l0, l1);
}

// All four weights -> fp16 in one launch (B-side: hi only)
__global__ void conv_w_kernel(const float* __restrict__ Wq, const float* __restrict__ Wk,
                              const float* __restrict__ Wv, const float* __restrict__ Wo,
                              __half* __restrict__ whi, __half* __restrict__ wohi, int n4)
{
    int i = blockIdx.x * blockDim.x + threadIdx.x;
    if (i >= 4 * n4) return;
    int sel = i / n4;
    int rem = i - sel * n4;
    const float* src = (sel == 0) ? Wq : (sel == 1) ? Wk : (sel == 2) ? Wv : Wo;
    float4 v = reinterpret_cast<const float4*>(src)[rem];
    uint2 o = make_uint2(packh(v.x, v.y), packh(v.z, v.w));
    if (sel < 3) reinterpret_cast<uint2*>(whi)[(size_t)sel * n4 + rem] = o;
    else         reinterpret_cast<uint2*>(wohi)[rem] = o;
}

// ---------------------------------------------------------------------------
// fp16-split HMMA GEMM (unchanged from R10).
// ---------------------------------------------------------------------------
#define BK        64
#define ROWB      144
#define GSTAGE_B  (384 * ROWB)      // 55296
#define GEMM_SMEM (2 * GSTAGE_B)    // 110592

__global__ __launch_bounds__(256, 2) void gemm_mma_kernel(
    const __half* __restrict__ Ahi, const __half* __restrict__ Alo,
    const __half* __restrict__ Bh, const int* __restrict__ pos,
    float* __restrict__ Cq,
    __half* __restrict__ Qhi, __half* __restrict__ Qlo,
    __half* __restrict__ Kh, __half* __restrict__ Vh,
    int K, int do_rope)
{
    extern __shared__ char gsm[];

    const int tid  = threadIdx.x;
    const int warp = tid >> 5;
    const int lane = tid & 31;
    const int wr   = warp & 3;
    const int wc   = warp >> 2;
    const int bm   = blockIdx.y * 128;
    const int bn   = blockIdx.x * 128;

    float acc[2][8][4];
#pragma unroll
    for (int i = 0; i < 2; i++)
#pragma unroll
        for (int j = 0; j < 8; j++)
#pragma unroll
            for (int k = 0; k < 4; k++) acc[i][j][k] = 0.0f;

    const int nkc = K / BK;   // 16

    auto load_chunk = [&](int c, int stage) {
        const int kc = c * BK;
        char* st = gsm + stage * GSTAGE_B;
#pragma unroll
        for (int p = 0; p < 12; p++) {
            int v   = tid + p * 256;
            int r   = v >> 3;
            int seg = v & 7;
            int rr  = r & 127;
            const __half* base;
            size_t grow;
            if (r < 128)      { base = Ahi; grow = (size_t)(bm + rr); }
            else if (r < 256) { base = Alo; grow = (size_t)(bm + rr); }
            else              { base = Bh;  grow = (size_t)(bn + rr); }
            CP_ASYNC16(smem_u32(st + r * ROWB + seg * 16),
                       base + grow * K + kc + seg * 8);
        }
    };

    load_chunk(0, 0); CP_COMMIT();

    const int sub  = lane >> 3;
    const int lrow = lane & 7;

    for (int c = 0; c < nkc; ++c) {
        if (c + 1 < nkc) {
            load_chunk(c + 1, (c + 1) & 1);
            CP_COMMIT();
            CP_WAIT(1);
        } else {
            CP_WAIT(0);
        }
        __syncthreads();

        char* st = gsm + (c & 1) * GSTAGE_B;

#pragma unroll
        for (int s = 0; s < 4; ++s) {
            uint32_t afh[2][4], afl[2][4];
#pragma unroll
            for (int mt = 0; mt < 2; ++mt) {
                int row = wr * 32 + mt * 16 + (sub & 1) * 8 + lrow;
                uint32_t ad = smem_u32(st + row * ROWB + s * 32 + (sub >> 1) * 16);
                LDMATRIX_X4(afh[mt][0], afh[mt][1], afh[mt][2], afh[mt][3], ad);
                LDMATRIX_X4(afl[mt][0], afl[mt][1], afl[mt][2], afl[mt][3],
                            ad + 128 * ROWB);
            }
#pragma unroll
            for (int nt = 0; nt < 4; ++nt) {
                int row = wc * 64 + nt * 16 + (sub >> 1) * 8 + lrow;
                uint32_t bd = smem_u32(st + (256 + row) * ROWB + s * 32 + (sub & 1) * 16);
                uint32_t bh[4];
                LDMATRIX_X4(bh[0], bh[1], bh[2], bh[3], bd);
#pragma unroll
                for (int mt = 0; mt < 2; ++mt) {
                    MMA_F16(acc[mt][2 * nt],     afh[mt], bh[0], bh[1]);
                    MMA_F16(acc[mt][2 * nt + 1], afh[mt], bh[2], bh[3]);
                    MMA_F16(acc[mt][2 * nt],     afl[mt], bh[0], bh[1]);
                    MMA_F16(acc[mt][2 * nt + 1], afl[mt], bh[2], bh[3]);
                }
            }
        }
        __syncthreads();
    }

    if (bn < 1024 && !do_rope) {
#pragma unroll
        for (int mt = 0; mt < 2; ++mt)
#pragma unroll
            for (int nt = 0; nt < 8; ++nt) {
                int r0 = bm + wr * 32 + mt * 16 + (lane >> 2);
                int cc = bn + wc * 64 + nt * 8 + (lane & 3) * 2;
                *reinterpret_cast<float2*>(&Cq[(size_t)r0 * 1024 + cc]) =
                    make_float2(acc[mt][nt][0], acc[mt][nt][1]);
                *reinterpret_cast<float2*>(&Cq[(size_t)(r0 + 8) * 1024 + cc]) =
                    make_float2(acc[mt][nt][2], acc[mt][nt][3]);
            }
    } else if (bn < 2048) {
        const bool isQ = (bn < 1024);
#pragma unroll
        for (int mt = 0; mt < 2; ++mt)
#pragma unroll
            for (int nt = 0; nt < 8; ++nt) {
                int r0 = bm + wr * 32 + mt * 16 + (lane >> 2);
                int cc = (isQ ? bn : bn - 1024) + wc * 64 + nt * 8 + (lane & 3) * 2;
                int j  = (cc & 63) >> 1;
                float invf = powf(10000.0f, -(float)(2 * j) / 64.0f);
                {
                    float ang = (float)pos[r0 & (SEQ - 1)] * invf;
                    float sn, cs; sincosf(ang, &sn, &cs);
                    float y0 = acc[mt][nt][0] * cs - acc[mt][nt][1] * sn;
                    float y1 = acc[mt][nt][0] * sn + acc[mt][nt][1] * cs;
                    if (isQ) {
                        uint32_t lo, hi = split_pair_h(y0, y1, lo);
                        *reinterpret_cast<uint32_t*>(&Qhi[(size_t)r0 * 1024 + cc]) = hi;
                        *reinterpret_cast<uint32_t*>(&Qlo[(size_t)r0 * 1024 + cc]) = lo;
                    } else {
                        *reinterpret_cast<uint32_t*>(&Kh[(size_t)r0 * 1024 + cc]) =
                            packh(y0, y1);
                    }
                }
                {
                    int r1 = r0 + 8;
                    float ang = (float)pos[r1 & (SEQ - 1)] * invf;
                    float sn, cs; sincosf(ang, &sn, &cs);
                    float y0 = acc[mt][nt][2] * cs - acc[mt][nt][3] * sn;
                    float y1 = acc[mt][nt][2] * sn + acc[mt][nt][3] * cs;
                    if (isQ) {
                        uint32_t lo, hi = split_pair_h(y0, y1, lo);
                        *reinterpret_cast<uint32_t*>(&Qhi[(size_t)r1 * 1024 + cc]) = hi;
                        *reinterpret_cast<uint32_t*>(&Qlo[(size_t)r1 * 1024 + cc]) = lo;
                    } else {
                        *reinterpret_cast<uint32_t*>(&Kh[(size_t)r1 * 1024 + cc]) =
                            packh(y0, y1);
                    }
                }
            }
    } else {
#pragma unroll
        for (int mt = 0; mt < 2; ++mt)
#pragma unroll
            for (int nt = 0; nt < 8; ++nt) {
                int r0 = bm + wr * 32 + mt * 16 + (lane >> 2);
                int cc = bn - 2048 + wc * 64 + nt * 8 + (lane & 3) * 2;
                *reinterpret_cast<uint32_t*>(&Vh[(size_t)r0 * 1024 + cc]) =
                    packh(acc[mt][nt][0], acc[mt][nt][1]);
                *reinterpret_cast<uint32_t*>(&Vh[(size_t)(r0 + 8) * 1024 + cc]) =
                    packh(acc[mt][nt][2], acc[mt][nt][3]);
            }
    }
}

// ---------------------------------------------------------------------------
// fp16 HMMA flash attention, causal, 2 CTAs/SM (128-reg cap).
// exp2-based softmax; P packed per-kt inside PV loop to cut live registers.
// ---------------------------------------------------------------------------
#define AT_ROWE 72
#define KV_ARRE (64 * AT_ROWE)
#define KV_BUFE (2 * KV_ARRE)
#define ATTN_SMEM (2 * KV_BUFE * 2)
#define SCALE_LOG2E 0.18033688011112042f   // 0.125 * log2(e)

__global__ __launch_bounds__(256, 2) void attn_mma_kernel()
{
    extern __shared__ char at_sm[];
    __half* smb = reinterpret_cast<__half*>(at_sm);

    const int tid  = threadIdx.x;
    const int w    = tid >> 5;
    const int lane = tid & 31;
    const int sub  = lane >> 3;
    const int lrow = lane & 7;
    const int qt   = (int)(gridDim.x - 1 - blockIdx.x);
    const int bh   = blockIdx.y;
    const int b    = bh >> 4;
    const int h    = bh & 15;

    const size_t rowbase = (size_t)b * SEQ;
    const int    q0      = qt * 128;

    {
        const __half* srcs[2];
        srcs[0] = g_qhi; srcs[1] = g_qlo;
#pragma unroll
        for (int arr = 0; arr < 2; ++arr) {
            const __half* s = srcs[arr] + (rowbase + q0) * D_MODEL + h * 64;
            __half* d = smb + arr * (128 * AT_ROWE);
#pragma unroll
            for (int p = 0; p < 4; ++p) {
                int v = tid + p * 256;
                int r = v >> 3, seg = v & 7;
                CP_ASYNC16(smem_u32(d + r * AT_ROWE + seg * 8),
                           s + (size_t)r * D_MODEL + seg * 8);
            }
        }
        CP_COMMIT(); CP_WAIT(0);
        __syncthreads();
    }

    uint32_t qh[4][4], ql[4][4];
#pragma unroll
    for (int kt = 0; kt < 4; ++kt) {
        int row = w * 16 + (sub & 1) * 8 + lrow;
        int col = kt * 16 + (sub >> 1) * 8;
        uint32_t a0 = smem_u32(smb + row * AT_ROWE + col);
        LDMATRIX_X4(qh[kt][0], qh[kt][1], qh[kt][2], qh[kt][3], a0);
        uint32_t a1 = smem_u32(smb + 128 * AT_ROWE + row * AT_ROWE + col);
        LDMATRIX_X4(ql[kt][0], ql[kt][1], ql[kt][2], ql[kt][3], a1);
    }
    __syncthreads();

    float O[8][4];
#pragma unroll
    for (int i = 0; i < 8; i++)
#pragma unroll
        for (int j = 0; j < 4; j++) O[i][j] = 0.0f;
    float mrow[2] = { -INFINITY, -INFINITY };
    float lrow2[2] = { 0.0f, 0.0f };

    const int ntiles = 2 * qt + 2;

    auto load_kv = [&](int k0, __half* buf) {
        const __half* srcs[2];
        srcs[0] = g_khi; srcs[1] = g_vhi;
#pragma unroll
        for (int arr = 0; arr < 2; ++arr) {
            const __half* s = srcs[arr] + (rowbase + k0) * D_MODEL + h * 64;
            __half* d = buf + arr * KV_ARRE;
#pragma unroll
            for (int p = 0; p < 2; ++p) {
                int v = tid + p * 256;
                int r = v >> 3, seg = v & 7;
                CP_ASYNC16(smem_u32(d + r * AT_ROWE + seg * 8),
                           s + (size_t)r * D_MODEL + seg * 8);
            }
        }
    };

    load_kv(0, smb); CP_COMMIT();

    for (int t = 0; t < ntiles; ++t) {
        __half* cbuf = smb + (t & 1) * KV_BUFE;
        if (t + 1 < ntiles) {
            load_kv((t + 1) * 64, smb + ((t + 1) & 1) * KV_BUFE);
            CP_COMMIT();
            CP_WAIT(1);
        } else {
            CP_WAIT(0);
        }
        __syncthreads();

        const int k0 = t * 64;
        const bool active = (k0 <= q0 + w * 16 + 15);

        if (active) {
            __half* sKh = cbuf;
            __half* sVh = cbuf + KV_ARRE;

            // ---- S = Q K^T (2-pass fp16 split) ----
            float sacc[8][4];
#pragma unroll
            for (int i = 0; i < 8; i++)
#pragma unroll
                for (int j = 0; j < 4; j++) sacc[i][j] = 0.0f;

#pragma unroll
            for (int kt = 0; kt < 4; ++kt) {
#pragma unroll
                for (int g = 0; g < 4; ++g) {
                    int row = g * 16 + (sub >> 1) * 8 + lrow;
                    int col = kt * 16 + (sub & 1) * 8;
                    uint32_t kh[4];
                    LDMATRIX_X4(kh[0], kh[1], kh[2], kh[3],
                                smem_u32(sKh + row * AT_ROWE + col));
                    MMA_F16(sacc[2 * g],     qh[kt], kh[0], kh[1]);
                    MMA_F16(sacc[2 * g + 1], qh[kt], kh[2], kh[3]);
                    MMA_F16(sacc[2 * g],     ql[kt], kh[0], kh[1]);
                    MMA_F16(sacc[2 * g + 1], ql[kt], kh[2], kh[3]);
                }
            }

            // ---- scale (log2 domain) + causal mask ----
            const int qrow0 = q0 + w * 16 + (lane >> 2);
            const bool need_mask = (k0 + 63 > q0 + w * 16);
#pragma unroll
            for (int nt = 0; nt < 8; ++nt) {
#pragma unroll
                for (int j = 0; j < 4; j++) sacc[nt][j] *= SCALE_LOG2E;
                if (need_mask) {
                    int col = k0 + nt * 8 + (lane & 3) * 2;
                    if (col     > qrow0)     sacc[nt][0] = -INFINITY;
                    if (col + 1 > qrow0)     sacc[nt][1] = -INFINITY;
                    if (col     > qrow0 + 8) sacc[nt][2] = -INFINITY;
                    if (col + 1 > qrow0 + 8) sacc[nt][3] = -INFINITY;
                }
            }

            // ---- online softmax (base-2) ----
            float mx0 = -INFINITY, mx1 = -INFINITY;
#pragma unroll
            for (int nt = 0; nt < 8; ++nt) {
                mx0 = fmaxf(mx0, fmaxf(sacc[nt][0], sacc[nt][1]));
                mx1 = fmaxf(mx1, fmaxf(sacc[nt][2], sacc[nt][3]));
            }
            mx0 = fmaxf(mx0, __shfl_xor_sync(0xffffffff, mx0, 1));
            mx0 = fmaxf(mx0, __shfl_xor_sync(0xffffffff, mx0, 2));
            mx1 = fmaxf(mx1, __shfl_xor_sync(0xffffffff, mx1, 1));
            mx1 = fmaxf(mx1, __shfl_xor_sync(0xffffffff, mx1, 2));

            float mn0 = fmaxf(mrow[0], mx0);
            float mn1 = fmaxf(mrow[1], mx1);
            float a0 = exp2f(mrow[0] - mn0);
            float a1 = exp2f(mrow[1] - mn1);
            mrow[0] = mn0; mrow[1] = mn1;

            float rs0 = 0.0f, rs1 = 0.0f;
#pragma unroll
            for (int nt = 0; nt < 8; ++nt) {
                sacc[nt][0] = exp2f(sacc[nt][0] - mn0);
                sacc[nt][1] = exp2f(sacc[nt][1] - mn0);
                sacc[nt][2] = exp2f(sacc[nt][2] - mn1);
                sacc[nt][3] = exp2f(sacc[nt][3] - mn1);
                rs0 += sacc[nt][0] + sacc[nt][1];
                rs1 += sacc[nt][2] + sacc[nt][3];
            }
            rs0 += __shfl_xor_sync(0xffffffff, rs0, 1);
            rs0 += __shfl_xor_sync(0xffffffff, rs0, 2);
            rs1 += __shfl_xor_sync(0xffffffff, rs1, 1);
            rs1 += __shfl_xor_sync(0xffffffff, rs1, 2);
            lrow2[0] = lrow2[0] * a0 + rs0;
            lrow2[1] = lrow2[1] * a1 + rs1;

#pragma unroll
            for (int dn = 0; dn < 8; ++dn) {
                O[dn][0] *= a0; O[dn][1] *= a0;
                O[dn][2] *= a1; O[dn][3] *= a1;
            }

            // ---- O += P V: pack P hi/lo per-kt (8 live regs), then MMA ----
#pragma unroll
            for (int kt = 0; kt < 4; ++kt) {
                uint32_t ph[4], pl[4];
                {
                    float e[8] = { sacc[2 * kt][0],     sacc[2 * kt][1],
                                   sacc[2 * kt][2],     sacc[2 * kt][3],
                                   sacc[2 * kt + 1][0], sacc[2 * kt + 1][1],
                                   sacc[2 * kt + 1][2], sacc[2 * kt + 1][3] };
#pragma unroll
                    for (int i = 0; i < 4; i++) {
                        uint32_t lo;
                        ph[i] = split_pair_h(e[2 * i], e[2 * i + 1], lo);
                        pl[i] = lo;
                    }
                }
#pragma unroll
                for (int dg = 0; dg < 4; ++dg) {
                    int row = kt * 16 + (sub & 1) * 8 + lrow;
                    int col = dg * 16 + (sub >> 1) * 8;
                    uint32_t vh[4];
                    LDMATRIX_X4_T(vh[0], vh[1], vh[2], vh[3],
                                  smem_u32(sVh + row * AT_ROWE + col));
                    MMA_F16(O[2 * dg],     ph, vh[0], vh[1]);
                    MMA_F16(O[2 * dg + 1], ph, vh[2], vh[3]);
                    MMA_F16(O[2 * dg],     pl, vh[0], vh[1]);
                    MMA_F16(O[2 * dg + 1], pl, vh[2], vh[3]);
                }
            }
        }
        __syncthreads();
    }

    const float inv0 = 1.0f / lrow2[0];
    const float inv1 = 1.0f / lrow2[1];
    const size_t r0 = rowbase + q0 + w * 16 + (lane >> 2);
#pragma unroll
    for (int dn = 0; dn < 8; ++dn) {
        int col = h * 64 + dn * 8 + (lane & 3) * 2;
        uint32_t lo0, hi0 = split_pair_h(O[dn][0] * inv0, O[dn][1] * inv0, lo0);
        uint32_t lo1, hi1 = split_pair_h(O[dn][2] * inv1, O[dn][3] * inv1, lo1);
        *reinterpret_cast<uint32_t*>(&g_aohi[r0 * D_MODEL + col]) = hi0;
        *reinterpret_cast<uint32_t*>(&g_aolo[r0 * D_MODEL + col]) = lo0;
        *reinterpret_cast<uint32_t*>(&g_aohi[(r0 + 8) * D_MODEL + col]) = hi1;
        *reinterpret_cast<uint32_t*>(&g_aolo[(r0 + 8) * D_MODEL + col]) = lo1;
    }
}

// ---------------------------------------------------------------------------
// Launch
// ---------------------------------------------------------------------------
extern "C" void kernel_launch(void* const* d_in, const int* in_sizes, int n_in,
                              void* d_out, int out_size)
{
    const float* x   = (const float*)d_in[0];
    const int*   pos = (const int*)  d_in[1];
    const float* Wq  = (const float*)d_in[2];
    const float* Wk  = (const float*)d_in[3];
    const float* Wv  = (const float*)d_in[4];
    const float* Wo  = (const float*)d_in[5];
    float*       out = (float*)d_out;

    __half *xhi, *xlo, *aohi, *aolo, *qhi, *qlo, *khi, *vhi, *whi, *wohi;
    cudaGetSymbolAddress((void**)&xhi,  g_xhi);
    cudaGetSymbolAddress((void**)&xlo,  g_xlo);
    cudaGetSymbolAddress((void**)&aohi, g_aohi);
    cudaGetSymbolAddress((void**)&aolo, g_aolo);
    cudaGetSymbolAddress((void**)&qhi,  g_qhi);
    cudaGetSymbolAddress((void**)&qlo,  g_qlo);
    cudaGetSymbolAddress((void**)&khi,  g_khi);
    cudaGetSymbolAddress((void**)&vhi,  g_vhi);
    cudaGetSymbolAddress((void**)&whi,  g_whi);
    cudaGetSymbolAddress((void**)&wohi, g_wohi);

    cudaFuncSetAttribute(gemm_mma_kernel,
                         cudaFuncAttributeMaxDynamicSharedMemorySize, GEMM_SMEM);
    cudaFuncSetAttribute(attn_mma_kernel,
                         cudaFuncAttributeMaxDynamicSharedMemorySize, ATTN_SMEM);

    const int nx = M_ROWS * D_MODEL / 4;
    const int nw = D_MODEL * D_MODEL / 4;

    split_h_kernel<<<(nx + 255) / 256, 256>>>(x, xhi, xlo, nx);
    conv_w_kernel<<<(4 * nw + 255) / 256, 256>>>(Wq, Wk, Wv, Wo, whi, wohi, nw);

    gemm_mma_kernel<<<dim3(24, 64), 256, GEMM_SMEM>>>(
        xhi, xlo, whi, pos, nullptr, qhi, qlo, khi, vhi, D_MODEL, 1);

    attn_mma_kernel<<<dim3(SEQ / 128, BATCH * NUM_HEADS), 256, ATTN_SMEM>>>();

    gemm_mma_kernel<<<dim3(8, 64), 256, GEMM_SMEM>>>(
        aohi, aolo, wohi, pos, out, qhi, qlo, khi, vhi, D_MODEL, 0);
}

// round 15
// speedup vs baseline: 4.8718x; 1.0699x over previous
#include <cuda_runtime.h>
#include <cuda_fp16.h>
#include <math.h>
#include <stdint.h>

#define D_MODEL   1024
#define NUM_HEADS 16
#define HEAD_DIM  64
#define BATCH     4
#define SEQ       2048
#define M_ROWS    (BATCH * SEQ)   // 8192

// ---------------------------------------------------------------------------
// Scratch (allocation-free rule: __device__ globals)
// ---------------------------------------------------------------------------
__device__ __half g_xhi [M_ROWS * D_MODEL];
__device__ __half g_xlo [M_ROWS * D_MODEL];
__device__ __half g_aohi[M_ROWS * D_MODEL];
__device__ __half g_aolo[M_ROWS * D_MODEL];
__device__ __half g_qhi [M_ROWS * D_MODEL];
__device__ __half g_qlo [M_ROWS * D_MODEL];
__device__ __half g_khi [M_ROWS * D_MODEL];   // B-operand: hi only
__device__ __half g_vhi [M_ROWS * D_MODEL];   // B-operand: hi only
__device__ __half g_whi [3 * D_MODEL * D_MODEL];  // packed Wq|Wk|Wv
__device__ __half g_wohi[D_MODEL * D_MODEL];

// ---------------------------------------------------------------------------
// Helpers
// ---------------------------------------------------------------------------
__device__ __forceinline__ uint32_t smem_u32(const void* p) {
    uint32_t a;
    asm("{ .reg .u64 t; cvta.to.shared.u64 t, %1; cvt.u32.u64 %0, t; }"
        : "=r"(a) : "l"(p));
    return a;
}

#define CP_ASYNC16(dst, src) \
    asm volatile("cp.async.cg.shared.global [%0], [%1], 16;" \
                 :: "r"(dst), "l"(src) : "memory")
#define CP_COMMIT() asm volatile("cp.async.commit_group;" ::: "memory")
#define CP_WAIT(n)  asm volatile("cp.async.wait_group %0;" :: "n"(n) : "memory")

#define LDMATRIX_X4(r0, r1, r2, r3, addr) \
    asm volatile("ldmatrix.sync.aligned.m8n8.x4.shared.b16 {%0,%1,%2,%3}, [%4];" \
                 : "=r"(r0), "=r"(r1), "=r"(r2), "=r"(r3) : "r"(addr))

#define LDMATRIX_X4_T(r0, r1, r2, r3, addr) \
    asm volatile("ldmatrix.sync.aligned.m8n8.x4.trans.shared.b16 {%0,%1,%2,%3}, [%4];" \
                 : "=r"(r0), "=r"(r1), "=r"(r2), "=r"(r3) : "r"(addr))

#define MMA_F16(d, a, b0, b1) \
    asm volatile("mma.sync.aligned.m16n8k16.row.col.f32.f16.f16.f32 " \
                 "{%0,%1,%2,%3}, {%4,%5,%6,%7}, {%8,%9}, {%0,%1,%2,%3};" \
                 : "+f"((d)[0]), "+f"((d)[1]), "+f"((d)[2]), "+f"((d)[3]) \
                 : "r"((a)[0]), "r"((a)[1]), "r"((a)[2]), "r"((a)[3]), \
                   "r"(b0), "r"(b1))

__device__ __forceinline__ uint32_t packh(float lo, float hi) {
    __half2 t = __floats2half2_rn(lo, hi);
    return *reinterpret_cast<uint32_t*>(&t);
}

__device__ __forceinline__ uint32_t split_pair_h(float y0, float y1, uint32_t& lo_out) {
    __half h0 = __float2half_rn(y0);
    __half h1 = __float2half_rn(y1);
    float r0 = y0 - __half2float(h0);
    float r1 = y1 - __half2float(h1);
    lo_out = packh(r0, r1);
    __half2 hp = make_half2(h0, h1);
    return *reinterpret_cast<uint32_t*>(&hp);
}

// ---------------------------------------------------------------------------
// fp32 -> fp16 hi/lo split (A-side: x)
// ---------------------------------------------------------------------------
__global__ void split_h_kernel(const float* __restrict__ src,
                               __half* __restrict__ hi,
                               __half* __restrict__ lo, int n4)
{
    int i = blockIdx.x * blockDim.x + threadIdx.x;
    if (i >= n4) return;
    float4 v = reinterpret_cast<const float4*>(src)[i];
    uint32_t l0, h0 = split_pair_h(v.x, v.y, l0);
    uint32_t l1, h1 = split_pair_h(v.z, v.w, l1);
    reinterpret_cast<uint2*>(hi)[i] = make_uint2(h0, h1);
    reinterpret_cast<uint2*>(lo)[i] = make_uint2(l0, l1);
}

// All four weights -> fp16 in one launch (B-side: hi only)
__global__ void conv_w_kernel(const float* __restrict__ Wq, const float* __restrict__ Wk,
                              const float* __restrict__ Wv, const float* __restrict__ Wo,
                              __half* __restrict__ whi, __half* __restrict__ wohi, int n4)
{
    int i = blockIdx.x * blockDim.x + threadIdx.x;
    if (i >= 4 * n4) return;
    int sel = i / n4;
    int rem = i - sel * n4;
    const float* src = (sel == 0) ? Wq : (sel == 1) ? Wk : (sel == 2) ? Wv : Wo;
    float4 v = reinterpret_cast<const float4*>(src)[rem];
    uint2 o = make_uint2(packh(v.x, v.y), packh(v.z, v.w));
    if (sel < 3) reinterpret_cast<uint2*>(whi)[(size_t)sel * n4 + rem] = o;
    else         reinterpret_cast<uint2*>(wohi)[rem] = o;
}

// ---------------------------------------------------------------------------
// fp16-split HMMA GEMM (unchanged from R10/R11).
// ---------------------------------------------------------------------------
#define BK        64
#define ROWB      144
#define GSTAGE_B  (384 * ROWB)      // 55296
#define GEMM_SMEM (2 * GSTAGE_B)    // 110592

__global__ __launch_bounds__(256, 2) void gemm_mma_kernel(
    const __half* __restrict__ Ahi, const __half* __restrict__ Alo,
    const __half* __restrict__ Bh, const int* __restrict__ pos,
    float* __restrict__ Cq,
    __half* __restrict__ Qhi, __half* __restrict__ Qlo,
    __half* __restrict__ Kh, __half* __restrict__ Vh,
    int K, int do_rope)
{
    extern __shared__ char gsm[];

    const int tid  = threadIdx.x;
    const int warp = tid >> 5;
    const int lane = tid & 31;
    const int wr   = warp & 3;
    const int wc   = warp >> 2;
    const int bm   = blockIdx.y * 128;
    const int bn   = blockIdx.x * 128;

    float acc[2][8][4];
#pragma unroll
    for (int i = 0; i < 2; i++)
#pragma unroll
        for (int j = 0; j < 8; j++)
#pragma unroll
            for (int k = 0; k < 4; k++) acc[i][j][k] = 0.0f;

    const int nkc = K / BK;   // 16

    auto load_chunk = [&](int c, int stage) {
        const int kc = c * BK;
        char* st = gsm + stage * GSTAGE_B;
#pragma unroll
        for (int p = 0; p < 12; p++) {
            int v   = tid + p * 256;
            int r   = v >> 3;
            int seg = v & 7;
            int rr  = r & 127;
            const __half* base;
            size_t grow;
            if (r < 128)      { base = Ahi; grow = (size_t)(bm + rr); }
            else if (r < 256) { base = Alo; grow = (size_t)(bm + rr); }
            else              { base = Bh;  grow = (size_t)(bn + rr); }
            CP_ASYNC16(smem_u32(st + r * ROWB + seg * 16),
                       base + grow * K + kc + seg * 8);
        }
    };

    load_chunk(0, 0); CP_COMMIT();

    const int sub  = lane >> 3;
    const int lrow = lane & 7;

    for (int c = 0; c < nkc; ++c) {
        if (c + 1 < nkc) {
            load_chunk(c + 1, (c + 1) & 1);
            CP_COMMIT();
            CP_WAIT(1);
        } else {
            CP_WAIT(0);
        }
        __syncthreads();

        char* st = gsm + (c & 1) * GSTAGE_B;

#pragma unroll
        for (int s = 0; s < 4; ++s) {
            uint32_t afh[2][4], afl[2][4];
#pragma unroll
            for (int mt = 0; mt < 2; ++mt) {
                int row = wr * 32 + mt * 16 + (sub & 1) * 8 + lrow;
                uint32_t ad = smem_u32(st + row * ROWB + s * 32 + (sub >> 1) * 16);
                LDMATRIX_X4(afh[mt][0], afh[mt][1], afh[mt][2], afh[mt][3], ad);
                LDMATRIX_X4(afl[mt][0], afl[mt][1], afl[mt][2], afl[mt][3],
                            ad + 128 * ROWB);
            }
#pragma unroll
            for (int nt = 0; nt < 4; ++nt) {
                int row = wc * 64 + nt * 16 + (sub >> 1) * 8 + lrow;
                uint32_t bd = smem_u32(st + (256 + row) * ROWB + s * 32 + (sub & 1) * 16);
                uint32_t bh[4];
                LDMATRIX_X4(bh[0], bh[1], bh[2], bh[3], bd);
#pragma unroll
                for (int mt = 0; mt < 2; ++mt) {
                    MMA_F16(acc[mt][2 * nt],     afh[mt], bh[0], bh[1]);
                    MMA_F16(acc[mt][2 * nt + 1], afh[mt], bh[2], bh[3]);
                    MMA_F16(acc[mt][2 * nt],     afl[mt], bh[0], bh[1]);
                    MMA_F16(acc[mt][2 * nt + 1], afl[mt], bh[2], bh[3]);
                }
            }
        }
        __syncthreads();
    }

    if (bn < 1024 && !do_rope) {
#pragma unroll
        for (int mt = 0; mt < 2; ++mt)
#pragma unroll
            for (int nt = 0; nt < 8; ++nt) {
                int r0 = bm + wr * 32 + mt * 16 + (lane >> 2);
                int cc = bn + wc * 64 + nt * 8 + (lane & 3) * 2;
                *reinterpret_cast<float2*>(&Cq[(size_t)r0 * 1024 + cc]) =
                    make_float2(acc[mt][nt][0], acc[mt][nt][1]);
                *reinterpret_cast<float2*>(&Cq[(size_t)(r0 + 8) * 1024 + cc]) =
                    make_float2(acc[mt][nt][2], acc[mt][nt][3]);
            }
    } else if (bn < 2048) {
        const bool isQ = (bn < 1024);
#pragma unroll
        for (int mt = 0; mt < 2; ++mt)
#pragma unroll
            for (int nt = 0; nt < 8; ++nt) {
                int r0 = bm + wr * 32 + mt * 16 + (lane >> 2);
                int cc = (isQ ? bn : bn - 1024) + wc * 64 + nt * 8 + (lane & 3) * 2;
                int j  = (cc & 63) >> 1;
                float invf = powf(10000.0f, -(float)(2 * j) / 64.0f);
                {
                    float ang = (float)pos[r0 & (SEQ - 1)] * invf;
                    float sn, cs; sincosf(ang, &sn, &cs);
                    float y0 = acc[mt][nt][0] * cs - acc[mt][nt][1] * sn;
                    float y1 = acc[mt][nt][0] * sn + acc[mt][nt][1] * cs;
                    if (isQ) {
                        uint32_t lo, hi = split_pair_h(y0, y1, lo);
                        *reinterpret_cast<uint32_t*>(&Qhi[(size_t)r0 * 1024 + cc]) = hi;
                        *reinterpret_cast<uint32_t*>(&Qlo[(size_t)r0 * 1024 + cc]) = lo;
                    } else {
                        *reinterpret_cast<uint32_t*>(&Kh[(size_t)r0 * 1024 + cc]) =
                            packh(y0, y1);
                    }
                }
                {
                    int r1 = r0 + 8;
                    float ang = (float)pos[r1 & (SEQ - 1)] * invf;
                    float sn, cs; sincosf(ang, &sn, &cs);
                    float y0 = acc[mt][nt][2] * cs - acc[mt][nt][3] * sn;
                    float y1 = acc[mt][nt][2] * sn + acc[mt][nt][3] * cs;
                    if (isQ) {
                        uint32_t lo, hi = split_pair_h(y0, y1, lo);
                        *reinterpret_cast<uint32_t*>(&Qhi[(size_t)r1 * 1024 + cc]) = hi;
                        *reinterpret_cast<uint32_t*>(&Qlo[(size_t)r1 * 1024 + cc]) = lo;
                    } else {
                        *reinterpret_cast<uint32_t*>(&Kh[(size_t)r1 * 1024 + cc]) =
                            packh(y0, y1);
                    }
                }
            }
    } else {
#pragma unroll
        for (int mt = 0; mt < 2; ++mt)
#pragma unroll
            for (int nt = 0; nt < 8; ++nt) {
                int r0 = bm + wr * 32 + mt * 16 + (lane >> 2);
                int cc = bn - 2048 + wc * 64 + nt * 8 + (lane & 3) * 2;
                *reinterpret_cast<uint32_t*>(&Vh[(size_t)r0 * 1024 + cc]) =
                    packh(acc[mt][nt][0], acc[mt][nt][1]);
                *reinterpret_cast<uint32_t*>(&Vh[(size_t)(r0 + 8) * 1024 + cc]) =
                    packh(acc[mt][nt][2], acc[mt][nt][3]);
            }
    }
}

// ---------------------------------------------------------------------------
// fp16 HMMA flash attention, causal, true 2 CTAs/SM.
// Q hi/lo lives in persistent smem (frags re-LDSM'd per tile) -> small reg set.
// PV uses P-hi only (P-lo dropped; P in [0,1], roundoff ~2^-12).
// smem/CTA: Q 36864B + KV double-buffer 36864B = 73728B.
// ---------------------------------------------------------------------------
#define AT_ROWE 72
#define Q_ELEMS (128 * AT_ROWE)         // one Q array (hi or lo)
#define KV_ARRE (64 * AT_ROWE)
#define KV_BUFE (2 * KV_ARRE)
#define ATTN_SMEM ((2 * Q_ELEMS + 2 * KV_BUFE) * 2)   // 73728 bytes
#define SCALE_LOG2E 0.18033688011112042f   // 0.125 * log2(e)

__global__ __launch_bounds__(256, 2) void attn_mma_kernel()
{
    extern __shared__ char at_sm[];
    __half* sQ  = reinterpret_cast<__half*>(at_sm);            // [2][128][72]
    __half* sKV = sQ + 2 * Q_ELEMS;                            // [2][2][64][72]

    const int tid  = threadIdx.x;
    const int w    = tid >> 5;
    const int lane = tid & 31;
    const int sub  = lane >> 3;
    const int lrow = lane & 7;
    const int qt   = (int)(gridDim.x - 1 - blockIdx.x);   // reversed: big first
    const int bh   = blockIdx.y;
    const int b    = bh >> 4;
    const int h    = bh & 15;

    const size_t rowbase = (size_t)b * SEQ;
    const int    q0      = qt * 128;

    // ---- Stage Q hi/lo into persistent smem ----
    {
        const __half* srcs[2];
        srcs[0] = g_qhi; srcs[1] = g_qlo;
#pragma unroll
        for (int arr = 0; arr < 2; ++arr) {
            const __half* s = srcs[arr] + (rowbase + q0) * D_MODEL + h * 64;
            __half* d = sQ + arr * Q_ELEMS;
#pragma unroll
            for (int p = 0; p < 4; ++p) {
                int v = tid + p * 256;
                int r = v >> 3, seg = v & 7;
                CP_ASYNC16(smem_u32(d + r * AT_ROWE + seg * 8),
                           s + (size_t)r * D_MODEL + seg * 8);
            }
        }
        CP_COMMIT();
    }

    float O[8][4];
#pragma unroll
    for (int i = 0; i < 8; i++)
#pragma unroll
        for (int j = 0; j < 4; j++) O[i][j] = 0.0f;
    float mrow[2] = { -INFINITY, -INFINITY };
    float lrow2[2] = { 0.0f, 0.0f };

    const int ntiles = 2 * qt + 2;

    auto load_kv = [&](int k0, __half* buf) {
        const __half* srcs[2];
        srcs[0] = g_khi; srcs[1] = g_vhi;
#pragma unroll
        for (int arr = 0; arr < 2; ++arr) {
            const __half* s = srcs[arr] + (rowbase + k0) * D_MODEL + h * 64;
            __half* d = buf + arr * KV_ARRE;
#pragma unroll
            for (int p = 0; p < 2; ++p) {
                int v = tid + p * 256;
                int r = v >> 3, seg = v & 7;
                CP_ASYNC16(smem_u32(d + r * AT_ROWE + seg * 8),
                           s + (size_t)r * D_MODEL + seg * 8);
            }
        }
    };

    load_kv(0, sKV); CP_COMMIT();

    const int qrow_w = w * 16 + (sub & 1) * 8 + lrow;   // Q smem row for A-frags

    for (int t = 0; t < ntiles; ++t) {
        __half* cbuf = sKV + (t & 1) * KV_BUFE;
        if (t + 1 < ntiles) {
            load_kv((t + 1) * 64, sKV + ((t + 1) & 1) * KV_BUFE);
            CP_COMMIT();
            CP_WAIT(1);
        } else {
            CP_WAIT(0);
        }
        __syncthreads();

        const int k0 = t * 64;
        const bool active = (k0 <= q0 + w * 16 + 15);

        if (active) {
            __half* sKh = cbuf;
            __half* sVh = cbuf + KV_ARRE;

            // ---- S = Q K^T (2-pass fp16 split; Q frags from smem) ----
            float sacc[8][4];
#pragma unroll
            for (int i = 0; i < 8; i++)
#pragma unroll
                for (int j = 0; j < 4; j++) sacc[i][j] = 0.0f;

#pragma unroll
            for (int kt = 0; kt < 4; ++kt) {
                int qcol = kt * 16 + (sub >> 1) * 8;
                uint32_t qh[4], ql[4];
                LDMATRIX_X4(qh[0], qh[1], qh[2], qh[3],
                            smem_u32(sQ + qrow_w * AT_ROWE + qcol));
                LDMATRIX_X4(ql[0], ql[1], ql[2], ql[3],
                            smem_u32(sQ + Q_ELEMS + qrow_w * AT_ROWE + qcol));
#pragma unroll
                for (int g = 0; g < 4; ++g) {
                    int row = g * 16 + (sub >> 1) * 8 + lrow;
                    int col = kt * 16 + (sub & 1) * 8;
                    uint32_t kh[4];
                    LDMATRIX_X4(kh[0], kh[1], kh[2], kh[3],
                                smem_u32(sKh + row * AT_ROWE + col));
                    MMA_F16(sacc[2 * g],     qh, kh[0], kh[1]);
                    MMA_F16(sacc[2 * g + 1], qh, kh[2], kh[3]);
                    MMA_F16(sacc[2 * g],     ql, kh[0], kh[1]);
                    MMA_F16(sacc[2 * g + 1], ql, kh[2], kh[3]);
                }
            }

            // ---- scale (log2 domain) + causal mask ----
            const int qrow0 = q0 + w * 16 + (lane >> 2);
            const bool need_mask = (k0 + 63 > q0 + w * 16);
#pragma unroll
            for (int nt = 0; nt < 8; ++nt) {
#pragma unroll
                for (int j = 0; j < 4; j++) sacc[nt][j] *= SCALE_LOG2E;
                if (need_mask) {
                    int col = k0 + nt * 8 + (lane & 3) * 2;
                    if (col     > qrow0)     sacc[nt][0] = -INFINITY;
                    if (col + 1 > qrow0)     sacc[nt][1] = -INFINITY;
                    if (col     > qrow0 + 8) sacc[nt][2] = -INFINITY;
                    if (col + 1 > qrow0 + 8) sacc[nt][3] = -INFINITY;
                }
            }

            // ---- online softmax (base-2) ----
            float mx0 = -INFINITY, mx1 = -INFINITY;
#pragma unroll
            for (int nt = 0; nt < 8; ++nt) {
                mx0 = fmaxf(mx0, fmaxf(sacc[nt][0], sacc[nt][1]));
                mx1 = fmaxf(mx1, fmaxf(sacc[nt][2], sacc[nt][3]));
            }
            mx0 = fmaxf(mx0, __shfl_xor_sync(0xffffffff, mx0, 1));
            mx0 = fmaxf(mx0, __shfl_xor_sync(0xffffffff, mx0, 2));
            mx1 = fmaxf(mx1, __shfl_xor_sync(0xffffffff, mx1, 1));
            mx1 = fmaxf(mx1, __shfl_xor_sync(0xffffffff, mx1, 2));

            float mn0 = fmaxf(mrow[0], mx0);
            float mn1 = fmaxf(mrow[1], mx1);
            float a0 = exp2f(mrow[0] - mn0);
            float a1 = exp2f(mrow[1] - mn1);
            mrow[0] = mn0; mrow[1] = mn1;

            float rs0 = 0.0f, rs1 = 0.0f;
#pragma unroll
            for (int nt = 0; nt < 8; ++nt) {
                sacc[nt][0] = exp2f(sacc[nt][0] - mn0);
                sacc[nt][1] = exp2f(sacc[nt][1] - mn0);
                sacc[nt][2] = exp2f(sacc[nt][2] - mn1);
                sacc[nt][3] = exp2f(sacc[nt][3] - mn1);
                rs0 += sacc[nt][0] + sacc[nt][1];
                rs1 += sacc[nt][2] + sacc[nt][3];
            }
            rs0 += __shfl_xor_sync(0xffffffff, rs0, 1);
            rs0 += __shfl_xor_sync(0xffffffff, rs0, 2);
            rs1 += __shfl_xor_sync(0xffffffff, rs1, 1);
            rs1 += __shfl_xor_sync(0xffffffff, rs1, 2);
            lrow2[0] = lrow2[0] * a0 + rs0;
            lrow2[1] = lrow2[1] * a1 + rs1;

#pragma unroll
            for (int dn = 0; dn < 8; ++dn) {
                O[dn][0] *= a0; O[dn][1] *= a0;
                O[dn][2] *= a1; O[dn][3] *= a1;
            }

            // ---- O += P V (P-hi only) ----
#pragma unroll
            for (int kt = 0; kt < 4; ++kt) {
                uint32_t ph[4];
                ph[0] = packh(sacc[2 * kt][0],     sacc[2 * kt][1]);
                ph[1] = packh(sacc[2 * kt][2],     sacc[2 * kt][3]);
                ph[2] = packh(sacc[2 * kt + 1][0], sacc[2 * kt + 1][1]);
                ph[3] = packh(sacc[2 * kt + 1][2], sacc[2 * kt + 1][3]);
#pragma unroll
                for (int dg = 0; dg < 4; ++dg) {
                    int row = kt * 16 + (sub & 1) * 8 + lrow;
                    int col = dg * 16 + (sub >> 1) * 8;
                    uint32_t vh[4];
                    LDMATRIX_X4_T(vh[0], vh[1], vh[2], vh[3],
                                  smem_u32(sVh + row * AT_ROWE + col));
                    MMA_F16(O[2 * dg],     ph, vh[0], vh[1]);
                    MMA_F16(O[2 * dg + 1], ph, vh[2], vh[3]);
                }
            }
        }
        __syncthreads();
    }

    // ---- normalize + write AO as fp16 hi/lo ----
    const float inv0 = 1.0f / lrow2[0];
    const float inv1 = 1.0f / lrow2[1];
    const size_t r0 = rowbase + q0 + w * 16 + (lane >> 2);
#pragma unroll
    for (int dn = 0; dn < 8; ++dn) {
        int col = h * 64 + dn * 8 + (lane & 3) * 2;
        uint32_t lo0, hi0 = split_pair_h(O[dn][0] * inv0, O[dn][1] * inv0, lo0);
        uint32_t lo1, hi1 = split_pair_h(O[dn][2] * inv1, O[dn][3] * inv1, lo1);
        *reinterpret_cast<uint32_t*>(&g_aohi[r0 * D_MODEL + col]) = hi0;
        *reinterpret_cast<uint32_t*>(&g_aolo[r0 * D_MODEL + col]) = lo0;
        *reinterpret_cast<uint32_t*>(&g_aohi[(r0 + 8) * D_MODEL + col]) = hi1;
        *reinterpret_cast<uint32_t*>(&g_aolo[(r0 + 8) * D_MODEL + col]) = lo1;
    }
}

// ---------------------------------------------------------------------------
// Launch
// ---------------------------------------------------------------------------
extern "C" void kernel_launch(void* const* d_in, const int* in_sizes, int n_in,
                              void* d_out, int out_size)
{
    const float* x   = (const float*)d_in[0];
    const int*   pos = (const int*)  d_in[1];
    const float* Wq  = (const float*)d_in[2];
    const float* Wk  = (const float*)d_in[3];
    const float* Wv  = (const float*)d_in[4];
    const float* Wo  = (const float*)d_in[5];
    float*       out = (float*)d_out;

    __half *xhi, *xlo, *aohi, *aolo, *qhi, *qlo, *khi, *vhi, *whi, *wohi;
    cudaGetSymbolAddress((void**)&xhi,  g_xhi);
    cudaGetSymbolAddress((void**)&xlo,  g_xlo);
    cudaGetSymbolAddress((void**)&aohi, g_aohi);
    cudaGetSymbolAddress((void**)&aolo, g_aolo);
    cudaGetSymbolAddress((void**)&qhi,  g_qhi);
    cudaGetSymbolAddress((void**)&qlo,  g_qlo);
    cudaGetSymbolAddress((void**)&khi,  g_khi);
    cudaGetSymbolAddress((void**)&vhi,  g_vhi);
    cudaGetSymbolAddress((void**)&whi,  g_whi);
    cudaGetSymbolAddress((void**)&wohi, g_wohi);

    cudaFuncSetAttribute(gemm_mma_kernel,
                         cudaFuncAttributeMaxDynamicSharedMemorySize, GEMM_SMEM);
    cudaFuncSetAttribute(attn_mma_kernel,
                         cudaFuncAttributeMaxDynamicSharedMemorySize, ATTN_SMEM);

    const int nx = M_ROWS * D_MODEL / 4;
    const int nw = D_MODEL * D_MODEL / 4;

    split_h_kernel<<<(nx + 255) / 256, 256>>>(x, xhi, xlo, nx);
    conv_w_kernel<<<(4 * nw + 255) / 256, 256>>>(Wq, Wk, Wv, Wo, whi, wohi, nw);

    gemm_mma_kernel<<<dim3(24, 64), 256, GEMM_SMEM>>>(
        xhi, xlo, whi, pos, nullptr, qhi, qlo, khi, vhi, D_MODEL, 1);

    attn_mma_kernel<<<dim3(SEQ / 128, BATCH * NUM_HEADS), 256, ATTN_SMEM>>>();

    gemm_mma_kernel<<<dim3(8, 64), 256, GEMM_SMEM>>>(
        aohi, aolo, wohi, pos, out, qhi, qlo, khi, vhi, D_MODEL, 0);
}

// round 17
// speedup vs baseline: 5.2271x; 1.0729x over previous
#include <cuda_runtime.h>
#include <cuda_fp16.h>
#include <math.h>
#include <stdint.h>

#define D_MODEL   1024
#define NUM_HEADS 16
#define HEAD_DIM  64
#define BATCH     4
#define SEQ       2048
#define M_ROWS    (BATCH * SEQ)   // 8192

// ---------------------------------------------------------------------------
// Scratch (allocation-free rule: __device__ globals)
// ---------------------------------------------------------------------------
__device__ __half g_xhi [M_ROWS * D_MODEL];
__device__ __half g_xlo [M_ROWS * D_MODEL];
__device__ __half g_aohi[M_ROWS * D_MODEL];
__device__ __half g_aolo[M_ROWS * D_MODEL];
__device__ __half g_qhi [M_ROWS * D_MODEL];
__device__ __half g_qlo [M_ROWS * D_MODEL];
__device__ __half g_khi [M_ROWS * D_MODEL];   // B-operand: hi only
__device__ __half g_vhi [M_ROWS * D_MODEL];   // B-operand: hi only
__device__ __half g_whi [3 * D_MODEL * D_MODEL];  // packed Wq|Wk|Wv
__device__ __half g_wohi[D_MODEL * D_MODEL];

// ---------------------------------------------------------------------------
// Helpers
// ---------------------------------------------------------------------------
__device__ __forceinline__ uint32_t smem_u32(const void* p) {
    uint32_t a;
    asm("{ .reg .u64 t; cvta.to.shared.u64 t, %1; cvt.u32.u64 %0, t; }"
        : "=r"(a) : "l"(p));
    return a;
}

#define CP_ASYNC16(dst, src) \
    asm volatile("cp.async.cg.shared.global [%0], [%1], 16;" \
                 :: "r"(dst), "l"(src) : "memory")
#define CP_COMMIT() asm volatile("cp.async.commit_group;" ::: "memory")
#define CP_WAIT(n)  asm volatile("cp.async.wait_group %0;" :: "n"(n) : "memory")

#define LDMATRIX_X4(r0, r1, r2, r3, addr) \
    asm volatile("ldmatrix.sync.aligned.m8n8.x4.shared.b16 {%0,%1,%2,%3}, [%4];" \
                 : "=r"(r0), "=r"(r1), "=r"(r2), "=r"(r3) : "r"(addr))

#define LDMATRIX_X4_T(r0, r1, r2, r3, addr) \
    asm volatile("ldmatrix.sync.aligned.m8n8.x4.trans.shared.b16 {%0,%1,%2,%3}, [%4];" \
                 : "=r"(r0), "=r"(r1), "=r"(r2), "=r"(r3) : "r"(addr))

#define MMA_F16(d, a, b0, b1) \
    asm volatile("mma.sync.aligned.m16n8k16.row.col.f32.f16.f16.f32 " \
                 "{%0,%1,%2,%3}, {%4,%5,%6,%7}, {%8,%9}, {%0,%1,%2,%3};" \
                 : "+f"((d)[0]), "+f"((d)[1]), "+f"((d)[2]), "+f"((d)[3]) \
                 : "r"((a)[0]), "r"((a)[1]), "r"((a)[2]), "r"((a)[3]), \
                   "r"(b0), "r"(b1))

__device__ __forceinline__ uint32_t packh(float lo, float hi) {
    __half2 t = __floats2half2_rn(lo, hi);
    return *reinterpret_cast<uint32_t*>(&t);
}

__device__ __forceinline__ uint32_t split_pair_h(float y0, float y1, uint32_t& lo_out) {
    __half h0 = __float2half_rn(y0);
    __half h1 = __float2half_rn(y1);
    float r0 = y0 - __half2float(h0);
    float r1 = y1 - __half2float(h1);
    lo_out = packh(r0, r1);
    __half2 hp = make_half2(h0, h1);
    return *reinterpret_cast<uint32_t*>(&hp);
}

// ---------------------------------------------------------------------------
// fp32 -> fp16 hi/lo split (A-side: x)
// ---------------------------------------------------------------------------
__global__ void split_h_kernel(const float* __restrict__ src,
                               __half* __restrict__ hi,
                               __half* __restrict__ lo, int n4)
{
    int i = blockIdx.x * blockDim.x + threadIdx.x;
    if (i >= n4) return;
    float4 v = reinterpret_cast<const float4*>(src)[i];
    uint32_t l0, h0 = split_pair_h(v.x, v.y, l0);
    uint32_t l1, h1 = split_pair_h(v.z, v.w, l1);
    reinterpret_cast<uint2*>(hi)[i] = make_uint2(h0, h1);
    reinterpret_cast<uint2*>(lo)[i] = make_uint2(l0, l1);
}

// All four weights -> fp16 in one launch (B-side: hi only)
__global__ void conv_w_kernel(const float* __restrict__ Wq, const float* __restrict__ Wk,
                              const float* __restrict__ Wv, const float* __restrict__ Wo,
                              __half* __restrict__ whi, __half* __restrict__ wohi, int n4)
{
    int i = blockIdx.x * blockDim.x + threadIdx.x;
    if (i >= 4 * n4) return;
    int sel = i / n4;
    int rem = i - sel * n4;
    const float* src = (sel == 0) ? Wq : (sel == 1) ? Wk : (sel == 2) ? Wv : Wo;
    float4 v = reinterpret_cast<const float4*>(src)[rem];
    uint2 o = make_uint2(packh(v.x, v.y), packh(v.z, v.w));
    if (sel < 3) reinterpret_cast<uint2*>(whi)[(size_t)sel * n4 + rem] = o;
    else         reinterpret_cast<uint2*>(wohi)[rem] = o;
}

// ---------------------------------------------------------------------------
// fp16-split HMMA GEMM.
// lo_pass CTAs compute C = (Ah+Al)*Bh^T (2 passes); others C = Ah*Bh^T.
// K/V column tiles (do_rope && bn>=1024) are single-pass: their outputs are
// truncated to fp16 anyway, so the lo contribution is below storage roundoff.
// ---------------------------------------------------------------------------
#define BK        64
#define ROWB      144
#define GSTAGE_B  (384 * ROWB)      // 55296
#define GEMM_SMEM (2 * GSTAGE_B)    // 110592

__global__ __launch_bounds__(256, 2) void gemm_mma_kernel(
    const __half* __restrict__ Ahi, const __half* __restrict__ Alo,
    const __half* __restrict__ Bh, const int* __restrict__ pos,
    float* __restrict__ Cq,
    __half* __restrict__ Qhi, __half* __restrict__ Qlo,
    __half* __restrict__ Kh, __half* __restrict__ Vh,
    int K, int do_rope)
{
    extern __shared__ char gsm[];

    const int tid  = threadIdx.x;
    const int warp = tid >> 5;
    const int lane = tid & 31;
    const int wr   = warp & 3;
    const int wc   = warp >> 2;
    const int bm   = blockIdx.y * 128;
    const int bn   = blockIdx.x * 128;
    const bool lo_pass = (!do_rope) || (bn < 1024);   // Q tiles + out-proj

    float acc[2][8][4];
#pragma unroll
    for (int i = 0; i < 2; i++)
#pragma unroll
        for (int j = 0; j < 8; j++)
#pragma unroll
            for (int k = 0; k < 4; k++) acc[i][j][k] = 0.0f;

    const int nkc = K / BK;   // 16

    auto load_chunk = [&](int c, int stage) {
        const int kc = c * BK;
        char* st = gsm + stage * GSTAGE_B;
#pragma unroll
        for (int p = 0; p < 12; p++) {
            if (p >= 4 && p < 8 && !lo_pass) continue;   // skip Alo region
            int v   = tid + p * 256;
            int r   = v >> 3;
            int seg = v & 7;
            int rr  = r & 127;
            const __half* base;
            size_t grow;
            if (r < 128)      { base = Ahi; grow = (size_t)(bm + rr); }
            else if (r < 256) { base = Alo; grow = (size_t)(bm + rr); }
            else              { base = Bh;  grow = (size_t)(bn + rr); }
            CP_ASYNC16(smem_u32(st + r * ROWB + seg * 16),
                       base + grow * K + kc + seg * 8);
        }
    };

    load_chunk(0, 0); CP_COMMIT();

    const int sub  = lane >> 3;
    const int lrow = lane & 7;

    for (int c = 0; c < nkc; ++c) {
        if (c + 1 < nkc) {
            load_chunk(c + 1, (c + 1) & 1);
            CP_COMMIT();
            CP_WAIT(1);
        } else {
            CP_WAIT(0);
        }
        __syncthreads();

        char* st = gsm + (c & 1) * GSTAGE_B;

#pragma unroll
        for (int s = 0; s < 4; ++s) {
            uint32_t afh[2][4], afl[2][4];
#pragma unroll
            for (int mt = 0; mt < 2; ++mt) {
                int row = wr * 32 + mt * 16 + (sub & 1) * 8 + lrow;
                uint32_t ad = smem_u32(st + row * ROWB + s * 32 + (sub >> 1) * 16);
                LDMATRIX_X4(afh[mt][0], afh[mt][1], afh[mt][2], afh[mt][3], ad);
                if (lo_pass)
                    LDMATRIX_X4(afl[mt][0], afl[mt][1], afl[mt][2], afl[mt][3],
                                ad + 128 * ROWB);
            }
#pragma unroll
            for (int nt = 0; nt < 4; ++nt) {
                int row = wc * 64 + nt * 16 + (sub >> 1) * 8 + lrow;
                uint32_t bd = smem_u32(st + (256 + row) * ROWB + s * 32 + (sub & 1) * 16);
                uint32_t bh[4];
                LDMATRIX_X4(bh[0], bh[1], bh[2], bh[3], bd);
#pragma unroll
                for (int mt = 0; mt < 2; ++mt) {
                    MMA_F16(acc[mt][2 * nt],     afh[mt], bh[0], bh[1]);
                    MMA_F16(acc[mt][2 * nt + 1], afh[mt], bh[2], bh[3]);
                    if (lo_pass) {
                        MMA_F16(acc[mt][2 * nt],     afl[mt], bh[0], bh[1]);
                        MMA_F16(acc[mt][2 * nt + 1], afl[mt], bh[2], bh[3]);
                    }
                }
            }
        }
        __syncthreads();
    }

    if (bn < 1024 && !do_rope) {
#pragma unroll
        for (int mt = 0; mt < 2; ++mt)
#pragma unroll
            for (int nt = 0; nt < 8; ++nt) {
                int r0 = bm + wr * 32 + mt * 16 + (lane >> 2);
                int cc = bn + wc * 64 + nt * 8 + (lane & 3) * 2;
                *reinterpret_cast<float2*>(&Cq[(size_t)r0 * 1024 + cc]) =
                    make_float2(acc[mt][nt][0], acc[mt][nt][1]);
                *reinterpret_cast<float2*>(&Cq[(size_t)(r0 + 8) * 1024 + cc]) =
                    make_float2(acc[mt][nt][2], acc[mt][nt][3]);
            }
    } else if (bn < 2048) {
        const bool isQ = (bn < 1024);
#pragma unroll
        for (int mt = 0; mt < 2; ++mt)
#pragma unroll
            for (int nt = 0; nt < 8; ++nt) {
                int r0 = bm + wr * 32 + mt * 16 + (lane >> 2);
                int cc = (isQ ? bn : bn - 1024) + wc * 64 + nt * 8 + (lane & 3) * 2;
                int j  = (cc & 63) >> 1;
                float invf = powf(10000.0f, -(float)(2 * j) / 64.0f);
                {
                    float ang = (float)pos[r0 & (SEQ - 1)] * invf;
                    float sn, cs; sincosf(ang, &sn, &cs);
                    float y0 = acc[mt][nt][0] * cs - acc[mt][nt][1] * sn;
                    float y1 = acc[mt][nt][0] * sn + acc[mt][nt][1] * cs;
                    if (isQ) {
                        uint32_t lo, hi = split_pair_h(y0, y1, lo);
                        *reinterpret_cast<uint32_t*>(&Qhi[(size_t)r0 * 1024 + cc]) = hi;
                        *reinterpret_cast<uint32_t*>(&Qlo[(size_t)r0 * 1024 + cc]) = lo;
                    } else {
                        *reinterpret_cast<uint32_t*>(&Kh[(size_t)r0 * 1024 + cc]) =
                            packh(y0, y1);
                    }
                }
                {
                    int r1 = r0 + 8;
                    float ang = (float)pos[r1 & (SEQ - 1)] * invf;
                    float sn, cs; sincosf(ang, &sn, &cs);
                    float y0 = acc[mt][nt][2] * cs - acc[mt][nt][3] * sn;
                    float y1 = acc[mt][nt][2] * sn + acc[mt][nt][3] * cs;
                    if (isQ) {
                        uint32_t lo, hi = split_pair_h(y0, y1, lo);
                        *reinterpret_cast<uint32_t*>(&Qhi[(size_t)r1 * 1024 + cc]) = hi;
                        *reinterpret_cast<uint32_t*>(&Qlo[(size_t)r1 * 1024 + cc]) = lo;
                    } else {
                        *reinterpret_cast<uint32_t*>(&Kh[(size_t)r1 * 1024 + cc]) =
                            packh(y0, y1);
                    }
                }
            }
    } else {
#pragma unroll
        for (int mt = 0; mt < 2; ++mt)
#pragma unroll
            for (int nt = 0; nt < 8; ++nt) {
                int r0 = bm + wr * 32 + mt * 16 + (lane >> 2);
                int cc = bn - 2048 + wc * 64 + nt * 8 + (lane & 3) * 2;
                *reinterpret_cast<uint32_t*>(&Vh[(size_t)r0 * 1024 + cc]) =
                    packh(acc[mt][nt][0], acc[mt][nt][1]);
                *reinterpret_cast<uint32_t*>(&Vh[(size_t)(r0 + 8) * 1024 + cc]) =
                    packh(acc[mt][nt][2], acc[mt][nt][3]);
            }
    }
}

// ---------------------------------------------------------------------------
// fp16 HMMA flash attention, causal, 2 CTAs/SM (unchanged from R15).
// ---------------------------------------------------------------------------
#define AT_ROWE 72
#define Q_ELEMS (128 * AT_ROWE)
#define KV_ARRE (64 * AT_ROWE)
#define KV_BUFE (2 * KV_ARRE)
#define ATTN_SMEM ((2 * Q_ELEMS + 2 * KV_BUFE) * 2)   // 73728 bytes
#define SCALE_LOG2E 0.18033688011112042f   // 0.125 * log2(e)

__global__ __launch_bounds__(256, 2) void attn_mma_kernel()
{
    extern __shared__ char at_sm[];
    __half* sQ  = reinterpret_cast<__half*>(at_sm);
    __half* sKV = sQ + 2 * Q_ELEMS;

    const int tid  = threadIdx.x;
    const int w    = tid >> 5;
    const int lane = tid & 31;
    const int sub  = lane >> 3;
    const int lrow = lane & 7;
    const int qt   = (int)(gridDim.x - 1 - blockIdx.x);
    const int bh   = blockIdx.y;
    const int b    = bh >> 4;
    const int h    = bh & 15;

    const size_t rowbase = (size_t)b * SEQ;
    const int    q0      = qt * 128;

    {
        const __half* srcs[2];
        srcs[0] = g_qhi; srcs[1] = g_qlo;
#pragma unroll
        for (int arr = 0; arr < 2; ++arr) {
            const __half* s = srcs[arr] + (rowbase + q0) * D_MODEL + h * 64;
            __half* d = sQ + arr * Q_ELEMS;
#pragma unroll
            for (int p = 0; p < 4; ++p) {
                int v = tid + p * 256;
                int r = v >> 3, seg = v & 7;
                CP_ASYNC16(smem_u32(d + r * AT_ROWE + seg * 8),
                           s + (size_t)r * D_MODEL + seg * 8);
            }
        }
        CP_COMMIT();
    }

    float O[8][4];
#pragma unroll
    for (int i = 0; i < 8; i++)
#pragma unroll
        for (int j = 0; j < 4; j++) O[i][j] = 0.0f;
    float mrow[2] = { -INFINITY, -INFINITY };
    float lrow2[2] = { 0.0f, 0.0f };

    const int ntiles = 2 * qt + 2;

    auto load_kv = [&](int k0, __half* buf) {
        const __half* srcs[2];
        srcs[0] = g_khi; srcs[1] = g_vhi;
#pragma unroll
        for (int arr = 0; arr < 2; ++arr) {
            const __half* s = srcs[arr] + (rowbase + k0) * D_MODEL + h * 64;
            __half* d = buf + arr * KV_ARRE;
#pragma unroll
            for (int p = 0; p < 2; ++p) {
                int v = tid + p * 256;
                int r = v >> 3, seg = v & 7;
                CP_ASYNC16(smem_u32(d + r * AT_ROWE + seg * 8),
                           s + (size_t)r * D_MODEL + seg * 8);
            }
        }
    };

    load_kv(0, sKV); CP_COMMIT();

    const int qrow_w = w * 16 + (sub & 1) * 8 + lrow;

    for (int t = 0; t < ntiles; ++t) {
        __half* cbuf = sKV + (t & 1) * KV_BUFE;
        if (t + 1 < ntiles) {
            load_kv((t + 1) * 64, sKV + ((t + 1) & 1) * KV_BUFE);
            CP_COMMIT();
            CP_WAIT(1);
        } else {
            CP_WAIT(0);
        }
        __syncthreads();

        const int k0 = t * 64;
        const bool active = (k0 <= q0 + w * 16 + 15);

        if (active) {
            __half* sKh = cbuf;
            __half* sVh = cbuf + KV_ARRE;

            float sacc[8][4];
#pragma unroll
            for (int i = 0; i < 8; i++)
#pragma unroll
                for (int j = 0; j < 4; j++) sacc[i][j] = 0.0f;

#pragma unroll
            for (int kt = 0; kt < 4; ++kt) {
                int qcol = kt * 16 + (sub >> 1) * 8;
                uint32_t qh[4], ql[4];
                LDMATRIX_X4(qh[0], qh[1], qh[2], qh[3],
                            smem_u32(sQ + qrow_w * AT_ROWE + qcol));
                LDMATRIX_X4(ql[0], ql[1], ql[2], ql[3],
                            smem_u32(sQ + Q_ELEMS + qrow_w * AT_ROWE + qcol));
#pragma unroll
                for (int g = 0; g < 4; ++g) {
                    int row = g * 16 + (sub >> 1) * 8 + lrow;
                    int col = kt * 16 + (sub & 1) * 8;
                    uint32_t kh[4];
                    LDMATRIX_X4(kh[0], kh[1], kh[2], kh[3],
                                smem_u32(sKh + row * AT_ROWE + col));
                    MMA_F16(sacc[2 * g],     qh, kh[0], kh[1]);
                    MMA_F16(sacc[2 * g + 1], qh, kh[2], kh[3]);
                    MMA_F16(sacc[2 * g],     ql, kh[0], kh[1]);
                    MMA_F16(sacc[2 * g + 1], ql, kh[2], kh[3]);
                }
            }

            const int qrow0 = q0 + w * 16 + (lane >> 2);
            const bool need_mask = (k0 + 63 > q0 + w * 16);
#pragma unroll
            for (int nt = 0; nt < 8; ++nt) {
#pragma unroll
                for (int j = 0; j < 4; j++) sacc[nt][j] *= SCALE_LOG2E;
                if (need_mask) {
                    int col = k0 + nt * 8 + (lane & 3) * 2;
                    if (col     > qrow0)     sacc[nt][0] = -INFINITY;
                    if (col + 1 > qrow0)     sacc[nt][1] = -INFINITY;
                    if (col     > qrow0 + 8) sacc[nt][2] = -INFINITY;
                    if (col + 1 > qrow0 + 8) sacc[nt][3] = -INFINITY;
                }
            }

            float mx0 = -INFINITY, mx1 = -INFINITY;
#pragma unroll
            for (int nt = 0; nt < 8; ++nt) {
                mx0 = fmaxf(mx0, fmaxf(sacc[nt][0], sacc[nt][1]));
                mx1 = fmaxf(mx1, fmaxf(sacc[nt][2], sacc[nt][3]));
            }
            mx0 = fmaxf(mx0, __shfl_xor_sync(0xffffffff, mx0, 1));
            mx0 = fmaxf(mx0, __shfl_xor_sync(0xffffffff, mx0, 2));
            mx1 = fmaxf(mx1, __shfl_xor_sync(0xffffffff, mx1, 1));
            mx1 = fmaxf(mx1, __shfl_xor_sync(0xffffffff, mx1, 2));

            float mn0 = fmaxf(mrow[0], mx0);
            float mn1 = fmaxf(mrow[1], mx1);
            float a0 = exp2f(mrow[0] - mn0);
            float a1 = exp2f(mrow[1] - mn1);
            mrow[0] = mn0; mrow[1] = mn1;

            float rs0 = 0.0f, rs1 = 0.0f;
#pragma unroll
            for (int nt = 0; nt < 8; ++nt) {
                sacc[nt][0] = exp2f(sacc[nt][0] - mn0);
                sacc[nt][1] = exp2f(sacc[nt][1] - mn0);
                sacc[nt][2] = exp2f(sacc[nt][2] - mn1);
                sacc[nt][3] = exp2f(sacc[nt][3] - mn1);
                rs0 += sacc[nt][0] + sacc[nt][1];
                rs1 += sacc[nt][2] + sacc[nt][3];
            }
            rs0 += __shfl_xor_sync(0xffffffff, rs0, 1);
            rs0 += __shfl_xor_sync(0xffffffff, rs0, 2);
            rs1 += __shfl_xor_sync(0xffffffff, rs1, 1);
            rs1 += __shfl_xor_sync(0xffffffff, rs1, 2);
            lrow2[0] = lrow2[0] * a0 + rs0;
            lrow2[1] = lrow2[1] * a1 + rs1;

#pragma unroll
            for (int dn = 0; dn < 8; ++dn) {
                O[dn][0] *= a0; O[dn][1] *= a0;
                O[dn][2] *= a1; O[dn][3] *= a1;
            }

#pragma unroll
            for (int kt = 0; kt < 4; ++kt) {
                uint32_t ph[4];
                ph[0] = packh(sacc[2 * kt][0],     sacc[2 * kt][1]);
                ph[1] = packh(sacc[2 * kt][2],     sacc[2 * kt][3]);
                ph[2] = packh(sacc[2 * kt + 1][0], sacc[2 * kt + 1][1]);
                ph[3] = packh(sacc[2 * kt + 1][2], sacc[2 * kt + 1][3]);
#pragma unroll
                for (int dg = 0; dg < 4; ++dg) {
                    int row = kt * 16 + (sub & 1) * 8 + lrow;
                    int col = dg * 16 + (sub >> 1) * 8;
                    uint32_t vh[4];
                    LDMATRIX_X4_T(vh[0], vh[1], vh[2], vh[3],
                                  smem_u32(sVh + row * AT_ROWE + col));
                    MMA_F16(O[2 * dg],     ph, vh[0], vh[1]);
                    MMA_F16(O[2 * dg + 1], ph, vh[2], vh[3]);
                }
            }
        }
        __syncthreads();
    }

    const float inv0 = 1.0f / lrow2[0];
    const float inv1 = 1.0f / lrow2[1];
    const size_t r0 = rowbase + q0 + w * 16 + (lane >> 2);
#pragma unroll
    for (int dn = 0; dn < 8; ++dn) {
        int col = h * 64 + dn * 8 + (lane & 3) * 2;
        uint32_t lo0, hi0 = split_pair_h(O[dn][0] * inv0, O[dn][1] * inv0, lo0);
        uint32_t lo1, hi1 = split_pair_h(O[dn][2] * inv1, O[dn][3] * inv1, lo1);
        *reinterpret_cast<uint32_t*>(&g_aohi[r0 * D_MODEL + col]) = hi0;
        *reinterpret_cast<uint32_t*>(&g_aolo[r0 * D_MODEL + col]) = lo0;
        *reinterpret_cast<uint32_t*>(&g_aohi[(r0 + 8) * D_MODEL + col]) = hi1;
        *reinterpret_cast<uint32_t*>(&g_aolo[(r0 + 8) * D_MODEL + col]) = lo1;
    }
}

// ---------------------------------------------------------------------------
// Launch
// ---------------------------------------------------------------------------
extern "C" void kernel_launch(void* const* d_in, const int* in_sizes, int n_in,
                              void* d_out, int out_size)
{
    const float* x   = (const float*)d_in[0];
    const int*   pos = (const int*)  d_in[1];
    const float* Wq  = (const float*)d_in[2];
    const float* Wk  = (const float*)d_in[3];
    const float* Wv  = (const float*)d_in[4];
    const float* Wo  = (const float*)d_in[5];
    float*       out = (float*)d_out;

    __half *xhi, *xlo, *aohi, *aolo, *qhi, *qlo, *khi, *vhi, *whi, *wohi;
    cudaGetSymbolAddress((void**)&xhi,  g_xhi);
    cudaGetSymbolAddress((void**)&xlo,  g_xlo);
    cudaGetSymbolAddress((void**)&aohi, g_aohi);
    cudaGetSymbolAddress((void**)&aolo, g_aolo);
    cudaGetSymbolAddress((void**)&qhi,  g_qhi);
    cudaGetSymbolAddress((void**)&qlo,  g_qlo);
    cudaGetSymbolAddress((void**)&khi,  g_khi);
    cudaGetSymbolAddress((void**)&vhi,  g_vhi);
    cudaGetSymbolAddress((void**)&whi,  g_whi);
    cudaGetSymbolAddress((void**)&wohi, g_wohi);

    cudaFuncSetAttribute(gemm_mma_kernel,
                         cudaFuncAttributeMaxDynamicSharedMemorySize, GEMM_SMEM);
    cudaFuncSetAttribute(attn_mma_kernel,
                         cudaFuncAttributeMaxDynamicSharedMemorySize, ATTN_SMEM);

    const int nx = M_ROWS * D_MODEL / 4;
    const int nw = D_MODEL * D_MODEL / 4;

    split_h_kernel<<<(nx + 255) / 256, 256>>>(x, xhi, xlo, nx);
    conv_w_kernel<<<(4 * nw + 255) / 256, 256>>>(Wq, Wk, Wv, Wo, whi, wohi, nw);

    gemm_mma_kernel<<<dim3(24, 64), 256, GEMM_SMEM>>>(
        xhi, xlo, whi, pos, nullptr, qhi, qlo, khi, vhi, D_MODEL, 1);

    attn_mma_kernel<<<dim3(SEQ / 128, BATCH * NUM_HEADS), 256, ATTN_SMEM>>>();

    gemm_mma_kernel<<<dim3(8, 64), 256, GEMM_SMEM>>>(
        aohi, aolo, wohi, pos, out, qhi, qlo, khi, vhi, D_MODEL, 0);
}